// round 1
// baseline (speedup 1.0000x reference)
#include <cuda_runtime.h>
#include <cuda_bf16.h>

#define H 128
#define E 1048576
#define NV 262144
#define T 4096
#define NET 8
#define FD 1056   // 8*H + 32
#define HD 256    // 2*H

// ---------------- scratch (static device allocations; no runtime alloc) ----
__device__ int g_ecnt[T];
__device__ int g_eoff[T + 1];
__device__ int g_ecur[T];
__device__ int g_ncnt[T];
__device__ int g_noff[T + 1];
__device__ int g_ncur[T];
__device__ unsigned g_eidx[E];   // edge idx | (is_inbound << 31)
__device__ int      g_esrc[E];
__device__ float    g_esw[E];
__device__ float    g_elw[E];
__device__ float    g_et[E];
__device__ unsigned g_nlist[NV]; // node idx | (is_hop1 << 31)
__device__ float g_fused[(size_t)T * FD];
__device__ float g_hidden[(size_t)T * HD];
__device__ float g_norm3[3];

__device__ __forceinline__ float gelu_exact(float x) {
    return 0.5f * x * (1.0f + erff(x * 0.7071067811865476f));
}

// ---------------- init -----------------------------------------------------
__global__ void k_init() {
    int i = blockIdx.x * blockDim.x + threadIdx.x;
    if (i < T) { g_ecnt[i] = 0; g_ncnt[i] = 0; }
    if (i < 3) g_norm3[i] = 0.0f;
}

// ---------------- counting -------------------------------------------------
__global__ void k_count_edges(const int* __restrict__ ed, const int* __restrict__ esg,
                              const int* __restrict__ tli) {
    int i = blockIdx.x * blockDim.x + threadIdx.x;
    if (i >= E) return;
    int sg = esg[i];
    if (ed[i] == tli[sg]) atomicAdd(&g_ecnt[sg], 1);
}

__global__ void k_count_nodes(const int* __restrict__ nsg) {
    int i = blockIdx.x * blockDim.x + threadIdx.x;
    if (i >= NV) return;
    atomicAdd(&g_ncnt[nsg[i]], 1);
}

// ---------------- scan (1 block, 1024 threads, 4 elems/thread) -------------
__global__ void k_scan() {
    __shared__ int sh[1024];
    int tid = threadIdx.x;
    for (int p = 0; p < 2; p++) {
        int* cnt = p ? g_ncnt : g_ecnt;
        int* off = p ? g_noff : g_eoff;
        int* cur = p ? g_ncur : g_ecur;
        int b = tid * 4;
        int c0 = cnt[b], c1 = cnt[b + 1], c2 = cnt[b + 2], c3 = cnt[b + 3];
        int s = c0 + c1 + c2 + c3;
        sh[tid] = s;
        __syncthreads();
        for (int o = 1; o < 1024; o <<= 1) {
            int v = (tid >= o) ? sh[tid - o] : 0;
            __syncthreads();
            sh[tid] += v;
            __syncthreads();
        }
        int excl = sh[tid] - s;
        off[b] = excl;                    cur[b] = excl;
        off[b + 1] = excl + c0;           cur[b + 1] = excl + c0;
        off[b + 2] = excl + c0 + c1;      cur[b + 2] = excl + c0 + c1;
        off[b + 3] = excl + c0 + c1 + c2; cur[b + 3] = excl + c0 + c1 + c2;
        if (tid == 1023) off[T] = sh[tid];
        __syncthreads();
    }
}

// ---------------- scatter --------------------------------------------------
__global__ void k_scatter_edges(const int* __restrict__ ed, const int* __restrict__ esg,
                                const int* __restrict__ tli, const int* __restrict__ rel,
                                const float* __restrict__ tm, const int* __restrict__ esrc) {
    int i = blockIdx.x * blockDim.x + threadIdx.x;
    if (i >= E) return;
    int sg = esg[i];
    if (ed[i] != tli[sg]) return;
    int pos = atomicAdd(&g_ecur[sg], 1);
    float t = tm[i];
    g_eidx[pos] = (unsigned)i | ((rel[i] < NET) ? 0x80000000u : 0u);
    g_esrc[pos] = esrc[i];
    g_esw[pos] = expf(-t);
    g_elw[pos] = expf(-t * (1.0f / 24.0f));
    g_et[pos] = t;
}

__global__ void k_scatter_nodes(const int* __restrict__ nsg, const int* __restrict__ hop) {
    int i = blockIdx.x * blockDim.x + threadIdx.x;
    if (i >= NV) return;
    int pos = atomicAdd(&g_ncur[nsg[i]], 1);
    g_nlist[pos] = (unsigned)i | ((hop[i] == 1) ? 0x80000000u : 0u);
}

// ---------------- block reduce helpers (128 threads) -----------------------
__device__ __forceinline__ float blk_sum(float v, float* sb) {
#pragma unroll
    for (int o = 16; o > 0; o >>= 1) v += __shfl_xor_sync(0xffffffffu, v, o);
    __syncthreads();
    if ((threadIdx.x & 31) == 0) sb[threadIdx.x >> 5] = v;
    __syncthreads();
    return sb[0] + sb[1] + sb[2] + sb[3];
}

__device__ __forceinline__ float blk_ln(float x, float* sb) {
    float m = blk_sum(x, sb) * (1.0f / 128.0f);
    float d = x - m;
    float v = blk_sum(d * d, sb) * (1.0f / 128.0f);
    return d * rsqrtf(v + 1e-5f);
}

// ---------------- per-target aggregation + feature build -------------------
__global__ void __launch_bounds__(128) k_main(const float* __restrict__ node_repr,
                                              const float* __restrict__ edge_repr,
                                              const float* __restrict__ W1,
                                              const float* __restrict__ b1) {
    __shared__ float sb[4];
    int t = blockIdx.x;
    int h = threadIdx.x;

    float a_is = 0, a_os = 0, a_il = 0, a_ol = 0, a_hs = 0, a_hl = 0;
    float d_is = 0, d_os = 0, d_il = 0, d_ol = 0, sm = 0, lm = 0, tsum = 0, cin = 0, cout = 0;
    int e0 = g_eoff[t], e1 = g_eoff[t + 1];
    for (int i = e0; i < e1; i++) {
        unsigned pk = g_eidx[i];
        int e = pk & 0x7fffffff;
        int src = g_esrc[i];
        float sw = g_esw[i], lw = g_elw[i];
        float er = edge_repr[(size_t)e * H + h];
        float sr = node_repr[(size_t)src * H + h];
        if (pk & 0x80000000u) { a_is += sw * er; a_il += lw * er; d_is += sw; d_il += lw; cin += 1.0f; }
        else                  { a_os += sw * er; a_ol += lw * er; d_os += sw; d_ol += lw; cout += 1.0f; }
        a_hs += sw * sr; a_hl += lw * sr;
        sm += sw; lm += lw; tsum += g_et[i];
    }

    float a_h1 = 0, a_h2 = 0, c1 = 0, c2 = 0;
    int n0 = g_noff[t], n1 = g_noff[t + 1];
    for (int i = n0; i < n1; i++) {
        unsigned pk = g_nlist[i];
        int n = pk & 0x7fffffff;
        float nr = node_repr[(size_t)n * H + h];
        if (pk & 0x80000000u) { a_h1 += nr; c1 += 1.0f; }
        else                  { a_h2 += nr; c2 += 1.0f; }
    }

    float in_s  = a_is / fmaxf(d_is, 1e-6f);
    float out_s = a_os / fmaxf(d_os, 1e-6f);
    float in_l  = a_il / fmaxf(d_il, 1e-6f);
    float out_l = a_ol / fmaxf(d_ol, 1e-6f);
    float h1es  = a_hs / fmaxf(sm, 1e-6f);
    float h1el  = a_hl / fmaxf(lm, 1e-6f);
    float h1m   = a_h1 / fmaxf(c1, 1e-6f);
    float h2m   = a_h2 / fmaxf(c2, 1e-6f);

    float burst = blk_ln(in_s + out_s - in_l - out_l, sb);
    float dirg  = blk_ln(out_l - in_l, sb);
    float hopg  = blk_ln(h1m - h2m, sb);
    float slg   = blk_ln(h1es - h1el, sb);
    float asym  = blk_ln(fabsf(dirg), sb);
    float h1n   = blk_ln(h1m, sb);
    float h2n   = blk_ln(h2m, sb);
    float rb    = blk_ln(in_l + out_l, sb);

    float ssh = blk_sum(hopg * hopg, sb);
    float sss = blk_sum(slg * slg, sb);
    float ssd = blk_sum(dirg * dirg, sb);
    if (h == 0) {
        atomicAdd(&g_norm3[0], sqrtf(ssh));
        atomicAdd(&g_norm3[1], sqrtf(sss));
        atomicAdd(&g_norm3[2], sqrtf(ssd));
    }

    float* fr = g_fused + (size_t)t * FD;
    fr[h] = burst; fr[H + h] = dirg; fr[2 * H + h] = hopg; fr[3 * H + h] = slg;
    fr[4 * H + h] = asym; fr[5 * H + h] = h1n; fr[6 * H + h] = h2n; fr[7 * H + h] = rb;

    if (h < 32) {
        float s0 = log1pf(cin), s1 = log1pf(cout), s2 = log1pf(c1), s3 = log1pf(c2);
        float cnt = cin + cout;
        float s4 = tsum / fmaxf(cnt, 1e-6f);
        float s5 = sm, s6 = lm, s7 = sm - lm;
        float acc = b1[h];
        acc += s0 * W1[0 * 32 + h] + s1 * W1[1 * 32 + h] + s2 * W1[2 * 32 + h] + s3 * W1[3 * 32 + h]
             + s4 * W1[4 * 32 + h] + s5 * W1[5 * 32 + h] + s6 * W1[6 * 32 + h] + s7 * W1[7 * 32 + h];
        fr[8 * H + h] = gelu_exact(acc);
    }
}

// ---------------- GEMM1: [T,1056] @ [1056,256] + bias + GELU ---------------
// 64x64 tile, 128 threads, TM=4 TN=8, BK=16
__global__ void __launch_bounds__(128) k_gemm1(const float* __restrict__ W2,
                                               const float* __restrict__ b2) {
    __shared__ float As[16][72];
    __shared__ float Bs[16][64];
    int tid = threadIdx.x;
    int bm = blockIdx.x * 64, bn = blockIdx.y * 64;
    int arow = tid >> 1;           // 0..63
    int acol = (tid & 1) << 3;     // 0 or 8
    int br = tid >> 4;             // 0..7, plus br+8
    int bc = (tid & 15) << 2;      // 0..60
    int tm = (tid >> 3) << 2;      // 0..60
    int tn = (tid & 7) << 3;       // 0..56

    float acc[4][8];
#pragma unroll
    for (int i = 0; i < 4; i++)
#pragma unroll
        for (int j = 0; j < 8; j++) acc[i][j] = 0.0f;

    const float* Ap  = g_fused + (size_t)(bm + arow) * FD + acol;
    const float* Bp0 = W2 + (size_t)br * HD + bn + bc;
    const float* Bp1 = W2 + (size_t)(br + 8) * HD + bn + bc;

    for (int k0 = 0; k0 < FD; k0 += 16) {
        float4 av0 = *(const float4*)(Ap + k0);
        float4 av1 = *(const float4*)(Ap + k0 + 4);
        float4 bv0 = *(const float4*)(Bp0 + (size_t)k0 * HD);
        float4 bv1 = *(const float4*)(Bp1 + (size_t)k0 * HD);
        __syncthreads();
        As[acol + 0][arow] = av0.x; As[acol + 1][arow] = av0.y;
        As[acol + 2][arow] = av0.z; As[acol + 3][arow] = av0.w;
        As[acol + 4][arow] = av1.x; As[acol + 5][arow] = av1.y;
        As[acol + 6][arow] = av1.z; As[acol + 7][arow] = av1.w;
        *(float4*)&Bs[br][bc] = bv0;
        *(float4*)&Bs[br + 8][bc] = bv1;
        __syncthreads();
#pragma unroll
        for (int kk = 0; kk < 16; kk++) {
            float4 a4  = *(const float4*)&As[kk][tm];
            float4 b40 = *(const float4*)&Bs[kk][tn];
            float4 b41 = *(const float4*)&Bs[kk][tn + 4];
            float a[4] = {a4.x, a4.y, a4.z, a4.w};
            float b[8] = {b40.x, b40.y, b40.z, b40.w, b41.x, b41.y, b41.z, b41.w};
#pragma unroll
            for (int i = 0; i < 4; i++)
#pragma unroll
                for (int j = 0; j < 8; j++) acc[i][j] += a[i] * b[j];
        }
    }
#pragma unroll
    for (int i = 0; i < 4; i++) {
#pragma unroll
        for (int j = 0; j < 8; j++) {
            float x = acc[i][j] + b2[bn + tn + j];
            g_hidden[(size_t)(bm + tm + i) * HD + bn + tn + j] = gelu_exact(x);
        }
    }
}

// ---------------- GEMM2: [T,256] @ [256,128] + bias + 0.25*tanh ------------
// 16 targets per block, 256 threads
__global__ void __launch_bounds__(256) k_gemm2(const float* __restrict__ W3,
                                               const float* __restrict__ b3,
                                               float* __restrict__ out) {
    __shared__ float hs[16 * 256];
    int tid = threadIdx.x;
    int t0 = blockIdx.x * 16;
    for (int i = tid; i < 16 * 256; i += 256) hs[i] = g_hidden[(size_t)t0 * 256 + i];
    __syncthreads();
    int n = tid & 127;
    int half = tid >> 7;
    const float* hp = hs + half * 8 * 256;
    float acc[8] = {0, 0, 0, 0, 0, 0, 0, 0};
    for (int k = 0; k < 256; k += 4) {
        float w0 = W3[(k + 0) * 128 + n];
        float w1 = W3[(k + 1) * 128 + n];
        float w2 = W3[(k + 2) * 128 + n];
        float w3v = W3[(k + 3) * 128 + n];
#pragma unroll
        for (int r = 0; r < 8; r++) {
            float4 hv = *(const float4*)&hp[r * 256 + k];
            acc[r] += hv.x * w0 + hv.y * w1 + hv.z * w2 + hv.w * w3v;
        }
    }
    float bias = b3[n];
#pragma unroll
    for (int r = 0; r < 8; r++) {
        out[(size_t)(t0 + half * 8 + r) * 128 + n] = 0.25f * tanhf(acc[r] + bias);
    }
}

// ---------------- finalize norms -------------------------------------------
__global__ void k_finalize(float* __restrict__ out) {
    int i = threadIdx.x;
    if (i < 3) out[(size_t)T * H + i] = g_norm3[i] * (1.0f / (float)T);
}

// ---------------- launcher -------------------------------------------------
extern "C" void kernel_launch(void* const* d_in, const int* in_sizes, int n_in,
                              void* d_out, int out_size) {
    const float* node_repr = (const float*)d_in[0];
    const float* edge_repr = (const float*)d_in[1];
    const int*   edge_src  = (const int*)d_in[2];
    const int*   edge_dst  = (const int*)d_in[3];
    const int*   rel_ids   = (const int*)d_in[4];
    const float* etime     = (const float*)d_in[5];
    const int*   tli       = (const int*)d_in[6];
    const int*   nsg       = (const int*)d_in[7];
    const int*   esg       = (const int*)d_in[8];
    const int*   hop       = (const int*)d_in[9];
    const float* W1 = (const float*)d_in[10];
    const float* b1 = (const float*)d_in[11];
    const float* W2 = (const float*)d_in[12];
    const float* b2 = (const float*)d_in[13];
    const float* W3 = (const float*)d_in[14];
    const float* b3 = (const float*)d_in[15];
    float* out = (float*)d_out;

    k_init<<<16, 256>>>();
    k_count_edges<<<E / 256, 256>>>(edge_dst, esg, tli);
    k_count_nodes<<<NV / 256, 256>>>(nsg);
    k_scan<<<1, 1024>>>();
    k_scatter_edges<<<E / 256, 256>>>(edge_dst, esg, tli, rel_ids, etime, edge_src);
    k_scatter_nodes<<<NV / 256, 256>>>(nsg, hop);
    k_main<<<T, 128>>>(node_repr, edge_repr, W1, b1);
    k_gemm1<<<dim3(64, 4), 128>>>(W2, b2);
    k_gemm2<<<T / 16, 256>>>(W3, b3, out);
    k_finalize<<<1, 32>>>(out);
}

// round 2
// speedup vs baseline: 1.3042x; 1.3042x over previous
#include <cuda_runtime.h>
#include <cuda_bf16.h>

#define H 128
#define E 1048576
#define NV 262144
#define T 4096
#define NET 8
#define FD 1056   // 8*H + 32
#define HD 256    // 2*H

// ---------------- scratch ---------------------------------------------------
__device__ int g_ecnt[T];
__device__ int g_eoff[T + 1];
__device__ int g_ecur[T];
__device__ int g_ncnt[T];
__device__ int g_noff[T + 1];
__device__ int g_ncur[T];
__device__ float4   g_emeta[E];  // x: idx|flag bits, y: src bits, z: sw, w: lw
__device__ float    g_et[E];
__device__ unsigned g_nlist[NV]; // node idx | (is_hop1 << 31)
__device__ float g_fused[(size_t)T * FD];
__device__ float g_hidden[(size_t)T * HD];
__device__ float g_norm3[3];

typedef unsigned long long u64;

__device__ __forceinline__ float gelu_exact(float x) {
    return 0.5f * x * (1.0f + erff(x * 0.7071067811865476f));
}
__device__ __forceinline__ u64 pack2(float lo, float hi) {
    u64 r; asm("mov.b64 %0, {%1, %2};" : "=l"(r) : "f"(lo), "f"(hi)); return r;
}
__device__ __forceinline__ u64 rep2(float v) {
    u64 r; asm("mov.b64 %0, {%1, %1};" : "=l"(r) : "f"(v)); return r;
}
__device__ __forceinline__ void fma2(u64& acc, u64 a, u64 b) {
    asm("fma.rn.f32x2 %0, %1, %2, %0;" : "+l"(acc) : "l"(a), "l"(b));
}
__device__ __forceinline__ void unpack2(u64 v, float& lo, float& hi) {
    asm("mov.b64 {%0, %1}, %2;" : "=f"(lo), "=f"(hi) : "l"(v));
}

// ---------------- init ------------------------------------------------------
__global__ void k_init() {
    int i = blockIdx.x * blockDim.x + threadIdx.x;
    if (i < T) { g_ecnt[i] = 0; g_ncnt[i] = 0; }
    if (i < 3) g_norm3[i] = 0.0f;
}

// ---------------- counting (merged) -----------------------------------------
__global__ void k_count(const int* __restrict__ ed, const int* __restrict__ esg,
                        const int* __restrict__ tli, const int* __restrict__ nsg) {
    int i = blockIdx.x * blockDim.x + threadIdx.x;
    if (i < E) {
        int sg = esg[i];
        if (ed[i] == tli[sg]) atomicAdd(&g_ecnt[sg], 1);
    }
    if (i < NV) atomicAdd(&g_ncnt[nsg[i]], 1);
}

// ---------------- scan: warp-shuffle, 1024 threads, 4 elems/thread ----------
__global__ void k_scan() {
    __shared__ int wsum[32];
    int tid = threadIdx.x;
    int lane = tid & 31, w = tid >> 5;
    for (int p = 0; p < 2; p++) {
        int* cnt = p ? g_ncnt : g_ecnt;
        int* off = p ? g_noff : g_eoff;
        int* cur = p ? g_ncur : g_ecur;
        int b = tid * 4;
        int c0 = cnt[b], c1 = cnt[b + 1], c2 = cnt[b + 2], c3 = cnt[b + 3];
        int s = c0 + c1 + c2 + c3;
        int v = s;
#pragma unroll
        for (int o = 1; o < 32; o <<= 1) {
            int u = __shfl_up_sync(0xffffffffu, v, o);
            if (lane >= o) v += u;
        }
        if (lane == 31) wsum[w] = v;
        __syncthreads();
        if (w == 0) {
            int x = wsum[lane];
#pragma unroll
            for (int o = 1; o < 32; o <<= 1) {
                int u = __shfl_up_sync(0xffffffffu, x, o);
                if (lane >= o) x += u;
            }
            wsum[lane] = x;
        }
        __syncthreads();
        int excl = v - s + (w ? wsum[w - 1] : 0);
        off[b] = excl;                    cur[b] = excl;
        off[b + 1] = excl + c0;           cur[b + 1] = excl + c0;
        off[b + 2] = excl + c0 + c1;      cur[b + 2] = excl + c0 + c1;
        off[b + 3] = excl + c0 + c1 + c2; cur[b + 3] = excl + c0 + c1 + c2;
        if (tid == 0) off[T] = wsum[31];
        __syncthreads();
    }
}

// ---------------- scatter (merged) ------------------------------------------
__global__ void k_scatter(const int* __restrict__ ed, const int* __restrict__ esg,
                          const int* __restrict__ tli, const int* __restrict__ rel,
                          const float* __restrict__ tm, const int* __restrict__ esrc,
                          const int* __restrict__ nsg, const int* __restrict__ hop) {
    int i = blockIdx.x * blockDim.x + threadIdx.x;
    if (i < E) {
        int sg = esg[i];
        if (ed[i] == tli[sg]) {
            int pos = atomicAdd(&g_ecur[sg], 1);
            float t = tm[i];
            unsigned pk = (unsigned)i | ((rel[i] < NET) ? 0x80000000u : 0u);
            float4 mt;
            mt.x = __uint_as_float(pk);
            mt.y = __int_as_float(esrc[i]);
            mt.z = expf(-t);
            mt.w = expf(-t * (1.0f / 24.0f));
            g_emeta[pos] = mt;
            g_et[pos] = t;
        }
    }
    if (i < NV) {
        int pos = atomicAdd(&g_ncur[nsg[i]], 1);
        g_nlist[pos] = (unsigned)i | ((hop[i] == 1) ? 0x80000000u : 0u);
    }
}

// ---------------- block reduce helpers (128 threads) ------------------------
__device__ __forceinline__ float blk_sum(float v, float* sb) {
#pragma unroll
    for (int o = 16; o > 0; o >>= 1) v += __shfl_xor_sync(0xffffffffu, v, o);
    __syncthreads();
    if ((threadIdx.x & 31) == 0) sb[threadIdx.x >> 5] = v;
    __syncthreads();
    return sb[0] + sb[1] + sb[2] + sb[3];
}

__device__ __forceinline__ float blk_ln(float x, float* sb) {
    float m = blk_sum(x, sb) * (1.0f / 128.0f);
    float d = x - m;
    float v = blk_sum(d * d, sb) * (1.0f / 128.0f);
    return d * rsqrtf(v + 1e-5f);
}

// ---------------- per-target aggregation + feature build --------------------
__global__ void __launch_bounds__(128) k_main(const float* __restrict__ node_repr,
                                              const float* __restrict__ edge_repr,
                                              const float* __restrict__ W1,
                                              const float* __restrict__ b1) {
    __shared__ float sb[4];
    int t = blockIdx.x;
    int h = threadIdx.x;

    float a_is = 0, a_os = 0, a_il = 0, a_ol = 0, a_hs = 0, a_hl = 0;
    float d_is = 0, d_os = 0, d_il = 0, d_ol = 0, sm = 0, lm = 0, tsum = 0, cin = 0, cout = 0;
    int e0 = g_eoff[t], e1 = g_eoff[t + 1];
#pragma unroll 4
    for (int i = e0; i < e1; i++) {
        float4 mt = g_emeta[i];
        unsigned pk = __float_as_uint(mt.x);
        int e = pk & 0x7fffffff;
        int src = __float_as_int(mt.y);
        float sw = mt.z, lw = mt.w;
        float er = edge_repr[(size_t)e * H + h];
        float sr = node_repr[(size_t)src * H + h];
        if (pk & 0x80000000u) { a_is += sw * er; a_il += lw * er; d_is += sw; d_il += lw; cin += 1.0f; }
        else                  { a_os += sw * er; a_ol += lw * er; d_os += sw; d_ol += lw; cout += 1.0f; }
        a_hs += sw * sr; a_hl += lw * sr;
        sm += sw; lm += lw; tsum += g_et[i];
    }

    float a_h1 = 0, a_h2 = 0, c1 = 0, c2 = 0;
    int n0 = g_noff[t], n1 = g_noff[t + 1];
#pragma unroll 4
    for (int i = n0; i < n1; i++) {
        unsigned pk = g_nlist[i];
        int n = pk & 0x7fffffff;
        float nr = node_repr[(size_t)n * H + h];
        if (pk & 0x80000000u) { a_h1 += nr; c1 += 1.0f; }
        else                  { a_h2 += nr; c2 += 1.0f; }
    }

    float in_s  = a_is / fmaxf(d_is, 1e-6f);
    float out_s = a_os / fmaxf(d_os, 1e-6f);
    float in_l  = a_il / fmaxf(d_il, 1e-6f);
    float out_l = a_ol / fmaxf(d_ol, 1e-6f);
    float h1es  = a_hs / fmaxf(sm, 1e-6f);
    float h1el  = a_hl / fmaxf(lm, 1e-6f);
    float h1m   = a_h1 / fmaxf(c1, 1e-6f);
    float h2m   = a_h2 / fmaxf(c2, 1e-6f);

    float burst = blk_ln(in_s + out_s - in_l - out_l, sb);
    float dirg  = blk_ln(out_l - in_l, sb);
    float hopg  = blk_ln(h1m - h2m, sb);
    float slg   = blk_ln(h1es - h1el, sb);
    float asym  = blk_ln(fabsf(dirg), sb);
    float h1n   = blk_ln(h1m, sb);
    float h2n   = blk_ln(h2m, sb);
    float rb    = blk_ln(in_l + out_l, sb);

    float ssh = blk_sum(hopg * hopg, sb);
    float sss = blk_sum(slg * slg, sb);
    float ssd = blk_sum(dirg * dirg, sb);
    if (h == 0) {
        atomicAdd(&g_norm3[0], sqrtf(ssh));
        atomicAdd(&g_norm3[1], sqrtf(sss));
        atomicAdd(&g_norm3[2], sqrtf(ssd));
    }

    float* fr = g_fused + (size_t)t * FD;
    fr[h] = burst; fr[H + h] = dirg; fr[2 * H + h] = hopg; fr[3 * H + h] = slg;
    fr[4 * H + h] = asym; fr[5 * H + h] = h1n; fr[6 * H + h] = h2n; fr[7 * H + h] = rb;

    if (h < 32) {
        float s0 = log1pf(cin), s1 = log1pf(cout), s2 = log1pf(c1), s3 = log1pf(c2);
        float cnt = cin + cout;
        float s4 = tsum / fmaxf(cnt, 1e-6f);
        float s5 = sm, s6 = lm, s7 = sm - lm;
        float acc = b1[h];
        acc += s0 * W1[0 * 32 + h] + s1 * W1[1 * 32 + h] + s2 * W1[2 * 32 + h] + s3 * W1[3 * 32 + h]
             + s4 * W1[4 * 32 + h] + s5 * W1[5 * 32 + h] + s6 * W1[6 * 32 + h] + s7 * W1[7 * 32 + h];
        fr[8 * H + h] = gelu_exact(acc);
    }
}

// ---------------- GEMM1: [T,1056] @ [1056,256] + bias + GELU ----------------
// BM=128 BN=64 BK=16, 128 threads, TM=8 TN=8, f32x2 FMA, reg double-buffer.
// grid = (32, 4) = 128 blocks -> single wave on 148 SMs.
__global__ void __launch_bounds__(128) k_gemm1(const float* __restrict__ W2,
                                               const float* __restrict__ b2) {
    __shared__ float As[16][128];  // [k][m]
    __shared__ float Bs[16][64];   // [k][n]
    int tid = threadIdx.x;
    int bm = blockIdx.x * 128, bn = blockIdx.y * 64;
    int tn = (tid & 7) << 3;       // 0..56
    int tm = (tid >> 3) << 3;      // 0..120
    int br = tid >> 3;             // 0..15
    int bcc = (tid & 7) << 3;      // 0..56

    u64 acc2[4][8];
#pragma unroll
    for (int i = 0; i < 4; i++)
#pragma unroll
        for (int j = 0; j < 8; j++) acc2[i][j] = 0ull;

    const float* Ap = g_fused + (size_t)(bm + tid) * FD;
    const float* Bp = W2 + (size_t)br * HD + bn + bcc;

    // prefetch tile 0
    float4 ar[4]; float4 brg[2];
#pragma unroll
    for (int q = 0; q < 4; q++) ar[q] = *(const float4*)(Ap + q * 4);
    brg[0] = *(const float4*)(Bp);
    brg[1] = *(const float4*)(Bp + 4);

    for (int k0 = 0; k0 < FD; k0 += 16) {
        __syncthreads();
        // store transposed A
#pragma unroll
        for (int q = 0; q < 4; q++) {
            As[q * 4 + 0][tid] = ar[q].x; As[q * 4 + 1][tid] = ar[q].y;
            As[q * 4 + 2][tid] = ar[q].z; As[q * 4 + 3][tid] = ar[q].w;
        }
        *(float4*)&Bs[br][bcc] = brg[0];
        *(float4*)&Bs[br][bcc + 4] = brg[1];
        __syncthreads();
        if (k0 + 16 < FD) {
#pragma unroll
            for (int q = 0; q < 4; q++) ar[q] = *(const float4*)(Ap + k0 + 16 + q * 4);
            brg[0] = *(const float4*)(Bp + (size_t)(k0 + 16) * HD);
            brg[1] = *(const float4*)(Bp + (size_t)(k0 + 16) * HD + 4);
        }
#pragma unroll
        for (int kk = 0; kk < 16; kk++) {
            ulonglong2 av0 = *(const ulonglong2*)&As[kk][tm];
            ulonglong2 av1 = *(const ulonglong2*)&As[kk][tm + 4];
            float4 b0 = *(const float4*)&Bs[kk][tn];
            float4 b1v = *(const float4*)&Bs[kk][tn + 4];
            u64 aa[4] = {av0.x, av0.y, av1.x, av1.y};
            u64 bb[8];
            bb[0] = rep2(b0.x); bb[1] = rep2(b0.y); bb[2] = rep2(b0.z); bb[3] = rep2(b0.w);
            bb[4] = rep2(b1v.x); bb[5] = rep2(b1v.y); bb[6] = rep2(b1v.z); bb[7] = rep2(b1v.w);
#pragma unroll
            for (int m2 = 0; m2 < 4; m2++)
#pragma unroll
                for (int j = 0; j < 8; j++) fma2(acc2[m2][j], aa[m2], bb[j]);
        }
    }

    // epilogue: unpack pairs (m, m+1), add bias, gelu, store vectorized
#pragma unroll
    for (int m2 = 0; m2 < 4; m2++) {
        float r0[8], r1[8];
#pragma unroll
        for (int j = 0; j < 8; j++) {
            float lo, hi;
            unpack2(acc2[m2][j], lo, hi);
            float bias = b2[bn + tn + j];
            r0[j] = gelu_exact(lo + bias);
            r1[j] = gelu_exact(hi + bias);
        }
        int row0 = bm + tm + 2 * m2;
        float* p0 = g_hidden + (size_t)row0 * HD + bn + tn;
        float* p1 = p0 + HD;
        *(float4*)p0 = make_float4(r0[0], r0[1], r0[2], r0[3]);
        *(float4*)(p0 + 4) = make_float4(r0[4], r0[5], r0[6], r0[7]);
        *(float4*)p1 = make_float4(r1[0], r1[1], r1[2], r1[3]);
        *(float4*)(p1 + 4) = make_float4(r1[4], r1[5], r1[6], r1[7]);
    }
}

// ---------------- GEMM2: [T,256] @ [256,128] + bias + 0.25*tanh -------------
__global__ void __launch_bounds__(256) k_gemm2(const float* __restrict__ W3,
                                               const float* __restrict__ b3,
                                               float* __restrict__ out) {
    __shared__ float hs[16 * 256];
    int tid = threadIdx.x;
    int t0 = blockIdx.x * 16;
    for (int i = tid; i < 16 * 256; i += 256)
        hs[i] = g_hidden[(size_t)t0 * 256 + i];
    __syncthreads();
    int n = tid & 127;
    int half = tid >> 7;
    const float* hp = hs + half * 8 * 256;
    u64 acc2[8];
#pragma unroll
    for (int r = 0; r < 8; r++) acc2[r] = 0ull;
    for (int k = 0; k < 256; k += 4) {
        float w0 = W3[(k + 0) * 128 + n];
        float w1 = W3[(k + 1) * 128 + n];
        float w2 = W3[(k + 2) * 128 + n];
        float w3v = W3[(k + 3) * 128 + n];
        u64 w01 = pack2(w0, w1);
        u64 w23 = pack2(w2, w3v);
#pragma unroll
        for (int r = 0; r < 8; r++) {
            ulonglong2 hv = *(const ulonglong2*)&hp[r * 256 + k];
            fma2(acc2[r], hv.x, w01);
            fma2(acc2[r], hv.y, w23);
        }
    }
    float bias = b3[n];
#pragma unroll
    for (int r = 0; r < 8; r++) {
        float lo, hi;
        unpack2(acc2[r], lo, hi);
        out[(size_t)(t0 + half * 8 + r) * 128 + n] = 0.25f * tanhf(lo + hi + bias);
    }
}

// ---------------- finalize norms --------------------------------------------
__global__ void k_finalize(float* __restrict__ out) {
    int i = threadIdx.x;
    if (i < 3) out[(size_t)T * H + i] = g_norm3[i] * (1.0f / (float)T);
}

// ---------------- launcher --------------------------------------------------
extern "C" void kernel_launch(void* const* d_in, const int* in_sizes, int n_in,
                              void* d_out, int out_size) {
    const float* node_repr = (const float*)d_in[0];
    const float* edge_repr = (const float*)d_in[1];
    const int*   edge_src  = (const int*)d_in[2];
    const int*   edge_dst  = (const int*)d_in[3];
    const int*   rel_ids   = (const int*)d_in[4];
    const float* etime     = (const float*)d_in[5];
    const int*   tli       = (const int*)d_in[6];
    const int*   nsg       = (const int*)d_in[7];
    const int*   esg       = (const int*)d_in[8];
    const int*   hop       = (const int*)d_in[9];
    const float* W1 = (const float*)d_in[10];
    const float* b1 = (const float*)d_in[11];
    const float* W2 = (const float*)d_in[12];
    const float* b2 = (const float*)d_in[13];
    const float* W3 = (const float*)d_in[14];
    const float* b3 = (const float*)d_in[15];
    float* out = (float*)d_out;

    k_init<<<16, 256>>>();
    k_count<<<E / 256, 256>>>(edge_dst, esg, tli, nsg);
    k_scan<<<1, 1024>>>();
    k_scatter<<<E / 256, 256>>>(edge_dst, esg, tli, rel_ids, etime, edge_src, nsg, hop);
    k_main<<<T, 128>>>(node_repr, edge_repr, W1, b1);
    k_gemm1<<<dim3(32, 4), 128>>>(W2, b2);
    k_gemm2<<<T / 16, 256>>>(W3, b3, out);
    k_finalize<<<1, 32>>>(out);
}

// round 4
// speedup vs baseline: 1.5694x; 1.2034x over previous
#include <cuda_runtime.h>
#include <cuda_bf16.h>
#include <cstdint>

#define H 128
#define E 1048576
#define NV 262144
#define T 4096
#define NET 8
#define FD 1056   // 8*H + 32
#define HD 256    // 2*H

// ---------------- scratch ---------------------------------------------------
__device__ int g_ecnt[T];
__device__ int g_eoff[T + 1];
__device__ int g_ecur[T];
__device__ int g_ncnt[T];
__device__ int g_noff[T + 1];
__device__ int g_ncur[T];
__device__ float4   g_emeta[E];  // x: edge idx | (inbound<<31), y: src bits, z: sw, w: lw
__device__ unsigned g_nlist[NV]; // node idx | (is_hop1 << 31)
__device__ float g_fused[(size_t)T * FD];
__device__ float g_hidden[(size_t)T * HD];
__device__ float g_norm3[3];

typedef unsigned long long u64;

__device__ __forceinline__ float gelu_exact(float x) {
    return 0.5f * x * (1.0f + erff(x * 0.7071067811865476f));
}
__device__ __forceinline__ u64 pack2(float lo, float hi) {
    u64 r; asm("mov.b64 %0, {%1, %2};" : "=l"(r) : "f"(lo), "f"(hi)); return r;
}
__device__ __forceinline__ u64 rep2(float v) {
    u64 r; asm("mov.b64 %0, {%1, %1};" : "=l"(r) : "f"(v)); return r;
}
__device__ __forceinline__ void fma2(u64& acc, u64 a, u64 b) {
    asm("fma.rn.f32x2 %0, %1, %2, %0;" : "+l"(acc) : "l"(a), "l"(b));
}
__device__ __forceinline__ void unpack2(u64 v, float& lo, float& hi) {
    asm("mov.b64 {%0, %1}, %2;" : "=f"(lo), "=f"(hi) : "l"(v));
}

// ---------------- init ------------------------------------------------------
__global__ void k_init() {
    int i = blockIdx.x * blockDim.x + threadIdx.x;
    if (i < T) { g_ecnt[i] = 0; g_ncnt[i] = 0; }
    if (i < 3) g_norm3[i] = 0.0f;
}

// ---------------- counting (4 elems/thread, int4 loads) ---------------------
__global__ void k_count(const int* __restrict__ ed, const int* __restrict__ esg,
                        const int* __restrict__ tli, const int* __restrict__ nsg) {
    int i = blockIdx.x * blockDim.x + threadIdx.x;   // quad index
    if (i < E / 4) {
        int4 d4 = ((const int4*)ed)[i];
        int4 s4 = ((const int4*)esg)[i];
        if (d4.x == __ldg(&tli[s4.x])) atomicAdd(&g_ecnt[s4.x], 1);
        if (d4.y == __ldg(&tli[s4.y])) atomicAdd(&g_ecnt[s4.y], 1);
        if (d4.z == __ldg(&tli[s4.z])) atomicAdd(&g_ecnt[s4.z], 1);
        if (d4.w == __ldg(&tli[s4.w])) atomicAdd(&g_ecnt[s4.w], 1);
    }
    if (i < NV / 4) {
        int4 n4 = ((const int4*)nsg)[i];
        atomicAdd(&g_ncnt[n4.x], 1);
        atomicAdd(&g_ncnt[n4.y], 1);
        atomicAdd(&g_ncnt[n4.z], 1);
        atomicAdd(&g_ncnt[n4.w], 1);
    }
}

// ---------------- scan ------------------------------------------------------
__global__ void k_scan() {
    __shared__ int wsum[32];
    int tid = threadIdx.x;
    int lane = tid & 31, w = tid >> 5;
    for (int p = 0; p < 2; p++) {
        int* cnt = p ? g_ncnt : g_ecnt;
        int* off = p ? g_noff : g_eoff;
        int* cur = p ? g_ncur : g_ecur;
        int b = tid * 4;
        int c0 = cnt[b], c1 = cnt[b + 1], c2 = cnt[b + 2], c3 = cnt[b + 3];
        int s = c0 + c1 + c2 + c3;
        int v = s;
#pragma unroll
        for (int o = 1; o < 32; o <<= 1) {
            int u = __shfl_up_sync(0xffffffffu, v, o);
            if (lane >= o) v += u;
        }
        if (lane == 31) wsum[w] = v;
        __syncthreads();
        if (w == 0) {
            int x = wsum[lane];
#pragma unroll
            for (int o = 1; o < 32; o <<= 1) {
                int u = __shfl_up_sync(0xffffffffu, x, o);
                if (lane >= o) x += u;
            }
            wsum[lane] = x;
        }
        __syncthreads();
        int excl = v - s + (w ? wsum[w - 1] : 0);
        off[b] = excl;                    cur[b] = excl;
        off[b + 1] = excl + c0;           cur[b + 1] = excl + c0;
        off[b + 2] = excl + c0 + c1;      cur[b + 2] = excl + c0 + c1;
        off[b + 3] = excl + c0 + c1 + c2; cur[b + 3] = excl + c0 + c1 + c2;
        if (tid == 0) off[T] = wsum[31];
        __syncthreads();
    }
}

// ---------------- scatter (4 elems/thread) ----------------------------------
__global__ void k_scatter(const int* __restrict__ ed, const int* __restrict__ esg,
                          const int* __restrict__ tli, const int* __restrict__ rel,
                          const float* __restrict__ tm, const int* __restrict__ esrc,
                          const int* __restrict__ nsg, const int* __restrict__ hop) {
    int i = blockIdx.x * blockDim.x + threadIdx.x;   // quad index
    if (i < E / 4) {
        int4 d4 = ((const int4*)ed)[i];
        int4 s4 = ((const int4*)esg)[i];
        int4 r4 = ((const int4*)rel)[i];
        float4 t4 = ((const float4*)tm)[i];
        int4 sr4 = ((const int4*)esrc)[i];
        int dd[4] = {d4.x, d4.y, d4.z, d4.w};
        int ss[4] = {s4.x, s4.y, s4.z, s4.w};
        int rr[4] = {r4.x, r4.y, r4.z, r4.w};
        float tt[4] = {t4.x, t4.y, t4.z, t4.w};
        int sc[4] = {sr4.x, sr4.y, sr4.z, sr4.w};
#pragma unroll
        for (int q = 0; q < 4; q++) {
            if (dd[q] == __ldg(&tli[ss[q]])) {
                int pos = atomicAdd(&g_ecur[ss[q]], 1);
                float t = tt[q];
                unsigned pk = (unsigned)(i * 4 + q) | ((rr[q] < NET) ? 0x80000000u : 0u);
                float4 mt;
                mt.x = __uint_as_float(pk);
                mt.y = __int_as_float(sc[q]);
                mt.z = expf(-t);
                mt.w = expf(-t * (1.0f / 24.0f));
                g_emeta[pos] = mt;
            }
        }
    }
    if (i < NV / 4) {
        int4 n4 = ((const int4*)nsg)[i];
        int4 h4 = ((const int4*)hop)[i];
        int nn[4] = {n4.x, n4.y, n4.z, n4.w};
        int hh[4] = {h4.x, h4.y, h4.z, h4.w};
#pragma unroll
        for (int q = 0; q < 4; q++) {
            int pos = atomicAdd(&g_ncur[nn[q]], 1);
            g_nlist[pos] = (unsigned)(i * 4 + q) | ((hh[q] == 1) ? 0x80000000u : 0u);
        }
    }
}

// ---------------- block reduce helpers (128 threads) ------------------------
__device__ __forceinline__ float blk_sum(float v, float* sb) {
#pragma unroll
    for (int o = 16; o > 0; o >>= 1) v += __shfl_xor_sync(0xffffffffu, v, o);
    __syncthreads();
    if ((threadIdx.x & 31) == 0) sb[threadIdx.x >> 5] = v;
    __syncthreads();
    return sb[0] + sb[1] + sb[2] + sb[3];
}
__device__ __forceinline__ float blk_ln(float x, float* sb) {
    float m = blk_sum(x, sb) * (1.0f / 128.0f);
    float d = x - m;
    float v = blk_sum(d * d, sb) * (1.0f / 128.0f);
    return d * rsqrtf(v + 1e-5f);
}

// ---------------- per-target aggregation + feature build --------------------
// 4 warps; each warp owns one edge/node per iter; lane holds channels
// [lane*4, lane*4+4) as float4 -> 512B/warp coalesced rows, high MLP.
__global__ void __launch_bounds__(128) k_main(const float* __restrict__ node_repr,
                                              const float* __restrict__ edge_repr,
                                              const float* __restrict__ W1,
                                              const float* __restrict__ b1) {
    __shared__ float cmb[4][8][128];
    __shared__ float scmb[4][11];
    __shared__ float sb[4];
    int t = blockIdx.x;
    int tid = threadIdx.x;
    int wid = tid >> 5, lane = tid & 31;
    int c4 = lane << 2;

    float4 v_is = {0,0,0,0}, v_os = {0,0,0,0}, v_il = {0,0,0,0}, v_ol = {0,0,0,0};
    float4 v_hs = {0,0,0,0}, v_hl = {0,0,0,0};
    float d_is = 0, d_os = 0, d_il = 0, d_ol = 0, smw = 0, lmw = 0, tsum = 0, cin = 0, cout = 0;

    int e0 = g_eoff[t], e1 = g_eoff[t + 1];
#pragma unroll 2
    for (int i = e0 + wid; i < e1; i += 4) {
        float4 mt = g_emeta[i];
        unsigned pk = __float_as_uint(mt.x);
        int eidx = pk & 0x7fffffff;
        int src = __float_as_int(mt.y);
        float sw = mt.z, lw = mt.w;
        float4 er = *(const float4*)(edge_repr + (size_t)eidx * H + c4);
        float4 sr = *(const float4*)(node_repr + (size_t)src * H + c4);
        if (pk & 0x80000000u) {
            v_is.x += sw * er.x; v_is.y += sw * er.y; v_is.z += sw * er.z; v_is.w += sw * er.w;
            v_il.x += lw * er.x; v_il.y += lw * er.y; v_il.z += lw * er.z; v_il.w += lw * er.w;
            d_is += sw; d_il += lw; cin += 1.0f;
        } else {
            v_os.x += sw * er.x; v_os.y += sw * er.y; v_os.z += sw * er.z; v_os.w += sw * er.w;
            v_ol.x += lw * er.x; v_ol.y += lw * er.y; v_ol.z += lw * er.z; v_ol.w += lw * er.w;
            d_os += sw; d_ol += lw; cout += 1.0f;
        }
        v_hs.x += sw * sr.x; v_hs.y += sw * sr.y; v_hs.z += sw * sr.z; v_hs.w += sw * sr.w;
        v_hl.x += lw * sr.x; v_hl.y += lw * sr.y; v_hl.z += lw * sr.z; v_hl.w += lw * sr.w;
        smw += sw; lmw += lw; tsum += -__logf(sw);
    }

    float4 v_h1 = {0,0,0,0}, v_h2 = {0,0,0,0};
    float c1 = 0, c2 = 0;
    int n0 = g_noff[t], n1 = g_noff[t + 1];
#pragma unroll 2
    for (int i = n0 + wid; i < n1; i += 4) {
        unsigned pk = g_nlist[i];
        float4 nr = *(const float4*)(node_repr + (size_t)(pk & 0x7fffffff) * H + c4);
        if (pk & 0x80000000u) {
            v_h1.x += nr.x; v_h1.y += nr.y; v_h1.z += nr.z; v_h1.w += nr.w; c1 += 1.0f;
        } else {
            v_h2.x += nr.x; v_h2.y += nr.y; v_h2.z += nr.z; v_h2.w += nr.w; c2 += 1.0f;
        }
    }

    *(float4*)&cmb[wid][0][c4] = v_is;
    *(float4*)&cmb[wid][1][c4] = v_os;
    *(float4*)&cmb[wid][2][c4] = v_il;
    *(float4*)&cmb[wid][3][c4] = v_ol;
    *(float4*)&cmb[wid][4][c4] = v_hs;
    *(float4*)&cmb[wid][5][c4] = v_hl;
    *(float4*)&cmb[wid][6][c4] = v_h1;
    *(float4*)&cmb[wid][7][c4] = v_h2;
    if (lane == 0) {
        scmb[wid][0] = d_is; scmb[wid][1] = d_os; scmb[wid][2] = d_il; scmb[wid][3] = d_ol;
        scmb[wid][4] = smw;  scmb[wid][5] = lmw;  scmb[wid][6] = tsum; scmb[wid][7] = cin;
        scmb[wid][8] = cout; scmb[wid][9] = c1;   scmb[wid][10] = c2;
    }
    __syncthreads();

    int h = tid;
    float a_is = cmb[0][0][h] + cmb[1][0][h] + cmb[2][0][h] + cmb[3][0][h];
    float a_os = cmb[0][1][h] + cmb[1][1][h] + cmb[2][1][h] + cmb[3][1][h];
    float a_il = cmb[0][2][h] + cmb[1][2][h] + cmb[2][2][h] + cmb[3][2][h];
    float a_ol = cmb[0][3][h] + cmb[1][3][h] + cmb[2][3][h] + cmb[3][3][h];
    float a_hs = cmb[0][4][h] + cmb[1][4][h] + cmb[2][4][h] + cmb[3][4][h];
    float a_hl = cmb[0][5][h] + cmb[1][5][h] + cmb[2][5][h] + cmb[3][5][h];
    float a_h1 = cmb[0][6][h] + cmb[1][6][h] + cmb[2][6][h] + cmb[3][6][h];
    float a_h2 = cmb[0][7][h] + cmb[1][7][h] + cmb[2][7][h] + cmb[3][7][h];
    d_is = scmb[0][0] + scmb[1][0] + scmb[2][0] + scmb[3][0];
    d_os = scmb[0][1] + scmb[1][1] + scmb[2][1] + scmb[3][1];
    d_il = scmb[0][2] + scmb[1][2] + scmb[2][2] + scmb[3][2];
    d_ol = scmb[0][3] + scmb[1][3] + scmb[2][3] + scmb[3][3];
    smw  = scmb[0][4] + scmb[1][4] + scmb[2][4] + scmb[3][4];
    lmw  = scmb[0][5] + scmb[1][5] + scmb[2][5] + scmb[3][5];
    tsum = scmb[0][6] + scmb[1][6] + scmb[2][6] + scmb[3][6];
    cin  = scmb[0][7] + scmb[1][7] + scmb[2][7] + scmb[3][7];
    cout = scmb[0][8] + scmb[1][8] + scmb[2][8] + scmb[3][8];
    c1   = scmb[0][9] + scmb[1][9] + scmb[2][9] + scmb[3][9];
    c2   = scmb[0][10] + scmb[1][10] + scmb[2][10] + scmb[3][10];

    float in_s  = a_is / fmaxf(d_is, 1e-6f);
    float out_s = a_os / fmaxf(d_os, 1e-6f);
    float in_l  = a_il / fmaxf(d_il, 1e-6f);
    float out_l = a_ol / fmaxf(d_ol, 1e-6f);
    float h1es  = a_hs / fmaxf(smw, 1e-6f);
    float h1el  = a_hl / fmaxf(lmw, 1e-6f);
    float h1m   = a_h1 / fmaxf(c1, 1e-6f);
    float h2m   = a_h2 / fmaxf(c2, 1e-6f);

    float burst = blk_ln(in_s + out_s - in_l - out_l, sb);
    float dirg  = blk_ln(out_l - in_l, sb);
    float hopg  = blk_ln(h1m - h2m, sb);
    float slg   = blk_ln(h1es - h1el, sb);
    float asym  = blk_ln(fabsf(dirg), sb);
    float h1n   = blk_ln(h1m, sb);
    float h2n   = blk_ln(h2m, sb);
    float rb    = blk_ln(in_l + out_l, sb);

    float ssh = blk_sum(hopg * hopg, sb);
    float sss = blk_sum(slg * slg, sb);
    float ssd = blk_sum(dirg * dirg, sb);
    if (h == 0) {
        atomicAdd(&g_norm3[0], sqrtf(ssh));
        atomicAdd(&g_norm3[1], sqrtf(sss));
        atomicAdd(&g_norm3[2], sqrtf(ssd));
    }

    float* fr = g_fused + (size_t)t * FD;
    fr[h] = burst; fr[H + h] = dirg; fr[2 * H + h] = hopg; fr[3 * H + h] = slg;
    fr[4 * H + h] = asym; fr[5 * H + h] = h1n; fr[6 * H + h] = h2n; fr[7 * H + h] = rb;

    if (h < 32) {
        float s0 = log1pf(cin), s1 = log1pf(cout), s2 = log1pf(c1), s3 = log1pf(c2);
        float cnt = cin + cout;
        float s4 = tsum / fmaxf(cnt, 1e-6f);
        float s5 = smw, s6 = lmw, s7 = smw - lmw;
        float acc = b1[h];
        acc += s0 * W1[0 * 32 + h] + s1 * W1[1 * 32 + h] + s2 * W1[2 * 32 + h] + s3 * W1[3 * 32 + h]
             + s4 * W1[4 * 32 + h] + s5 * W1[5 * 32 + h] + s6 * W1[6 * 32 + h] + s7 * W1[7 * 32 + h];
        fr[8 * H + h] = gelu_exact(acc);
    }
}

// ---------------- GEMM1: [T,1056] @ [1056,256] + bias + GELU ----------------
// BM=128 BN=64 BK=16, 128 threads, TM=8 TN=8, f32x2 FMA, reg double-buffer.
__global__ void __launch_bounds__(128) k_gemm1(const float* __restrict__ W2,
                                               const float* __restrict__ b2) {
    __shared__ float As[16][128];  // [k][m]
    __shared__ float Bs[16][64];   // [k][n]
    int tid = threadIdx.x;
    int bm = blockIdx.x * 128, bn = blockIdx.y * 64;
    int tn = (tid & 7) << 3;
    int tm = (tid >> 3) << 3;
    int br = tid >> 3;
    int bcc = (tid & 7) << 3;

    u64 acc2[4][8];
#pragma unroll
    for (int i = 0; i < 4; i++)
#pragma unroll
        for (int j = 0; j < 8; j++) acc2[i][j] = 0ull;

    const float* Ap = g_fused + (size_t)(bm + tid) * FD;
    const float* Bp = W2 + (size_t)br * HD + bn + bcc;

    float4 ar[4]; float4 brg[2];
#pragma unroll
    for (int q = 0; q < 4; q++) ar[q] = *(const float4*)(Ap + q * 4);
    brg[0] = *(const float4*)(Bp);
    brg[1] = *(const float4*)(Bp + 4);

    for (int k0 = 0; k0 < FD; k0 += 16) {
        __syncthreads();
#pragma unroll
        for (int q = 0; q < 4; q++) {
            As[q * 4 + 0][tid] = ar[q].x; As[q * 4 + 1][tid] = ar[q].y;
            As[q * 4 + 2][tid] = ar[q].z; As[q * 4 + 3][tid] = ar[q].w;
        }
        *(float4*)&Bs[br][bcc] = brg[0];
        *(float4*)&Bs[br][bcc + 4] = brg[1];
        __syncthreads();
        if (k0 + 16 < FD) {
#pragma unroll
            for (int q = 0; q < 4; q++) ar[q] = *(const float4*)(Ap + k0 + 16 + q * 4);
            brg[0] = *(const float4*)(Bp + (size_t)(k0 + 16) * HD);
            brg[1] = *(const float4*)(Bp + (size_t)(k0 + 16) * HD + 4);
        }
#pragma unroll
        for (int kk = 0; kk < 16; kk++) {
            ulonglong2 av0 = *(const ulonglong2*)&As[kk][tm];
            ulonglong2 av1 = *(const ulonglong2*)&As[kk][tm + 4];
            float4 b0 = *(const float4*)&Bs[kk][tn];
            float4 b1v = *(const float4*)&Bs[kk][tn + 4];
            u64 aa[4] = {av0.x, av0.y, av1.x, av1.y};
            u64 bb[8];
            bb[0] = rep2(b0.x); bb[1] = rep2(b0.y); bb[2] = rep2(b0.z); bb[3] = rep2(b0.w);
            bb[4] = rep2(b1v.x); bb[5] = rep2(b1v.y); bb[6] = rep2(b1v.z); bb[7] = rep2(b1v.w);
#pragma unroll
            for (int m2 = 0; m2 < 4; m2++)
#pragma unroll
                for (int j = 0; j < 8; j++) fma2(acc2[m2][j], aa[m2], bb[j]);
        }
    }

#pragma unroll
    for (int m2 = 0; m2 < 4; m2++) {
        float r0[8], r1[8];
#pragma unroll
        for (int j = 0; j < 8; j++) {
            float lo, hi;
            unpack2(acc2[m2][j], lo, hi);
            float bias = b2[bn + tn + j];
            r0[j] = gelu_exact(lo + bias);
            r1[j] = gelu_exact(hi + bias);
        }
        int row0 = bm + tm + 2 * m2;
        float* p0 = g_hidden + (size_t)row0 * HD + bn + tn;
        float* p1 = p0 + HD;
        *(float4*)p0 = make_float4(r0[0], r0[1], r0[2], r0[3]);
        *(float4*)(p0 + 4) = make_float4(r0[4], r0[5], r0[6], r0[7]);
        *(float4*)p1 = make_float4(r1[0], r1[1], r1[2], r1[3]);
        *(float4*)(p1 + 4) = make_float4(r1[4], r1[5], r1[6], r1[7]);
    }
}

// ---------------- GEMM2: [T,256] @ [256,128] + bias + 0.25*tanh -------------
__global__ void __launch_bounds__(256) k_gemm2(const float* __restrict__ W3,
                                               const float* __restrict__ b3,
                                               float* __restrict__ out) {
    __shared__ float hs[16 * 256];
    int tid = threadIdx.x;
    int t0 = blockIdx.x * 16;
    for (int i = tid; i < 16 * 256; i += 256)
        hs[i] = g_hidden[(size_t)t0 * 256 + i];
    __syncthreads();
    int n = tid & 127;
    int half = tid >> 7;
    const float* hp = hs + half * 8 * 256;
    u64 acc2[8];
#pragma unroll
    for (int r = 0; r < 8; r++) acc2[r] = 0ull;
    for (int k = 0; k < 256; k += 4) {
        float w0 = W3[(k + 0) * 128 + n];
        float w1 = W3[(k + 1) * 128 + n];
        float w2 = W3[(k + 2) * 128 + n];
        float w3v = W3[(k + 3) * 128 + n];
        u64 w01 = pack2(w0, w1);
        u64 w23 = pack2(w2, w3v);
#pragma unroll
        for (int r = 0; r < 8; r++) {
            ulonglong2 hv = *(const ulonglong2*)&hp[r * 256 + k];
            fma2(acc2[r], hv.x, w01);
            fma2(acc2[r], hv.y, w23);
        }
    }
    float bias = b3[n];
#pragma unroll
    for (int r = 0; r < 8; r++) {
        float lo, hi;
        unpack2(acc2[r], lo, hi);
        out[(size_t)(t0 + half * 8 + r) * 128 + n] = 0.25f * tanhf(lo + hi + bias);
    }
}

// ---------------- finalize norms --------------------------------------------
__global__ void k_finalize(float* __restrict__ out) {
    int i = threadIdx.x;
    if (i < 3) out[(size_t)T * H + i] = g_norm3[i] * (1.0f / (float)T);
}

// ---------------- launcher --------------------------------------------------
extern "C" void kernel_launch(void* const* d_in, const int* in_sizes, int n_in,
                              void* d_out, int out_size) {
    const float* node_repr = (const float*)d_in[0];
    const float* edge_repr = (const float*)d_in[1];
    const int*   edge_src  = (const int*)d_in[2];
    const int*   edge_dst  = (const int*)d_in[3];
    const int*   rel_ids   = (const int*)d_in[4];
    const float* etime     = (const float*)d_in[5];
    const int*   tli       = (const int*)d_in[6];
    const int*   nsg       = (const int*)d_in[7];
    const int*   esg       = (const int*)d_in[8];
    const int*   hop       = (const int*)d_in[9];
    const float* W1 = (const float*)d_in[10];
    const float* b1 = (const float*)d_in[11];
    const float* W2 = (const float*)d_in[12];
    const float* b2 = (const float*)d_in[13];
    const float* W3 = (const float*)d_in[14];
    const float* b3 = (const float*)d_in[15];
    float* out = (float*)d_out;

    k_init<<<16, 256>>>();
    k_count<<<E / 4 / 256, 256>>>(edge_dst, esg, tli, nsg);
    k_scan<<<1, 1024>>>();
    k_scatter<<<E / 4 / 256, 256>>>(edge_dst, esg, tli, rel_ids, etime, edge_src, nsg, hop);
    k_main<<<T, 128>>>(node_repr, edge_repr, W1, b1);
    k_gemm1<<<dim3(32, 4), 128>>>(W2, b2);
    k_gemm2<<<T / 16, 256>>>(W3, b3, out);
    k_finalize<<<1, 32>>>(out);
}

// round 5
// speedup vs baseline: 1.7145x; 1.0925x over previous
#include <cuda_runtime.h>
#include <cuda_bf16.h>
#include <cstdint>

#define H 128
#define E 1048576
#define NV 262144
#define T 4096
#define NET 8
#define FD 1056   // 8*H + 32
#define HD 256    // 2*H
#define ECAP 256  // edge bucket capacity per target (mean 64, sigma 8)
#define NCAP 256  // node bucket capacity per target

// ---------------- scratch ---------------------------------------------------
__device__ int g_ecnt[T];
__device__ int g_ncnt[T];
__device__ float4   g_emeta[(size_t)T * ECAP]; // x: idx|inbound<<31, y: src, z: sw, w: lw
__device__ unsigned g_nlist[(size_t)T * NCAP]; // node idx | (is_hop1 << 31)
__device__ float g_fused[(size_t)T * FD];
__device__ float g_hidden[(size_t)T * HD];
__device__ float g_norm3[3];

typedef unsigned long long u64;

__device__ __forceinline__ float gelu_exact(float x) {
    return 0.5f * x * (1.0f + erff(x * 0.7071067811865476f));
}
__device__ __forceinline__ u64 pack2(float lo, float hi) {
    u64 r; asm("mov.b64 %0, {%1, %2};" : "=l"(r) : "f"(lo), "f"(hi)); return r;
}
__device__ __forceinline__ u64 rep2(float v) {
    u64 r; asm("mov.b64 %0, {%1, %1};" : "=l"(r) : "f"(v)); return r;
}
__device__ __forceinline__ void fma2(u64& acc, u64 a, u64 b) {
    asm("fma.rn.f32x2 %0, %1, %2, %0;" : "+l"(acc) : "l"(a), "l"(b));
}
__device__ __forceinline__ void unpack2(u64 v, float& lo, float& hi) {
    asm("mov.b64 {%0, %1}, %2;" : "=f"(lo), "=f"(hi) : "l"(v));
}

// ---------------- init ------------------------------------------------------
__global__ void k_init() {
    int i = blockIdx.x * blockDim.x + threadIdx.x;
    if (i < T) { g_ecnt[i] = 0; g_ncnt[i] = 0; }
    if (i < 3) g_norm3[i] = 0.0f;
}

// ---------------- scatter into fixed-capacity buckets -----------------------
// blocks [0, E/4/256): edges, 4/thread. blocks [E/4/256, +NV/4/256): nodes.
#define EBLK (E / 4 / 256)
#define NBLK (NV / 4 / 256)
__global__ void k_scatter(const int* __restrict__ ed, const int* __restrict__ esg,
                          const int* __restrict__ tli, const int* __restrict__ rel,
                          const float* __restrict__ tm, const int* __restrict__ esrc,
                          const int* __restrict__ nsg, const int* __restrict__ hop) {
    int b = blockIdx.x;
    if (b < EBLK) {
        int i = b * 256 + threadIdx.x;   // quad index
        int4 d4 = ((const int4*)ed)[i];
        int4 s4 = ((const int4*)esg)[i];
        int4 r4 = ((const int4*)rel)[i];
        float4 t4 = ((const float4*)tm)[i];
        int4 sr4 = ((const int4*)esrc)[i];
        int dd[4] = {d4.x, d4.y, d4.z, d4.w};
        int ss[4] = {s4.x, s4.y, s4.z, s4.w};
        int rr[4] = {r4.x, r4.y, r4.z, r4.w};
        float tt[4] = {t4.x, t4.y, t4.z, t4.w};
        int sc[4] = {sr4.x, sr4.y, sr4.z, sr4.w};
#pragma unroll
        for (int q = 0; q < 4; q++) {
            if (dd[q] == __ldg(&tli[ss[q]])) {
                int pos = atomicAdd(&g_ecnt[ss[q]], 1);
                float t = tt[q];
                unsigned pk = (unsigned)(i * 4 + q) | ((rr[q] < NET) ? 0x80000000u : 0u);
                float4 mt;
                mt.x = __uint_as_float(pk);
                mt.y = __int_as_float(sc[q]);
                mt.z = expf(-t);
                mt.w = expf(-t * (1.0f / 24.0f));
                g_emeta[(size_t)ss[q] * ECAP + pos] = mt;
            }
        }
    } else {
        int i = (b - EBLK) * 256 + threadIdx.x;  // quad index
        int4 n4 = ((const int4*)nsg)[i];
        int4 h4 = ((const int4*)hop)[i];
        int nn[4] = {n4.x, n4.y, n4.z, n4.w};
        int hh[4] = {h4.x, h4.y, h4.z, h4.w};
#pragma unroll
        for (int q = 0; q < 4; q++) {
            int pos = atomicAdd(&g_ncnt[nn[q]], 1);
            g_nlist[(size_t)nn[q] * NCAP + pos] =
                (unsigned)(i * 4 + q) | ((hh[q] == 1) ? 0x80000000u : 0u);
        }
    }
}

// ---------------- block reduce helpers (128 threads) ------------------------
__device__ __forceinline__ float blk_sum(float v, float* sb) {
#pragma unroll
    for (int o = 16; o > 0; o >>= 1) v += __shfl_xor_sync(0xffffffffu, v, o);
    __syncthreads();
    if ((threadIdx.x & 31) == 0) sb[threadIdx.x >> 5] = v;
    __syncthreads();
    return sb[0] + sb[1] + sb[2] + sb[3];
}
__device__ __forceinline__ float blk_ln(float x, float* sb) {
    float m = blk_sum(x, sb) * (1.0f / 128.0f);
    float d = x - m;
    float v = blk_sum(d * d, sb) * (1.0f / 128.0f);
    return d * rsqrtf(v + 1e-5f);
}

// ---------------- per-target aggregation + feature build --------------------
__global__ void __launch_bounds__(128) k_main(const float* __restrict__ node_repr,
                                              const float* __restrict__ edge_repr,
                                              const float* __restrict__ W1,
                                              const float* __restrict__ b1) {
    __shared__ float cmb[4][8][128];
    __shared__ float scmb[4][11];
    __shared__ float sb[4];
    int t = blockIdx.x;
    int tid = threadIdx.x;
    int wid = tid >> 5, lane = tid & 31;
    int c4 = lane << 2;

    float4 v_is = {0,0,0,0}, v_os = {0,0,0,0}, v_il = {0,0,0,0}, v_ol = {0,0,0,0};
    float4 v_hs = {0,0,0,0}, v_hl = {0,0,0,0};
    float d_is = 0, d_os = 0, d_il = 0, d_ol = 0, smw = 0, lmw = 0, tsum = 0, cin = 0, cout = 0;

    int ecount = g_ecnt[t];
    const float4* ebase = g_emeta + (size_t)t * ECAP;
#pragma unroll 2
    for (int i = wid; i < ecount; i += 4) {
        float4 mt = ebase[i];
        unsigned pk = __float_as_uint(mt.x);
        int eidx = pk & 0x7fffffff;
        int src = __float_as_int(mt.y);
        float sw = mt.z, lw = mt.w;
        float4 er = *(const float4*)(edge_repr + (size_t)eidx * H + c4);
        float4 sr = *(const float4*)(node_repr + (size_t)src * H + c4);
        if (pk & 0x80000000u) {
            v_is.x += sw * er.x; v_is.y += sw * er.y; v_is.z += sw * er.z; v_is.w += sw * er.w;
            v_il.x += lw * er.x; v_il.y += lw * er.y; v_il.z += lw * er.z; v_il.w += lw * er.w;
            d_is += sw; d_il += lw; cin += 1.0f;
        } else {
            v_os.x += sw * er.x; v_os.y += sw * er.y; v_os.z += sw * er.z; v_os.w += sw * er.w;
            v_ol.x += lw * er.x; v_ol.y += lw * er.y; v_ol.z += lw * er.z; v_ol.w += lw * er.w;
            d_os += sw; d_ol += lw; cout += 1.0f;
        }
        v_hs.x += sw * sr.x; v_hs.y += sw * sr.y; v_hs.z += sw * sr.z; v_hs.w += sw * sr.w;
        v_hl.x += lw * sr.x; v_hl.y += lw * sr.y; v_hl.z += lw * sr.z; v_hl.w += lw * sr.w;
        smw += sw; lmw += lw; tsum += -__logf(sw);
    }

    float4 v_h1 = {0,0,0,0}, v_h2 = {0,0,0,0};
    float c1 = 0, c2 = 0;
    int ncount = g_ncnt[t];
    const unsigned* nbase = g_nlist + (size_t)t * NCAP;
#pragma unroll 2
    for (int i = wid; i < ncount; i += 4) {
        unsigned pk = nbase[i];
        float4 nr = *(const float4*)(node_repr + (size_t)(pk & 0x7fffffff) * H + c4);
        if (pk & 0x80000000u) {
            v_h1.x += nr.x; v_h1.y += nr.y; v_h1.z += nr.z; v_h1.w += nr.w; c1 += 1.0f;
        } else {
            v_h2.x += nr.x; v_h2.y += nr.y; v_h2.z += nr.z; v_h2.w += nr.w; c2 += 1.0f;
        }
    }

    *(float4*)&cmb[wid][0][c4] = v_is;
    *(float4*)&cmb[wid][1][c4] = v_os;
    *(float4*)&cmb[wid][2][c4] = v_il;
    *(float4*)&cmb[wid][3][c4] = v_ol;
    *(float4*)&cmb[wid][4][c4] = v_hs;
    *(float4*)&cmb[wid][5][c4] = v_hl;
    *(float4*)&cmb[wid][6][c4] = v_h1;
    *(float4*)&cmb[wid][7][c4] = v_h2;
    if (lane == 0) {
        scmb[wid][0] = d_is; scmb[wid][1] = d_os; scmb[wid][2] = d_il; scmb[wid][3] = d_ol;
        scmb[wid][4] = smw;  scmb[wid][5] = lmw;  scmb[wid][6] = tsum; scmb[wid][7] = cin;
        scmb[wid][8] = cout; scmb[wid][9] = c1;   scmb[wid][10] = c2;
    }
    __syncthreads();

    int h = tid;
    float a_is = cmb[0][0][h] + cmb[1][0][h] + cmb[2][0][h] + cmb[3][0][h];
    float a_os = cmb[0][1][h] + cmb[1][1][h] + cmb[2][1][h] + cmb[3][1][h];
    float a_il = cmb[0][2][h] + cmb[1][2][h] + cmb[2][2][h] + cmb[3][2][h];
    float a_ol = cmb[0][3][h] + cmb[1][3][h] + cmb[2][3][h] + cmb[3][3][h];
    float a_hs = cmb[0][4][h] + cmb[1][4][h] + cmb[2][4][h] + cmb[3][4][h];
    float a_hl = cmb[0][5][h] + cmb[1][5][h] + cmb[2][5][h] + cmb[3][5][h];
    float a_h1 = cmb[0][6][h] + cmb[1][6][h] + cmb[2][6][h] + cmb[3][6][h];
    float a_h2 = cmb[0][7][h] + cmb[1][7][h] + cmb[2][7][h] + cmb[3][7][h];
    d_is = scmb[0][0] + scmb[1][0] + scmb[2][0] + scmb[3][0];
    d_os = scmb[0][1] + scmb[1][1] + scmb[2][1] + scmb[3][1];
    d_il = scmb[0][2] + scmb[1][2] + scmb[2][2] + scmb[3][2];
    d_ol = scmb[0][3] + scmb[1][3] + scmb[2][3] + scmb[3][3];
    smw  = scmb[0][4] + scmb[1][4] + scmb[2][4] + scmb[3][4];
    lmw  = scmb[0][5] + scmb[1][5] + scmb[2][5] + scmb[3][5];
    tsum = scmb[0][6] + scmb[1][6] + scmb[2][6] + scmb[3][6];
    cin  = scmb[0][7] + scmb[1][7] + scmb[2][7] + scmb[3][7];
    cout = scmb[0][8] + scmb[1][8] + scmb[2][8] + scmb[3][8];
    c1   = scmb[0][9] + scmb[1][9] + scmb[2][9] + scmb[3][9];
    c2   = scmb[0][10] + scmb[1][10] + scmb[2][10] + scmb[3][10];

    float in_s  = a_is / fmaxf(d_is, 1e-6f);
    float out_s = a_os / fmaxf(d_os, 1e-6f);
    float in_l  = a_il / fmaxf(d_il, 1e-6f);
    float out_l = a_ol / fmaxf(d_ol, 1e-6f);
    float h1es  = a_hs / fmaxf(smw, 1e-6f);
    float h1el  = a_hl / fmaxf(lmw, 1e-6f);
    float h1m   = a_h1 / fmaxf(c1, 1e-6f);
    float h2m   = a_h2 / fmaxf(c2, 1e-6f);

    float burst = blk_ln(in_s + out_s - in_l - out_l, sb);
    float dirg  = blk_ln(out_l - in_l, sb);
    float hopg  = blk_ln(h1m - h2m, sb);
    float slg   = blk_ln(h1es - h1el, sb);
    float asym  = blk_ln(fabsf(dirg), sb);
    float h1n   = blk_ln(h1m, sb);
    float h2n   = blk_ln(h2m, sb);
    float rb    = blk_ln(in_l + out_l, sb);

    float ssh = blk_sum(hopg * hopg, sb);
    float sss = blk_sum(slg * slg, sb);
    float ssd = blk_sum(dirg * dirg, sb);
    if (h == 0) {
        atomicAdd(&g_norm3[0], sqrtf(ssh));
        atomicAdd(&g_norm3[1], sqrtf(sss));
        atomicAdd(&g_norm3[2], sqrtf(ssd));
    }

    float* fr = g_fused + (size_t)t * FD;
    fr[h] = burst; fr[H + h] = dirg; fr[2 * H + h] = hopg; fr[3 * H + h] = slg;
    fr[4 * H + h] = asym; fr[5 * H + h] = h1n; fr[6 * H + h] = h2n; fr[7 * H + h] = rb;

    if (h < 32) {
        float s0 = log1pf(cin), s1 = log1pf(cout), s2 = log1pf(c1), s3 = log1pf(c2);
        float cnt = cin + cout;
        float s4 = tsum / fmaxf(cnt, 1e-6f);
        float s5 = smw, s6 = lmw, s7 = smw - lmw;
        float acc = b1[h];
        acc += s0 * W1[0 * 32 + h] + s1 * W1[1 * 32 + h] + s2 * W1[2 * 32 + h] + s3 * W1[3 * 32 + h]
             + s4 * W1[4 * 32 + h] + s5 * W1[5 * 32 + h] + s6 * W1[6 * 32 + h] + s7 * W1[7 * 32 + h];
        fr[8 * H + h] = gelu_exact(acc);
    }
}

// ---------------- GEMM1: [T,1056] @ [1056,256] + bias + GELU ----------------
// BM=128 BN=64 BK=16, 128 threads, TM=8 TN=8, f32x2 FMA, reg double-buffer.
__global__ void __launch_bounds__(128) k_gemm1(const float* __restrict__ W2,
                                               const float* __restrict__ b2) {
    __shared__ float As[16][128];  // [k][m]
    __shared__ float Bs[16][64];   // [k][n]
    int tid = threadIdx.x;
    int bm = blockIdx.x * 128, bn = blockIdx.y * 64;
    int tn = (tid & 7) << 3;
    int tm = (tid >> 3) << 3;
    int br = tid >> 3;
    int bcc = (tid & 7) << 3;

    u64 acc2[4][8];
#pragma unroll
    for (int i = 0; i < 4; i++)
#pragma unroll
        for (int j = 0; j < 8; j++) acc2[i][j] = 0ull;

    const float* Ap = g_fused + (size_t)(bm + tid) * FD;
    const float* Bp = W2 + (size_t)br * HD + bn + bcc;

    float4 ar[4]; float4 brg[2];
#pragma unroll
    for (int q = 0; q < 4; q++) ar[q] = *(const float4*)(Ap + q * 4);
    brg[0] = *(const float4*)(Bp);
    brg[1] = *(const float4*)(Bp + 4);

    for (int k0 = 0; k0 < FD; k0 += 16) {
        __syncthreads();
#pragma unroll
        for (int q = 0; q < 4; q++) {
            As[q * 4 + 0][tid] = ar[q].x; As[q * 4 + 1][tid] = ar[q].y;
            As[q * 4 + 2][tid] = ar[q].z; As[q * 4 + 3][tid] = ar[q].w;
        }
        *(float4*)&Bs[br][bcc] = brg[0];
        *(float4*)&Bs[br][bcc + 4] = brg[1];
        __syncthreads();
        if (k0 + 16 < FD) {
#pragma unroll
            for (int q = 0; q < 4; q++) ar[q] = *(const float4*)(Ap + k0 + 16 + q * 4);
            brg[0] = *(const float4*)(Bp + (size_t)(k0 + 16) * HD);
            brg[1] = *(const float4*)(Bp + (size_t)(k0 + 16) * HD + 4);
        }
#pragma unroll
        for (int kk = 0; kk < 16; kk++) {
            ulonglong2 av0 = *(const ulonglong2*)&As[kk][tm];
            ulonglong2 av1 = *(const ulonglong2*)&As[kk][tm + 4];
            float4 b0 = *(const float4*)&Bs[kk][tn];
            float4 b1v = *(const float4*)&Bs[kk][tn + 4];
            u64 aa[4] = {av0.x, av0.y, av1.x, av1.y};
            u64 bb[8];
            bb[0] = rep2(b0.x); bb[1] = rep2(b0.y); bb[2] = rep2(b0.z); bb[3] = rep2(b0.w);
            bb[4] = rep2(b1v.x); bb[5] = rep2(b1v.y); bb[6] = rep2(b1v.z); bb[7] = rep2(b1v.w);
#pragma unroll
            for (int m2 = 0; m2 < 4; m2++)
#pragma unroll
                for (int j = 0; j < 8; j++) fma2(acc2[m2][j], aa[m2], bb[j]);
        }
    }

#pragma unroll
    for (int m2 = 0; m2 < 4; m2++) {
        float r0[8], r1[8];
#pragma unroll
        for (int j = 0; j < 8; j++) {
            float lo, hi;
            unpack2(acc2[m2][j], lo, hi);
            float bias = b2[bn + tn + j];
            r0[j] = gelu_exact(lo + bias);
            r1[j] = gelu_exact(hi + bias);
        }
        int row0 = bm + tm + 2 * m2;
        float* p0 = g_hidden + (size_t)row0 * HD + bn + tn;
        float* p1 = p0 + HD;
        *(float4*)p0 = make_float4(r0[0], r0[1], r0[2], r0[3]);
        *(float4*)(p0 + 4) = make_float4(r0[4], r0[5], r0[6], r0[7]);
        *(float4*)p1 = make_float4(r1[0], r1[1], r1[2], r1[3]);
        *(float4*)(p1 + 4) = make_float4(r1[4], r1[5], r1[6], r1[7]);
    }
}

// ---------------- GEMM2: [T,256] @ [256,128] + bias + 0.25*tanh + norms -----
__global__ void __launch_bounds__(256) k_gemm2(const float* __restrict__ W3,
                                               const float* __restrict__ b3,
                                               float* __restrict__ out) {
    __shared__ float hs[16 * 256];
    int tid = threadIdx.x;
    int t0 = blockIdx.x * 16;
    if (blockIdx.x == 0 && tid < 3)
        out[(size_t)T * H + tid] = g_norm3[tid] * (1.0f / (float)T);
    for (int i = tid; i < 16 * 256; i += 256)
        hs[i] = g_hidden[(size_t)t0 * 256 + i];
    __syncthreads();
    int n = tid & 127;
    int half = tid >> 7;
    const float* hp = hs + half * 8 * 256;
    u64 acc2[8];
#pragma unroll
    for (int r = 0; r < 8; r++) acc2[r] = 0ull;
    for (int k = 0; k < 256; k += 4) {
        float w0 = W3[(k + 0) * 128 + n];
        float w1 = W3[(k + 1) * 128 + n];
        float w2 = W3[(k + 2) * 128 + n];
        float w3v = W3[(k + 3) * 128 + n];
        u64 w01 = pack2(w0, w1);
        u64 w23 = pack2(w2, w3v);
#pragma unroll
        for (int r = 0; r < 8; r++) {
            ulonglong2 hv = *(const ulonglong2*)&hp[r * 256 + k];
            fma2(acc2[r], hv.x, w01);
            fma2(acc2[r], hv.y, w23);
        }
    }
    float bias = b3[n];
#pragma unroll
    for (int r = 0; r < 8; r++) {
        float lo, hi;
        unpack2(acc2[r], lo, hi);
        out[(size_t)(t0 + half * 8 + r) * 128 + n] = 0.25f * tanhf(lo + hi + bias);
    }
}

// ---------------- launcher --------------------------------------------------
extern "C" void kernel_launch(void* const* d_in, const int* in_sizes, int n_in,
                              void* d_out, int out_size) {
    const float* node_repr = (const float*)d_in[0];
    const float* edge_repr = (const float*)d_in[1];
    const int*   edge_src  = (const int*)d_in[2];
    const int*   edge_dst  = (const int*)d_in[3];
    const int*   rel_ids   = (const int*)d_in[4];
    const float* etime     = (const float*)d_in[5];
    const int*   tli       = (const int*)d_in[6];
    const int*   nsg       = (const int*)d_in[7];
    const int*   esg       = (const int*)d_in[8];
    const int*   hop       = (const int*)d_in[9];
    const float* W1 = (const float*)d_in[10];
    const float* b1 = (const float*)d_in[11];
    const float* W2 = (const float*)d_in[12];
    const float* b2 = (const float*)d_in[13];
    const float* W3 = (const float*)d_in[14];
    const float* b3 = (const float*)d_in[15];
    float* out = (float*)d_out;

    k_init<<<16, 256>>>();
    k_scatter<<<EBLK + NBLK, 256>>>(edge_dst, esg, tli, rel_ids, etime, edge_src, nsg, hop);
    k_main<<<T, 128>>>(node_repr, edge_repr, W1, b1);
    k_gemm1<<<dim3(32, 4), 128>>>(W2, b2);
    k_gemm2<<<T / 16, 256>>>(W3, b3, out);
}

// round 6
// speedup vs baseline: 1.8322x; 1.0686x over previous
#include <cuda_runtime.h>
#include <cuda_bf16.h>
#include <cstdint>

#define H 128
#define E 1048576
#define NV 262144
#define T 4096
#define NET 8
#define FD 1056   // 8*H + 32
#define HD 256    // 2*H
#define KS 132    // FD / 8 k-steps
#define ECAP 256
#define NCAP 256

// ---------------- scratch ---------------------------------------------------
__device__ int g_ecnt[T];
__device__ int g_ncnt[T];
__device__ float4   g_emeta[(size_t)T * ECAP];
__device__ unsigned g_nlist[(size_t)T * NCAP];
__device__ float g_Af[(size_t)(T / 16) * KS * 128];   // A fragments (tf32)
__device__ float g_Bf[(size_t)KS * 32 * 64];          // B fragments (tf32)
__device__ float g_hidden[(size_t)T * HD];
__device__ float g_norm3[3];

typedef unsigned long long u64;

__device__ __forceinline__ float gelu_exact(float x) {
    return 0.5f * x * (1.0f + erff(x * 0.7071067811865476f));
}
__device__ __forceinline__ u64 pack2(float lo, float hi) {
    u64 r; asm("mov.b64 %0, {%1, %2};" : "=l"(r) : "f"(lo), "f"(hi)); return r;
}
__device__ __forceinline__ void fma2(u64& acc, u64 a, u64 b) {
    asm("fma.rn.f32x2 %0, %1, %2, %0;" : "+l"(acc) : "l"(a), "l"(b));
}
__device__ __forceinline__ void unpack2(u64 v, float& lo, float& hi) {
    asm("mov.b64 {%0, %1}, %2;" : "=f"(lo), "=f"(hi) : "l"(v));
}
__device__ __forceinline__ float to_tf32(float x) {
    uint32_t u; asm("cvt.rna.tf32.f32 %0, %1;" : "=r"(u) : "f"(x));
    return __uint_as_float(u);
}
// m16n8k8 tf32 mma: c += a * b
__device__ __forceinline__ void mma8(float* c, const float4& a, const float2& b) {
    asm("mma.sync.aligned.m16n8k8.row.col.f32.tf32.tf32.f32 "
        "{%0,%1,%2,%3}, {%4,%5,%6,%7}, {%8,%9}, {%0,%1,%2,%3};"
        : "+f"(c[0]), "+f"(c[1]), "+f"(c[2]), "+f"(c[3])
        : "r"(__float_as_uint(a.x)), "r"(__float_as_uint(a.y)),
          "r"(__float_as_uint(a.z)), "r"(__float_as_uint(a.w)),
          "r"(__float_as_uint(b.x)), "r"(__float_as_uint(b.y)));
}
// A-fragment address: global element (m, k) -> frag slot
__device__ __forceinline__ void storeA(int m, int k, float v) {
    int kstep = k >> 3, kc = k & 7, mr = m & 15;
    int th = ((mr & 7) << 2) | (kc & 3);
    int reg = (mr >> 3) | ((kc >> 2) << 1);
    g_Af[((size_t)(m >> 4) * KS + kstep) * 128 + th * 4 + reg] = to_tf32(v);
}

// ---------------- init ------------------------------------------------------
__global__ void k_init() {
    int i = blockIdx.x * blockDim.x + threadIdx.x;
    if (i < T) { g_ecnt[i] = 0; g_ncnt[i] = 0; }
    if (i < 3) g_norm3[i] = 0.0f;
}

// ---------------- W2 -> tf32 B-fragments ------------------------------------
__global__ void k_cvtB(const float* __restrict__ W2) {
    int i = blockIdx.x * blockDim.x + threadIdx.x;  // i = k*HD + n
    int k = i >> 8, n = i & 255;
    float v = to_tf32(W2[i]);
    int kstep = k >> 3, kc = k & 7;
    int th = ((n & 7) << 2) | (kc & 3);
    int reg = kc >> 2;
    g_Bf[((size_t)kstep * 32 + (n >> 3)) * 64 + th * 2 + reg] = v;
}

// ---------------- scatter into fixed-capacity buckets -----------------------
#define EBLK (E / 4 / 256)
#define NBLK (NV / 4 / 256)
__global__ void k_scatter(const int* __restrict__ ed, const int* __restrict__ esg,
                          const int* __restrict__ tli, const int* __restrict__ rel,
                          const float* __restrict__ tm, const int* __restrict__ esrc,
                          const int* __restrict__ nsg, const int* __restrict__ hop) {
    int b = blockIdx.x;
    if (b < EBLK) {
        int i = b * 256 + threadIdx.x;
        int4 d4 = ((const int4*)ed)[i];
        int4 s4 = ((const int4*)esg)[i];
        int4 r4 = ((const int4*)rel)[i];
        float4 t4 = ((const float4*)tm)[i];
        int4 sr4 = ((const int4*)esrc)[i];
        int dd[4] = {d4.x, d4.y, d4.z, d4.w};
        int ss[4] = {s4.x, s4.y, s4.z, s4.w};
        int rr[4] = {r4.x, r4.y, r4.z, r4.w};
        float tt[4] = {t4.x, t4.y, t4.z, t4.w};
        int sc[4] = {sr4.x, sr4.y, sr4.z, sr4.w};
#pragma unroll
        for (int q = 0; q < 4; q++) {
            if (dd[q] == __ldg(&tli[ss[q]])) {
                int pos = atomicAdd(&g_ecnt[ss[q]], 1);
                float t = tt[q];
                unsigned pk = (unsigned)(i * 4 + q) | ((rr[q] < NET) ? 0x80000000u : 0u);
                float4 mt;
                mt.x = __uint_as_float(pk);
                mt.y = __int_as_float(sc[q]);
                mt.z = expf(-t);
                mt.w = expf(-t * (1.0f / 24.0f));
                g_emeta[(size_t)ss[q] * ECAP + pos] = mt;
            }
        }
    } else {
        int i = (b - EBLK) * 256 + threadIdx.x;
        int4 n4 = ((const int4*)nsg)[i];
        int4 h4 = ((const int4*)hop)[i];
        int nn[4] = {n4.x, n4.y, n4.z, n4.w};
        int hh[4] = {h4.x, h4.y, h4.z, h4.w};
#pragma unroll
        for (int q = 0; q < 4; q++) {
            int pos = atomicAdd(&g_ncnt[nn[q]], 1);
            g_nlist[(size_t)nn[q] * NCAP + pos] =
                (unsigned)(i * 4 + q) | ((hh[q] == 1) ? 0x80000000u : 0u);
        }
    }
}

// ---------------- block reduce helpers (128 threads) ------------------------
__device__ __forceinline__ float blk_sum(float v, float* sb) {
#pragma unroll
    for (int o = 16; o > 0; o >>= 1) v += __shfl_xor_sync(0xffffffffu, v, o);
    __syncthreads();
    if ((threadIdx.x & 31) == 0) sb[threadIdx.x >> 5] = v;
    __syncthreads();
    return sb[0] + sb[1] + sb[2] + sb[3];
}
__device__ __forceinline__ float blk_ln(float x, float* sb) {
    float m = blk_sum(x, sb) * (1.0f / 128.0f);
    float d = x - m;
    float v = blk_sum(d * d, sb) * (1.0f / 128.0f);
    return d * rsqrtf(v + 1e-5f);
}

// ---------------- per-target aggregation + feature build --------------------
__global__ void __launch_bounds__(128) k_main(const float* __restrict__ node_repr,
                                              const float* __restrict__ edge_repr,
                                              const float* __restrict__ W1,
                                              const float* __restrict__ b1) {
    __shared__ float cmb[4][8][128];
    __shared__ float scmb[4][11];
    __shared__ float sb[4];
    int t = blockIdx.x;
    int tid = threadIdx.x;
    int wid = tid >> 5, lane = tid & 31;
    int c4 = lane << 2;

    float4 v_is = {0,0,0,0}, v_os = {0,0,0,0}, v_il = {0,0,0,0}, v_ol = {0,0,0,0};
    float4 v_hs = {0,0,0,0}, v_hl = {0,0,0,0};
    float d_is = 0, d_os = 0, d_il = 0, d_ol = 0, smw = 0, lmw = 0, tsum = 0, cin = 0, cout = 0;

    int ecount = g_ecnt[t];
    const float4* ebase = g_emeta + (size_t)t * ECAP;
#pragma unroll 4
    for (int i = wid; i < ecount; i += 4) {
        float4 mt = ebase[i];
        unsigned pk = __float_as_uint(mt.x);
        int eidx = pk & 0x7fffffff;
        int src = __float_as_int(mt.y);
        float sw = mt.z, lw = mt.w;
        float4 er = *(const float4*)(edge_repr + (size_t)eidx * H + c4);
        float4 sr = *(const float4*)(node_repr + (size_t)src * H + c4);
        if (pk & 0x80000000u) {
            v_is.x += sw * er.x; v_is.y += sw * er.y; v_is.z += sw * er.z; v_is.w += sw * er.w;
            v_il.x += lw * er.x; v_il.y += lw * er.y; v_il.z += lw * er.z; v_il.w += lw * er.w;
            d_is += sw; d_il += lw; cin += 1.0f;
        } else {
            v_os.x += sw * er.x; v_os.y += sw * er.y; v_os.z += sw * er.z; v_os.w += sw * er.w;
            v_ol.x += lw * er.x; v_ol.y += lw * er.y; v_ol.z += lw * er.z; v_ol.w += lw * er.w;
            d_os += sw; d_ol += lw; cout += 1.0f;
        }
        v_hs.x += sw * sr.x; v_hs.y += sw * sr.y; v_hs.z += sw * sr.z; v_hs.w += sw * sr.w;
        v_hl.x += lw * sr.x; v_hl.y += lw * sr.y; v_hl.z += lw * sr.z; v_hl.w += lw * sr.w;
        smw += sw; lmw += lw; tsum += -__logf(sw);
    }

    float4 v_h1 = {0,0,0,0}, v_h2 = {0,0,0,0};
    float c1 = 0, c2 = 0;
    int ncount = g_ncnt[t];
    const unsigned* nbase = g_nlist + (size_t)t * NCAP;
#pragma unroll 4
    for (int i = wid; i < ncount; i += 4) {
        unsigned pk = nbase[i];
        float4 nr = *(const float4*)(node_repr + (size_t)(pk & 0x7fffffff) * H + c4);
        if (pk & 0x80000000u) {
            v_h1.x += nr.x; v_h1.y += nr.y; v_h1.z += nr.z; v_h1.w += nr.w; c1 += 1.0f;
        } else {
            v_h2.x += nr.x; v_h2.y += nr.y; v_h2.z += nr.z; v_h2.w += nr.w; c2 += 1.0f;
        }
    }

    *(float4*)&cmb[wid][0][c4] = v_is;
    *(float4*)&cmb[wid][1][c4] = v_os;
    *(float4*)&cmb[wid][2][c4] = v_il;
    *(float4*)&cmb[wid][3][c4] = v_ol;
    *(float4*)&cmb[wid][4][c4] = v_hs;
    *(float4*)&cmb[wid][5][c4] = v_hl;
    *(float4*)&cmb[wid][6][c4] = v_h1;
    *(float4*)&cmb[wid][7][c4] = v_h2;
    if (lane == 0) {
        scmb[wid][0] = d_is; scmb[wid][1] = d_os; scmb[wid][2] = d_il; scmb[wid][3] = d_ol;
        scmb[wid][4] = smw;  scmb[wid][5] = lmw;  scmb[wid][6] = tsum; scmb[wid][7] = cin;
        scmb[wid][8] = cout; scmb[wid][9] = c1;   scmb[wid][10] = c2;
    }
    __syncthreads();

    int h = tid;
    float a_is = cmb[0][0][h] + cmb[1][0][h] + cmb[2][0][h] + cmb[3][0][h];
    float a_os = cmb[0][1][h] + cmb[1][1][h] + cmb[2][1][h] + cmb[3][1][h];
    float a_il = cmb[0][2][h] + cmb[1][2][h] + cmb[2][2][h] + cmb[3][2][h];
    float a_ol = cmb[0][3][h] + cmb[1][3][h] + cmb[2][3][h] + cmb[3][3][h];
    float a_hs = cmb[0][4][h] + cmb[1][4][h] + cmb[2][4][h] + cmb[3][4][h];
    float a_hl = cmb[0][5][h] + cmb[1][5][h] + cmb[2][5][h] + cmb[3][5][h];
    float a_h1 = cmb[0][6][h] + cmb[1][6][h] + cmb[2][6][h] + cmb[3][6][h];
    float a_h2 = cmb[0][7][h] + cmb[1][7][h] + cmb[2][7][h] + cmb[3][7][h];
    d_is = scmb[0][0] + scmb[1][0] + scmb[2][0] + scmb[3][0];
    d_os = scmb[0][1] + scmb[1][1] + scmb[2][1] + scmb[3][1];
    d_il = scmb[0][2] + scmb[1][2] + scmb[2][2] + scmb[3][2];
    d_ol = scmb[0][3] + scmb[1][3] + scmb[2][3] + scmb[3][3];
    smw  = scmb[0][4] + scmb[1][4] + scmb[2][4] + scmb[3][4];
    lmw  = scmb[0][5] + scmb[1][5] + scmb[2][5] + scmb[3][5];
    tsum = scmb[0][6] + scmb[1][6] + scmb[2][6] + scmb[3][6];
    cin  = scmb[0][7] + scmb[1][7] + scmb[2][7] + scmb[3][7];
    cout = scmb[0][8] + scmb[1][8] + scmb[2][8] + scmb[3][8];
    c1   = scmb[0][9] + scmb[1][9] + scmb[2][9] + scmb[3][9];
    c2   = scmb[0][10] + scmb[1][10] + scmb[2][10] + scmb[3][10];

    float in_s  = a_is / fmaxf(d_is, 1e-6f);
    float out_s = a_os / fmaxf(d_os, 1e-6f);
    float in_l  = a_il / fmaxf(d_il, 1e-6f);
    float out_l = a_ol / fmaxf(d_ol, 1e-6f);
    float h1es  = a_hs / fmaxf(smw, 1e-6f);
    float h1el  = a_hl / fmaxf(lmw, 1e-6f);
    float h1m   = a_h1 / fmaxf(c1, 1e-6f);
    float h2m   = a_h2 / fmaxf(c2, 1e-6f);

    float burst = blk_ln(in_s + out_s - in_l - out_l, sb);
    float dirg  = blk_ln(out_l - in_l, sb);
    float hopg  = blk_ln(h1m - h2m, sb);
    float slg   = blk_ln(h1es - h1el, sb);
    float asym  = blk_ln(fabsf(dirg), sb);
    float h1n   = blk_ln(h1m, sb);
    float h2n   = blk_ln(h2m, sb);
    float rb    = blk_ln(in_l + out_l, sb);

    float ssh = blk_sum(hopg * hopg, sb);
    float sss = blk_sum(slg * slg, sb);
    float ssd = blk_sum(dirg * dirg, sb);
    if (h == 0) {
        atomicAdd(&g_norm3[0], sqrtf(ssh));
        atomicAdd(&g_norm3[1], sqrtf(sss));
        atomicAdd(&g_norm3[2], sqrtf(ssd));
    }

    // write fused features directly as tf32 A-fragments
    storeA(t, 0 * H + h, burst);
    storeA(t, 1 * H + h, dirg);
    storeA(t, 2 * H + h, hopg);
    storeA(t, 3 * H + h, slg);
    storeA(t, 4 * H + h, asym);
    storeA(t, 5 * H + h, h1n);
    storeA(t, 6 * H + h, h2n);
    storeA(t, 7 * H + h, rb);

    if (h < 32) {
        float s0 = log1pf(cin), s1 = log1pf(cout), s2 = log1pf(c1), s3 = log1pf(c2);
        float cnt = cin + cout;
        float s4 = tsum / fmaxf(cnt, 1e-6f);
        float s5 = smw, s6 = lmw, s7 = smw - lmw;
        float acc = b1[h];
        acc += s0 * W1[0 * 32 + h] + s1 * W1[1 * 32 + h] + s2 * W1[2 * 32 + h] + s3 * W1[3 * 32 + h]
             + s4 * W1[4 * 32 + h] + s5 * W1[5 * 32 + h] + s6 * W1[6 * 32 + h] + s7 * W1[7 * 32 + h];
        storeA(t, 8 * H + h, gelu_exact(acc));
    }
}

// ---------------- GEMM1: tf32 mma.sync, [T,1056]@[1056,256] + bias + GELU ---
// 256 threads = 8 warps (4 m-warps x 2 n-warps); warp tile 32x32.
// BM=128 BN=64, grid (32, 4) = 128 blocks. Fragments straight from L2/L1.
__global__ void __launch_bounds__(256) k_gemm1(const float* __restrict__ b2) {
    int tid = threadIdx.x, lane = tid & 31, warp = tid >> 5;
    int wm = warp & 3, wn = warp >> 2;
    int bm = blockIdx.x * 128, bn = blockIdx.y * 64;
    int mt0 = (bm >> 4) + wm * 2;     // first of 2 m16 tiles
    int nt0 = (bn >> 3) + wn * 4;     // first of 4 n8 tiles

    float c[2][4][4];
#pragma unroll
    for (int i = 0; i < 2; i++)
#pragma unroll
        for (int j = 0; j < 4; j++)
#pragma unroll
            for (int r = 0; r < 4; r++) c[i][j][r] = 0.0f;

    const float4* A0 = (const float4*)(g_Af + (size_t)mt0 * KS * 128) + lane;
    const float4* A1 = (const float4*)(g_Af + (size_t)(mt0 + 1) * KS * 128) + lane;
    const float2* B0 = (const float2*)(g_Bf + (size_t)nt0 * 64) + lane;

#pragma unroll 2
    for (int ks = 0; ks < KS; ks++) {
        float4 a0 = A0[ks * 32];
        float4 a1 = A1[ks * 32];
        float2 bf[4];
#pragma unroll
        for (int j = 0; j < 4; j++) bf[j] = B0[((size_t)ks * 32 + j) * 32];
#pragma unroll
        for (int j = 0; j < 4; j++) {
            mma8(c[0][j], a0, bf[j]);
            mma8(c[1][j], a1, bf[j]);
        }
    }

    // epilogue: bias + gelu, write g_hidden row-major
#pragma unroll
    for (int i = 0; i < 2; i++) {
        int r0 = bm + wm * 32 + i * 16 + (lane >> 2);
#pragma unroll
        for (int j = 0; j < 4; j++) {
            int cc = bn + wn * 32 + j * 8 + (lane & 3) * 2;
            float bx = b2[cc], by = b2[cc + 1];
            float2 lo, hi;
            lo.x = gelu_exact(c[i][j][0] + bx);
            lo.y = gelu_exact(c[i][j][1] + by);
            hi.x = gelu_exact(c[i][j][2] + bx);
            hi.y = gelu_exact(c[i][j][3] + by);
            *(float2*)(g_hidden + (size_t)r0 * HD + cc) = lo;
            *(float2*)(g_hidden + (size_t)(r0 + 8) * HD + cc) = hi;
        }
    }
}

// ---------------- GEMM2: [T,256] @ [256,128] + bias + 0.25*tanh + norms -----
__global__ void __launch_bounds__(256) k_gemm2(const float* __restrict__ W3,
                                               const float* __restrict__ b3,
                                               float* __restrict__ out) {
    __shared__ float hs[16 * 256];
    int tid = threadIdx.x;
    int t0 = blockIdx.x * 16;
    if (blockIdx.x == 0 && tid < 3)
        out[(size_t)T * H + tid] = g_norm3[tid] * (1.0f / (float)T);
    for (int i = tid; i < 16 * 256; i += 256)
        hs[i] = g_hidden[(size_t)t0 * 256 + i];
    __syncthreads();
    int n = tid & 127;
    int half = tid >> 7;
    const float* hp = hs + half * 8 * 256;
    u64 acc2[8];
#pragma unroll
    for (int r = 0; r < 8; r++) acc2[r] = 0ull;
    for (int k = 0; k < 256; k += 4) {
        float w0 = W3[(k + 0) * 128 + n];
        float w1 = W3[(k + 1) * 128 + n];
        float w2 = W3[(k + 2) * 128 + n];
        float w3v = W3[(k + 3) * 128 + n];
        u64 w01 = pack2(w0, w1);
        u64 w23 = pack2(w2, w3v);
#pragma unroll
        for (int r = 0; r < 8; r++) {
            ulonglong2 hv = *(const ulonglong2*)&hp[r * 256 + k];
            fma2(acc2[r], hv.x, w01);
            fma2(acc2[r], hv.y, w23);
        }
    }
    float bias = b3[n];
#pragma unroll
    for (int r = 0; r < 8; r++) {
        float lo, hi;
        unpack2(acc2[r], lo, hi);
        out[(size_t)(t0 + half * 8 + r) * 128 + n] = 0.25f * tanhf(lo + hi + bias);
    }
}

// ---------------- launcher --------------------------------------------------
extern "C" void kernel_launch(void* const* d_in, const int* in_sizes, int n_in,
                              void* d_out, int out_size) {
    const float* node_repr = (const float*)d_in[0];
    const float* edge_repr = (const float*)d_in[1];
    const int*   edge_src  = (const int*)d_in[2];
    const int*   edge_dst  = (const int*)d_in[3];
    const int*   rel_ids   = (const int*)d_in[4];
    const float* etime     = (const float*)d_in[5];
    const int*   tli       = (const int*)d_in[6];
    const int*   nsg       = (const int*)d_in[7];
    const int*   esg       = (const int*)d_in[8];
    const int*   hop       = (const int*)d_in[9];
    const float* W1 = (const float*)d_in[10];
    const float* b1 = (const float*)d_in[11];
    const float* W2 = (const float*)d_in[12];
    const float* b2 = (const float*)d_in[13];
    const float* W3 = (const float*)d_in[14];
    const float* b3 = (const float*)d_in[15];
    float* out = (float*)d_out;

    k_init<<<16, 256>>>();
    k_cvtB<<<FD * HD / 256, 256>>>(W2);
    k_scatter<<<EBLK + NBLK, 256>>>(edge_dst, esg, tli, rel_ids, etime, edge_src, nsg, hop);
    k_main<<<T, 128>>>(node_repr, edge_repr, W1, b1);
    k_gemm1<<<dim3(32, 4), 256>>>(b2);
    k_gemm2<<<T / 16, 256>>>(W3, b3, out);
}

// round 7
// speedup vs baseline: 1.8466x; 1.0079x over previous
#include <cuda_runtime.h>
#include <cuda_bf16.h>
#include <cstdint>

#define H 128
#define E 1048576
#define NV 262144
#define T 4096
#define NET 8
#define FD 1056   // 8*H + 32
#define HD 256    // 2*H
#define KS 132    // FD / 8 k-steps
#define ECAP 256
#define NCAP 256

// ---------------- scratch ---------------------------------------------------
__device__ int g_ecnt[T];
__device__ int g_ncnt[T];
__device__ float4   g_emeta[(size_t)T * ECAP];
__device__ unsigned g_nlist[(size_t)T * NCAP];
__device__ float g_Af[(size_t)(T / 16) * KS * 128];   // A fragments (tf32)
__device__ float g_Bf[(size_t)KS * 32 * 64];          // B fragments (tf32)
__device__ float g_escal[(size_t)T * 8];              // raw edge scalars
__device__ float g_hidden[(size_t)T * HD];
__device__ float g_norm3[3];

typedef unsigned long long u64;

__device__ __forceinline__ float gelu_exact(float x) {
    return 0.5f * x * (1.0f + erff(x * 0.7071067811865476f));
}
__device__ __forceinline__ u64 pack2(float lo, float hi) {
    u64 r; asm("mov.b64 %0, {%1, %2};" : "=l"(r) : "f"(lo), "f"(hi)); return r;
}
__device__ __forceinline__ void fma2(u64& acc, u64 a, u64 b) {
    asm("fma.rn.f32x2 %0, %1, %2, %0;" : "+l"(acc) : "l"(a), "l"(b));
}
__device__ __forceinline__ void unpack2(u64 v, float& lo, float& hi) {
    asm("mov.b64 {%0, %1}, %2;" : "=f"(lo), "=f"(hi) : "l"(v));
}
__device__ __forceinline__ float to_tf32(float x) {
    uint32_t u; asm("cvt.rna.tf32.f32 %0, %1;" : "=r"(u) : "f"(x));
    return __uint_as_float(u);
}
__device__ __forceinline__ void mma8(float* c, const float4& a, const float2& b) {
    asm("mma.sync.aligned.m16n8k8.row.col.f32.tf32.tf32.f32 "
        "{%0,%1,%2,%3}, {%4,%5,%6,%7}, {%8,%9}, {%0,%1,%2,%3};"
        : "+f"(c[0]), "+f"(c[1]), "+f"(c[2]), "+f"(c[3])
        : "r"(__float_as_uint(a.x)), "r"(__float_as_uint(a.y)),
          "r"(__float_as_uint(a.z)), "r"(__float_as_uint(a.w)),
          "r"(__float_as_uint(b.x)), "r"(__float_as_uint(b.y)));
}
__device__ __forceinline__ void storeA(int m, int k, float v) {
    int kstep = k >> 3, kc = k & 7, mr = m & 15;
    int th = ((mr & 7) << 2) | (kc & 3);
    int reg = (mr >> 3) | ((kc >> 2) << 1);
    g_Af[((size_t)(m >> 4) * KS + kstep) * 128 + th * 4 + reg] = to_tf32(v);
}

// ---------------- init ------------------------------------------------------
__global__ void k_init() {
    int i = blockIdx.x * blockDim.x + threadIdx.x;
    if (i < T) { g_ecnt[i] = 0; g_ncnt[i] = 0; }
    if (i < 3) g_norm3[i] = 0.0f;
}

// ---------------- W2 -> tf32 B-fragments ------------------------------------
__global__ void k_cvtB(const float* __restrict__ W2) {
    int i = blockIdx.x * blockDim.x + threadIdx.x;  // i = k*HD + n
    int k = i >> 8, n = i & 255;
    float v = to_tf32(W2[i]);
    int kstep = k >> 3, kc = k & 7;
    int th = ((n & 7) << 2) | (kc & 3);
    int reg = kc >> 2;
    g_Bf[((size_t)kstep * 32 + (n >> 3)) * 64 + th * 2 + reg] = v;
}

// ---------------- scatter into fixed-capacity buckets -----------------------
#define EBLK (E / 4 / 256)
#define NBLK (NV / 4 / 256)
__global__ void k_scatter(const int* __restrict__ ed, const int* __restrict__ esg,
                          const int* __restrict__ tli, const int* __restrict__ rel,
                          const float* __restrict__ tm, const int* __restrict__ esrc,
                          const int* __restrict__ nsg, const int* __restrict__ hop) {
    int b = blockIdx.x;
    if (b < EBLK) {
        int i = b * 256 + threadIdx.x;
        int4 d4 = ((const int4*)ed)[i];
        int4 s4 = ((const int4*)esg)[i];
        int4 r4 = ((const int4*)rel)[i];
        float4 t4 = ((const float4*)tm)[i];
        int4 sr4 = ((const int4*)esrc)[i];
        int dd[4] = {d4.x, d4.y, d4.z, d4.w};
        int ss[4] = {s4.x, s4.y, s4.z, s4.w};
        int rr[4] = {r4.x, r4.y, r4.z, r4.w};
        float tt[4] = {t4.x, t4.y, t4.z, t4.w};
        int sc[4] = {sr4.x, sr4.y, sr4.z, sr4.w};
#pragma unroll
        for (int q = 0; q < 4; q++) {
            if (dd[q] == __ldg(&tli[ss[q]])) {
                int pos = atomicAdd(&g_ecnt[ss[q]], 1);
                float t = tt[q];
                unsigned pk = (unsigned)(i * 4 + q) | ((rr[q] < NET) ? 0x80000000u : 0u);
                float4 mt;
                mt.x = __uint_as_float(pk);
                mt.y = __int_as_float(sc[q]);
                mt.z = expf(-t);
                mt.w = expf(-t * (1.0f / 24.0f));
                g_emeta[(size_t)ss[q] * ECAP + pos] = mt;
            }
        }
    } else {
        int i = (b - EBLK) * 256 + threadIdx.x;
        int4 n4 = ((const int4*)nsg)[i];
        int4 h4 = ((const int4*)hop)[i];
        int nn[4] = {n4.x, n4.y, n4.z, n4.w};
        int hh[4] = {h4.x, h4.y, h4.z, h4.w};
#pragma unroll
        for (int q = 0; q < 4; q++) {
            int pos = atomicAdd(&g_ncnt[nn[q]], 1);
            g_nlist[(size_t)nn[q] * NCAP + pos] =
                (unsigned)(i * 4 + q) | ((hh[q] == 1) ? 0x80000000u : 0u);
        }
    }
}

// ---------------- block reduce helpers (128 threads) ------------------------
__device__ __forceinline__ float blk_sum(float v, float* sb) {
#pragma unroll
    for (int o = 16; o > 0; o >>= 1) v += __shfl_xor_sync(0xffffffffu, v, o);
    __syncthreads();
    if ((threadIdx.x & 31) == 0) sb[threadIdx.x >> 5] = v;
    __syncthreads();
    return sb[0] + sb[1] + sb[2] + sb[3];
}
__device__ __forceinline__ float blk_ln(float x, float* sb) {
    float m = blk_sum(x, sb) * (1.0f / 128.0f);
    float d = x - m;
    float v = blk_sum(d * d, sb) * (1.0f / 128.0f);
    return d * rsqrtf(v + 1e-5f);
}

// ---------------- edge-side aggregation (features 0,1,3,4,7 + scalars) ------
__global__ void __launch_bounds__(128) k_edges(const float* __restrict__ node_repr,
                                               const float* __restrict__ edge_repr) {
    __shared__ float cmb[4][6][128];
    __shared__ float scmb[4][9];
    __shared__ float sb[4];
    int t = blockIdx.x;
    int tid = threadIdx.x;
    int wid = tid >> 5, lane = tid & 31;
    int c4 = lane << 2;

    float4 v_is = {0,0,0,0}, v_os = {0,0,0,0}, v_il = {0,0,0,0}, v_ol = {0,0,0,0};
    float4 v_hs = {0,0,0,0}, v_hl = {0,0,0,0};
    float d_is = 0, d_os = 0, d_il = 0, d_ol = 0, smw = 0, lmw = 0, tsum = 0, cin = 0, cout = 0;

    int ecount = g_ecnt[t];
    const float4* ebase = g_emeta + (size_t)t * ECAP;
#pragma unroll 4
    for (int i = wid; i < ecount; i += 4) {
        float4 mt = ebase[i];
        unsigned pk = __float_as_uint(mt.x);
        int eidx = pk & 0x7fffffff;
        int src = __float_as_int(mt.y);
        float sw = mt.z, lw = mt.w;
        float4 er = *(const float4*)(edge_repr + (size_t)eidx * H + c4);
        float4 sr = *(const float4*)(node_repr + (size_t)src * H + c4);
        if (pk & 0x80000000u) {
            v_is.x += sw * er.x; v_is.y += sw * er.y; v_is.z += sw * er.z; v_is.w += sw * er.w;
            v_il.x += lw * er.x; v_il.y += lw * er.y; v_il.z += lw * er.z; v_il.w += lw * er.w;
            d_is += sw; d_il += lw; cin += 1.0f;
        } else {
            v_os.x += sw * er.x; v_os.y += sw * er.y; v_os.z += sw * er.z; v_os.w += sw * er.w;
            v_ol.x += lw * er.x; v_ol.y += lw * er.y; v_ol.z += lw * er.z; v_ol.w += lw * er.w;
            d_os += sw; d_ol += lw; cout += 1.0f;
        }
        v_hs.x += sw * sr.x; v_hs.y += sw * sr.y; v_hs.z += sw * sr.z; v_hs.w += sw * sr.w;
        v_hl.x += lw * sr.x; v_hl.y += lw * sr.y; v_hl.z += lw * sr.z; v_hl.w += lw * sr.w;
        smw += sw; lmw += lw; tsum += -__logf(sw);
    }

    *(float4*)&cmb[wid][0][c4] = v_is;
    *(float4*)&cmb[wid][1][c4] = v_os;
    *(float4*)&cmb[wid][2][c4] = v_il;
    *(float4*)&cmb[wid][3][c4] = v_ol;
    *(float4*)&cmb[wid][4][c4] = v_hs;
    *(float4*)&cmb[wid][5][c4] = v_hl;
    if (lane == 0) {
        scmb[wid][0] = d_is; scmb[wid][1] = d_os; scmb[wid][2] = d_il; scmb[wid][3] = d_ol;
        scmb[wid][4] = smw;  scmb[wid][5] = lmw;  scmb[wid][6] = tsum; scmb[wid][7] = cin;
        scmb[wid][8] = cout;
    }
    __syncthreads();

    int h = tid;
    float a_is = cmb[0][0][h] + cmb[1][0][h] + cmb[2][0][h] + cmb[3][0][h];
    float a_os = cmb[0][1][h] + cmb[1][1][h] + cmb[2][1][h] + cmb[3][1][h];
    float a_il = cmb[0][2][h] + cmb[1][2][h] + cmb[2][2][h] + cmb[3][2][h];
    float a_ol = cmb[0][3][h] + cmb[1][3][h] + cmb[2][3][h] + cmb[3][3][h];
    float a_hs = cmb[0][4][h] + cmb[1][4][h] + cmb[2][4][h] + cmb[3][4][h];
    float a_hl = cmb[0][5][h] + cmb[1][5][h] + cmb[2][5][h] + cmb[3][5][h];
    d_is = scmb[0][0] + scmb[1][0] + scmb[2][0] + scmb[3][0];
    d_os = scmb[0][1] + scmb[1][1] + scmb[2][1] + scmb[3][1];
    d_il = scmb[0][2] + scmb[1][2] + scmb[2][2] + scmb[3][2];
    d_ol = scmb[0][3] + scmb[1][3] + scmb[2][3] + scmb[3][3];
    smw  = scmb[0][4] + scmb[1][4] + scmb[2][4] + scmb[3][4];
    lmw  = scmb[0][5] + scmb[1][5] + scmb[2][5] + scmb[3][5];
    tsum = scmb[0][6] + scmb[1][6] + scmb[2][6] + scmb[3][6];
    cin  = scmb[0][7] + scmb[1][7] + scmb[2][7] + scmb[3][7];
    cout = scmb[0][8] + scmb[1][8] + scmb[2][8] + scmb[3][8];

    float in_s  = a_is / fmaxf(d_is, 1e-6f);
    float out_s = a_os / fmaxf(d_os, 1e-6f);
    float in_l  = a_il / fmaxf(d_il, 1e-6f);
    float out_l = a_ol / fmaxf(d_ol, 1e-6f);
    float h1es  = a_hs / fmaxf(smw, 1e-6f);
    float h1el  = a_hl / fmaxf(lmw, 1e-6f);

    float burst = blk_ln(in_s + out_s - in_l - out_l, sb);
    float dirg  = blk_ln(out_l - in_l, sb);
    float slg   = blk_ln(h1es - h1el, sb);
    float asym  = blk_ln(fabsf(dirg), sb);
    float rb    = blk_ln(in_l + out_l, sb);

    float sss = blk_sum(slg * slg, sb);
    float ssd = blk_sum(dirg * dirg, sb);
    if (h == 0) {
        atomicAdd(&g_norm3[1], sqrtf(sss));
        atomicAdd(&g_norm3[2], sqrtf(ssd));
        float* es = g_escal + (size_t)t * 8;
        es[0] = cin; es[1] = cout; es[2] = tsum; es[3] = smw; es[4] = lmw;
    }

    storeA(t, 0 * H + h, burst);
    storeA(t, 1 * H + h, dirg);
    storeA(t, 3 * H + h, slg);
    storeA(t, 4 * H + h, asym);
    storeA(t, 7 * H + h, rb);
}

// ---------------- node-side aggregation (features 2,5,6,8) ------------------
__global__ void __launch_bounds__(128) k_nodes(const float* __restrict__ node_repr,
                                               const float* __restrict__ W1,
                                               const float* __restrict__ b1) {
    __shared__ float cmb[4][2][128];
    __shared__ float scmb[4][2];
    __shared__ float sb[4];
    int t = blockIdx.x;
    int tid = threadIdx.x;
    int wid = tid >> 5, lane = tid & 31;
    int c4 = lane << 2;

    float4 v_h1 = {0,0,0,0}, v_h2 = {0,0,0,0};
    float c1 = 0, c2 = 0;
    int ncount = g_ncnt[t];
    const unsigned* nbase = g_nlist + (size_t)t * NCAP;
#pragma unroll 4
    for (int i = wid; i < ncount; i += 4) {
        unsigned pk = nbase[i];
        float4 nr = *(const float4*)(node_repr + (size_t)(pk & 0x7fffffff) * H + c4);
        if (pk & 0x80000000u) {
            v_h1.x += nr.x; v_h1.y += nr.y; v_h1.z += nr.z; v_h1.w += nr.w; c1 += 1.0f;
        } else {
            v_h2.x += nr.x; v_h2.y += nr.y; v_h2.z += nr.z; v_h2.w += nr.w; c2 += 1.0f;
        }
    }

    *(float4*)&cmb[wid][0][c4] = v_h1;
    *(float4*)&cmb[wid][1][c4] = v_h2;
    if (lane == 0) { scmb[wid][0] = c1; scmb[wid][1] = c2; }
    __syncthreads();

    int h = tid;
    float a_h1 = cmb[0][0][h] + cmb[1][0][h] + cmb[2][0][h] + cmb[3][0][h];
    float a_h2 = cmb[0][1][h] + cmb[1][1][h] + cmb[2][1][h] + cmb[3][1][h];
    c1 = scmb[0][0] + scmb[1][0] + scmb[2][0] + scmb[3][0];
    c2 = scmb[0][1] + scmb[1][1] + scmb[2][1] + scmb[3][1];

    float h1m = a_h1 / fmaxf(c1, 1e-6f);
    float h2m = a_h2 / fmaxf(c2, 1e-6f);

    float hopg = blk_ln(h1m - h2m, sb);
    float h1n  = blk_ln(h1m, sb);
    float h2n  = blk_ln(h2m, sb);

    float ssh = blk_sum(hopg * hopg, sb);
    if (h == 0) atomicAdd(&g_norm3[0], sqrtf(ssh));

    storeA(t, 2 * H + h, hopg);
    storeA(t, 5 * H + h, h1n);
    storeA(t, 6 * H + h, h2n);

    if (h < 32) {
        const float* es = g_escal + (size_t)t * 8;
        float cin = es[0], cout = es[1], tsum = es[2], smw = es[3], lmw = es[4];
        float s0 = log1pf(cin), s1 = log1pf(cout), s2 = log1pf(c1), s3 = log1pf(c2);
        float cnt = cin + cout;
        float s4 = tsum / fmaxf(cnt, 1e-6f);
        float s5 = smw, s6 = lmw, s7 = smw - lmw;
        float acc = b1[h];
        acc += s0 * W1[0 * 32 + h] + s1 * W1[1 * 32 + h] + s2 * W1[2 * 32 + h] + s3 * W1[3 * 32 + h]
             + s4 * W1[4 * 32 + h] + s5 * W1[5 * 32 + h] + s6 * W1[6 * 32 + h] + s7 * W1[7 * 32 + h];
        storeA(t, 8 * H + h, gelu_exact(acc));
    }
}

// ---------------- GEMM1: tf32 mma.sync, [T,1056]@[1056,256] + bias + GELU ---
__global__ void __launch_bounds__(256) k_gemm1(const float* __restrict__ b2) {
    int tid = threadIdx.x, lane = tid & 31, warp = tid >> 5;
    int wm = warp & 3, wn = warp >> 2;
    int bm = blockIdx.x * 128, bn = blockIdx.y * 64;
    int mt0 = (bm >> 4) + wm * 2;
    int nt0 = (bn >> 3) + wn * 4;

    float c[2][4][4];
#pragma unroll
    for (int i = 0; i < 2; i++)
#pragma unroll
        for (int j = 0; j < 4; j++)
#pragma unroll
            for (int r = 0; r < 4; r++) c[i][j][r] = 0.0f;

    const float4* A0 = (const float4*)(g_Af + (size_t)mt0 * KS * 128) + lane;
    const float4* A1 = (const float4*)(g_Af + (size_t)(mt0 + 1) * KS * 128) + lane;
    const float2* B0 = (const float2*)(g_Bf + (size_t)nt0 * 64) + lane;

#pragma unroll 2
    for (int ks = 0; ks < KS; ks++) {
        float4 a0 = A0[ks * 32];
        float4 a1 = A1[ks * 32];
        float2 bf[4];
#pragma unroll
        for (int j = 0; j < 4; j++) bf[j] = B0[((size_t)ks * 32 + j) * 32];
#pragma unroll
        for (int j = 0; j < 4; j++) {
            mma8(c[0][j], a0, bf[j]);
            mma8(c[1][j], a1, bf[j]);
        }
    }

#pragma unroll
    for (int i = 0; i < 2; i++) {
        int r0 = bm + wm * 32 + i * 16 + (lane >> 2);
#pragma unroll
        for (int j = 0; j < 4; j++) {
            int cc = bn + wn * 32 + j * 8 + (lane & 3) * 2;
            float bx = b2[cc], by = b2[cc + 1];
            float2 lo, hi;
            lo.x = gelu_exact(c[i][j][0] + bx);
            lo.y = gelu_exact(c[i][j][1] + by);
            hi.x = gelu_exact(c[i][j][2] + bx);
            hi.y = gelu_exact(c[i][j][3] + by);
            *(float2*)(g_hidden + (size_t)r0 * HD + cc) = lo;
            *(float2*)(g_hidden + (size_t)(r0 + 8) * HD + cc) = hi;
        }
    }
}

// ---------------- GEMM2: [T,256] @ [256,128] + bias + 0.25*tanh + norms -----
__global__ void __launch_bounds__(256) k_gemm2(const float* __restrict__ W3,
                                               const float* __restrict__ b3,
                                               float* __restrict__ out) {
    __shared__ float hs[16 * 256];
    int tid = threadIdx.x;
    int t0 = blockIdx.x * 16;
    if (blockIdx.x == 0 && tid < 3)
        out[(size_t)T * H + tid] = g_norm3[tid] * (1.0f / (float)T);
    for (int i = tid; i < 16 * 256; i += 256)
        hs[i] = g_hidden[(size_t)t0 * 256 + i];
    __syncthreads();
    int n = tid & 127;
    int half = tid >> 7;
    const float* hp = hs + half * 8 * 256;
    u64 acc2[8];
#pragma unroll
    for (int r = 0; r < 8; r++) acc2[r] = 0ull;
    for (int k = 0; k < 256; k += 4) {
        float w0 = W3[(k + 0) * 128 + n];
        float w1 = W3[(k + 1) * 128 + n];
        float w2 = W3[(k + 2) * 128 + n];
        float w3v = W3[(k + 3) * 128 + n];
        u64 w01 = pack2(w0, w1);
        u64 w23 = pack2(w2, w3v);
#pragma unroll
        for (int r = 0; r < 8; r++) {
            ulonglong2 hv = *(const ulonglong2*)&hp[r * 256 + k];
            fma2(acc2[r], hv.x, w01);
            fma2(acc2[r], hv.y, w23);
        }
    }
    float bias = b3[n];
#pragma unroll
    for (int r = 0; r < 8; r++) {
        float lo, hi;
        unpack2(acc2[r], lo, hi);
        out[(size_t)(t0 + half * 8 + r) * 128 + n] = 0.25f * tanhf(lo + hi + bias);
    }
}

// ---------------- launcher --------------------------------------------------
extern "C" void kernel_launch(void* const* d_in, const int* in_sizes, int n_in,
                              void* d_out, int out_size) {
    const float* node_repr = (const float*)d_in[0];
    const float* edge_repr = (const float*)d_in[1];
    const int*   edge_src  = (const int*)d_in[2];
    const int*   edge_dst  = (const int*)d_in[3];
    const int*   rel_ids   = (const int*)d_in[4];
    const float* etime     = (const float*)d_in[5];
    const int*   tli       = (const int*)d_in[6];
    const int*   nsg       = (const int*)d_in[7];
    const int*   esg       = (const int*)d_in[8];
    const int*   hop       = (const int*)d_in[9];
    const float* W1 = (const float*)d_in[10];
    const float* b1 = (const float*)d_in[11];
    const float* W2 = (const float*)d_in[12];
    const float* b2 = (const float*)d_in[13];
    const float* W3 = (const float*)d_in[14];
    const float* b3 = (const float*)d_in[15];
    float* out = (float*)d_out;

    k_init<<<16, 256>>>();
    k_cvtB<<<FD * HD / 256, 256>>>(W2);
    k_scatter<<<EBLK + NBLK, 256>>>(edge_dst, esg, tli, rel_ids, etime, edge_src, nsg, hop);
    k_edges<<<T, 128>>>(node_repr, edge_repr);
    k_nodes<<<T, 128>>>(node_repr, W1, b1);
    k_gemm1<<<dim3(32, 4), 256>>>(b2);
    k_gemm2<<<T / 16, 256>>>(W3, b3, out);
}

// round 8
// speedup vs baseline: 1.8516x; 1.0027x over previous
#include <cuda_runtime.h>
#include <cuda_bf16.h>
#include <cstdint>

#define H 128
#define E 1048576
#define NV 262144
#define T 4096
#define NET 8
#define FD 1056   // 8*H + 32
#define HD 256    // 2*H
#define KS 132    // FD / 8 k-steps
#define ECAP 256
#define NCAP 256

// ---------------- scratch ---------------------------------------------------
__device__ int g_ecnt[T];
__device__ int g_ncnt[T];
__device__ int g_icnt[T];   // inbound target-edge count
__device__ int g_hcnt[T];   // hop1 node count
__device__ float4   g_emeta[(size_t)T * ECAP];
__device__ unsigned g_nlist[(size_t)T * NCAP];
__device__ float g_Af[(size_t)(T / 16) * KS * 128];   // A fragments (tf32)
__device__ float g_Bf[(size_t)KS * 32 * 64];          // B fragments (tf32)
__device__ float g_hidden[(size_t)T * HD];
__device__ float g_norm3[3];

typedef unsigned long long u64;

__device__ __forceinline__ float gelu_exact(float x) {
    return 0.5f * x * (1.0f + erff(x * 0.7071067811865476f));
}
__device__ __forceinline__ u64 pack2(float lo, float hi) {
    u64 r; asm("mov.b64 %0, {%1, %2};" : "=l"(r) : "f"(lo), "f"(hi)); return r;
}
__device__ __forceinline__ void fma2(u64& acc, u64 a, u64 b) {
    asm("fma.rn.f32x2 %0, %1, %2, %0;" : "+l"(acc) : "l"(a), "l"(b));
}
__device__ __forceinline__ void unpack2(u64 v, float& lo, float& hi) {
    asm("mov.b64 {%0, %1}, %2;" : "=f"(lo), "=f"(hi) : "l"(v));
}
__device__ __forceinline__ float to_tf32(float x) {
    uint32_t u; asm("cvt.rna.tf32.f32 %0, %1;" : "=r"(u) : "f"(x));
    return __uint_as_float(u);
}
__device__ __forceinline__ void mma8(float* c, const float4& a, const float2& b) {
    asm("mma.sync.aligned.m16n8k8.row.col.f32.tf32.tf32.f32 "
        "{%0,%1,%2,%3}, {%4,%5,%6,%7}, {%8,%9}, {%0,%1,%2,%3};"
        : "+f"(c[0]), "+f"(c[1]), "+f"(c[2]), "+f"(c[3])
        : "r"(__float_as_uint(a.x)), "r"(__float_as_uint(a.y)),
          "r"(__float_as_uint(a.z)), "r"(__float_as_uint(a.w)),
          "r"(__float_as_uint(b.x)), "r"(__float_as_uint(b.y)));
}
__device__ __forceinline__ void storeA(int m, int k, float v) {
    int kstep = k >> 3, kc = k & 7, mr = m & 15;
    int th = ((mr & 7) << 2) | (kc & 3);
    int reg = (mr >> 3) | ((kc >> 2) << 1);
    g_Af[((size_t)(m >> 4) * KS + kstep) * 128 + th * 4 + reg] = to_tf32(v);
}

// ---------------- init ------------------------------------------------------
__global__ void k_init() {
    int i = blockIdx.x * blockDim.x + threadIdx.x;
    if (i < T) { g_ecnt[i] = 0; g_ncnt[i] = 0; g_icnt[i] = 0; g_hcnt[i] = 0; }
    if (i < 3) g_norm3[i] = 0.0f;
}

// ---------------- W2 -> tf32 B-fragments ------------------------------------
__global__ void k_cvtB(const float* __restrict__ W2) {
    int i = blockIdx.x * blockDim.x + threadIdx.x;
    int k = i >> 8, n = i & 255;
    float v = to_tf32(W2[i]);
    int kstep = k >> 3, kc = k & 7;
    int th = ((n & 7) << 2) | (kc & 3);
    int reg = kc >> 2;
    g_Bf[((size_t)kstep * 32 + (n >> 3)) * 64 + th * 2 + reg] = v;
}

// ---------------- scatter into fixed-capacity buckets -----------------------
#define EBLK (E / 4 / 256)
#define NBLK (NV / 4 / 256)
__global__ void k_scatter(const int* __restrict__ ed, const int* __restrict__ esg,
                          const int* __restrict__ tli, const int* __restrict__ rel,
                          const float* __restrict__ tm, const int* __restrict__ esrc,
                          const int* __restrict__ nsg, const int* __restrict__ hop) {
    int b = blockIdx.x;
    if (b < EBLK) {
        int i = b * 256 + threadIdx.x;
        int4 d4 = ((const int4*)ed)[i];
        int4 s4 = ((const int4*)esg)[i];
        int4 r4 = ((const int4*)rel)[i];
        float4 t4 = ((const float4*)tm)[i];
        int4 sr4 = ((const int4*)esrc)[i];
        int dd[4] = {d4.x, d4.y, d4.z, d4.w};
        int ss[4] = {s4.x, s4.y, s4.z, s4.w};
        int rr[4] = {r4.x, r4.y, r4.z, r4.w};
        float tt[4] = {t4.x, t4.y, t4.z, t4.w};
        int sc[4] = {sr4.x, sr4.y, sr4.z, sr4.w};
#pragma unroll
        for (int q = 0; q < 4; q++) {
            if (dd[q] == __ldg(&tli[ss[q]])) {
                int pos = atomicAdd(&g_ecnt[ss[q]], 1);
                bool inb = (rr[q] < NET);
                if (inb) atomicAdd(&g_icnt[ss[q]], 1);
                float t = tt[q];
                unsigned pk = (unsigned)(i * 4 + q) | (inb ? 0x80000000u : 0u);
                float4 mt;
                mt.x = __uint_as_float(pk);
                mt.y = __int_as_float(sc[q]);
                mt.z = expf(-t);
                mt.w = expf(-t * (1.0f / 24.0f));
                g_emeta[(size_t)ss[q] * ECAP + pos] = mt;
            }
        }
    } else {
        int i = (b - EBLK) * 256 + threadIdx.x;
        int4 n4 = ((const int4*)nsg)[i];
        int4 h4 = ((const int4*)hop)[i];
        int nn[4] = {n4.x, n4.y, n4.z, n4.w};
        int hh[4] = {h4.x, h4.y, h4.z, h4.w};
#pragma unroll
        for (int q = 0; q < 4; q++) {
            int pos = atomicAdd(&g_ncnt[nn[q]], 1);
            bool h1 = (hh[q] == 1);
            if (h1) atomicAdd(&g_hcnt[nn[q]], 1);
            g_nlist[(size_t)nn[q] * NCAP + pos] =
                (unsigned)(i * 4 + q) | (h1 ? 0x80000000u : 0u);
        }
    }
}

// ---------------- block reduce helpers (128 threads) ------------------------
__device__ __forceinline__ float blk_sum(float v, float* sb) {
#pragma unroll
    for (int o = 16; o > 0; o >>= 1) v += __shfl_xor_sync(0xffffffffu, v, o);
    __syncthreads();
    if ((threadIdx.x & 31) == 0) sb[threadIdx.x >> 5] = v;
    __syncthreads();
    return sb[0] + sb[1] + sb[2] + sb[3];
}
__device__ __forceinline__ float blk_ln(float x, float* sb) {
    float m = blk_sum(x, sb) * (1.0f / 128.0f);
    float d = x - m;
    float v = blk_sum(d * d, sb) * (1.0f / 128.0f);
    return d * rsqrtf(v + 1e-5f);
}

// ---------------- edge_repr-side aggregation (features 0,1,4,7,8) -----------
__global__ void __launch_bounds__(128, 10) k_er(const float* __restrict__ edge_repr,
                                                const float* __restrict__ W1,
                                                const float* __restrict__ b1) {
    __shared__ float cmb[4][4][128];
    __shared__ float scmb[4][5];
    __shared__ float sb[4];
    int t = blockIdx.x;
    int tid = threadIdx.x;
    int wid = tid >> 5, lane = tid & 31;
    int c4 = lane << 2;

    float4 v_is = {0,0,0,0}, v_os = {0,0,0,0}, v_il = {0,0,0,0}, v_ol = {0,0,0,0};
    float d_is = 0, d_os = 0, d_il = 0, d_ol = 0, tsum = 0;

    int ecount = g_ecnt[t];
    const float4* ebase = g_emeta + (size_t)t * ECAP;
#pragma unroll 4
    for (int i = wid; i < ecount; i += 4) {
        float4 mt = ebase[i];
        unsigned pk = __float_as_uint(mt.x);
        int eidx = pk & 0x7fffffff;
        float sw = mt.z, lw = mt.w;
        float4 er = *(const float4*)(edge_repr + (size_t)eidx * H + c4);
        if (pk & 0x80000000u) {
            v_is.x += sw * er.x; v_is.y += sw * er.y; v_is.z += sw * er.z; v_is.w += sw * er.w;
            v_il.x += lw * er.x; v_il.y += lw * er.y; v_il.z += lw * er.z; v_il.w += lw * er.w;
            d_is += sw; d_il += lw;
        } else {
            v_os.x += sw * er.x; v_os.y += sw * er.y; v_os.z += sw * er.z; v_os.w += sw * er.w;
            v_ol.x += lw * er.x; v_ol.y += lw * er.y; v_ol.z += lw * er.z; v_ol.w += lw * er.w;
            d_os += sw; d_ol += lw;
        }
        tsum += -__logf(sw);
    }

    *(float4*)&cmb[wid][0][c4] = v_is;
    *(float4*)&cmb[wid][1][c4] = v_os;
    *(float4*)&cmb[wid][2][c4] = v_il;
    *(float4*)&cmb[wid][3][c4] = v_ol;
    if (lane == 0) {
        scmb[wid][0] = d_is; scmb[wid][1] = d_os; scmb[wid][2] = d_il; scmb[wid][3] = d_ol;
        scmb[wid][4] = tsum;
    }
    __syncthreads();

    int h = tid;
    float a_is = cmb[0][0][h] + cmb[1][0][h] + cmb[2][0][h] + cmb[3][0][h];
    float a_os = cmb[0][1][h] + cmb[1][1][h] + cmb[2][1][h] + cmb[3][1][h];
    float a_il = cmb[0][2][h] + cmb[1][2][h] + cmb[2][2][h] + cmb[3][2][h];
    float a_ol = cmb[0][3][h] + cmb[1][3][h] + cmb[2][3][h] + cmb[3][3][h];
    d_is = scmb[0][0] + scmb[1][0] + scmb[2][0] + scmb[3][0];
    d_os = scmb[0][1] + scmb[1][1] + scmb[2][1] + scmb[3][1];
    d_il = scmb[0][2] + scmb[1][2] + scmb[2][2] + scmb[3][2];
    d_ol = scmb[0][3] + scmb[1][3] + scmb[2][3] + scmb[3][3];
    tsum = scmb[0][4] + scmb[1][4] + scmb[2][4] + scmb[3][4];

    float in_s  = a_is / fmaxf(d_is, 1e-6f);
    float out_s = a_os / fmaxf(d_os, 1e-6f);
    float in_l  = a_il / fmaxf(d_il, 1e-6f);
    float out_l = a_ol / fmaxf(d_ol, 1e-6f);

    float burst = blk_ln(in_s + out_s - in_l - out_l, sb);
    float dirg  = blk_ln(out_l - in_l, sb);
    float asym  = blk_ln(fabsf(dirg), sb);
    float rb    = blk_ln(in_l + out_l, sb);

    float ssd = blk_sum(dirg * dirg, sb);
    if (h == 0) atomicAdd(&g_norm3[2], sqrtf(ssd));

    storeA(t, 0 * H + h, burst);
    storeA(t, 1 * H + h, dirg);
    storeA(t, 4 * H + h, asym);
    storeA(t, 7 * H + h, rb);

    if (h < 32) {
        float cin = (float)g_icnt[t];
        float cnt = (float)ecount;
        float cout = cnt - cin;
        float c1 = (float)g_hcnt[t];
        float c2 = (float)g_ncnt[t] - c1;
        float smw = d_is + d_os;
        float lmw = d_il + d_ol;
        float s0 = log1pf(cin), s1 = log1pf(cout), s2 = log1pf(c1), s3 = log1pf(c2);
        float s4 = tsum / fmaxf(cnt, 1e-6f);
        float s5 = smw, s6 = lmw, s7 = smw - lmw;
        float acc = b1[h];
        acc += s0 * W1[0 * 32 + h] + s1 * W1[1 * 32 + h] + s2 * W1[2 * 32 + h] + s3 * W1[3 * 32 + h]
             + s4 * W1[4 * 32 + h] + s5 * W1[5 * 32 + h] + s6 * W1[6 * 32 + h] + s7 * W1[7 * 32 + h];
        storeA(t, 8 * H + h, gelu_exact(acc));
    }
}

// ---------------- gather kernel: grid 2T ------------------------------------
// blocks [0,T): src gather (feature 3, norm[1]); [T,2T): node gather (2,5,6, norm[0])
__global__ void __launch_bounds__(128, 12) k_gather(const float* __restrict__ node_repr) {
    __shared__ float cmb[4][2][128];
    __shared__ float scmb[4][2];
    __shared__ float sb[4];
    int b = blockIdx.x;
    int tid = threadIdx.x;
    int wid = tid >> 5, lane = tid & 31;
    int c4 = lane << 2;
    int h = tid;

    if (b < T) {
        int t = b;
        float4 v_hs = {0,0,0,0}, v_hl = {0,0,0,0};
        float smw = 0, lmw = 0;
        int ecount = g_ecnt[t];
        const float4* ebase = g_emeta + (size_t)t * ECAP;
#pragma unroll 4
        for (int i = wid; i < ecount; i += 4) {
            float4 mt = ebase[i];
            int src = __float_as_int(mt.y);
            float sw = mt.z, lw = mt.w;
            float4 sr = *(const float4*)(node_repr + (size_t)src * H + c4);
            v_hs.x += sw * sr.x; v_hs.y += sw * sr.y; v_hs.z += sw * sr.z; v_hs.w += sw * sr.w;
            v_hl.x += lw * sr.x; v_hl.y += lw * sr.y; v_hl.z += lw * sr.z; v_hl.w += lw * sr.w;
            smw += sw; lmw += lw;
        }
        *(float4*)&cmb[wid][0][c4] = v_hs;
        *(float4*)&cmb[wid][1][c4] = v_hl;
        if (lane == 0) { scmb[wid][0] = smw; scmb[wid][1] = lmw; }
        __syncthreads();

        float a_hs = cmb[0][0][h] + cmb[1][0][h] + cmb[2][0][h] + cmb[3][0][h];
        float a_hl = cmb[0][1][h] + cmb[1][1][h] + cmb[2][1][h] + cmb[3][1][h];
        smw = scmb[0][0] + scmb[1][0] + scmb[2][0] + scmb[3][0];
        lmw = scmb[0][1] + scmb[1][1] + scmb[2][1] + scmb[3][1];

        float h1es = a_hs / fmaxf(smw, 1e-6f);
        float h1el = a_hl / fmaxf(lmw, 1e-6f);
        float slg = blk_ln(h1es - h1el, sb);
        float sss = blk_sum(slg * slg, sb);
        if (h == 0) atomicAdd(&g_norm3[1], sqrtf(sss));
        storeA(t, 3 * H + h, slg);
    } else {
        int t = b - T;
        float4 v_h1 = {0,0,0,0}, v_h2 = {0,0,0,0};
        int ncount = g_ncnt[t];
        const unsigned* nbase = g_nlist + (size_t)t * NCAP;
#pragma unroll 4
        for (int i = wid; i < ncount; i += 4) {
            unsigned pk = nbase[i];
            float4 nr = *(const float4*)(node_repr + (size_t)(pk & 0x7fffffff) * H + c4);
            if (pk & 0x80000000u) {
                v_h1.x += nr.x; v_h1.y += nr.y; v_h1.z += nr.z; v_h1.w += nr.w;
            } else {
                v_h2.x += nr.x; v_h2.y += nr.y; v_h2.z += nr.z; v_h2.w += nr.w;
            }
        }
        *(float4*)&cmb[wid][0][c4] = v_h1;
        *(float4*)&cmb[wid][1][c4] = v_h2;
        __syncthreads();

        float a_h1 = cmb[0][0][h] + cmb[1][0][h] + cmb[2][0][h] + cmb[3][0][h];
        float a_h2 = cmb[0][1][h] + cmb[1][1][h] + cmb[2][1][h] + cmb[3][1][h];
        float c1 = (float)g_hcnt[t];
        float c2 = (float)ncount - c1;

        float h1m = a_h1 / fmaxf(c1, 1e-6f);
        float h2m = a_h2 / fmaxf(c2, 1e-6f);

        float hopg = blk_ln(h1m - h2m, sb);
        float h1n  = blk_ln(h1m, sb);
        float h2n  = blk_ln(h2m, sb);

        float ssh = blk_sum(hopg * hopg, sb);
        if (h == 0) atomicAdd(&g_norm3[0], sqrtf(ssh));

        storeA(t, 2 * H + h, hopg);
        storeA(t, 5 * H + h, h1n);
        storeA(t, 6 * H + h, h2n);
    }
}

// ---------------- GEMM1: tf32 mma.sync, [T,1056]@[1056,256] + bias + GELU ---
__global__ void __launch_bounds__(256) k_gemm1(const float* __restrict__ b2) {
    int tid = threadIdx.x, lane = tid & 31, warp = tid >> 5;
    int wm = warp & 3, wn = warp >> 2;
    int bm = blockIdx.x * 128, bn = blockIdx.y * 64;
    int mt0 = (bm >> 4) + wm * 2;
    int nt0 = (bn >> 3) + wn * 4;

    float c[2][4][4];
#pragma unroll
    for (int i = 0; i < 2; i++)
#pragma unroll
        for (int j = 0; j < 4; j++)
#pragma unroll
            for (int r = 0; r < 4; r++) c[i][j][r] = 0.0f;

    const float4* A0 = (const float4*)(g_Af + (size_t)mt0 * KS * 128) + lane;
    const float4* A1 = (const float4*)(g_Af + (size_t)(mt0 + 1) * KS * 128) + lane;
    const float2* B0 = (const float2*)(g_Bf + (size_t)nt0 * 64) + lane;

#pragma unroll 2
    for (int ks = 0; ks < KS; ks++) {
        float4 a0 = A0[ks * 32];
        float4 a1 = A1[ks * 32];
        float2 bf[4];
#pragma unroll
        for (int j = 0; j < 4; j++) bf[j] = B0[((size_t)ks * 32 + j) * 32];
#pragma unroll
        for (int j = 0; j < 4; j++) {
            mma8(c[0][j], a0, bf[j]);
            mma8(c[1][j], a1, bf[j]);
        }
    }

#pragma unroll
    for (int i = 0; i < 2; i++) {
        int r0 = bm + wm * 32 + i * 16 + (lane >> 2);
#pragma unroll
        for (int j = 0; j < 4; j++) {
            int cc = bn + wn * 32 + j * 8 + (lane & 3) * 2;
            float bx = b2[cc], by = b2[cc + 1];
            float2 lo, hi;
            lo.x = gelu_exact(c[i][j][0] + bx);
            lo.y = gelu_exact(c[i][j][1] + by);
            hi.x = gelu_exact(c[i][j][2] + bx);
            hi.y = gelu_exact(c[i][j][3] + by);
            *(float2*)(g_hidden + (size_t)r0 * HD + cc) = lo;
            *(float2*)(g_hidden + (size_t)(r0 + 8) * HD + cc) = hi;
        }
    }
}

// ---------------- GEMM2: [T,256] @ [256,128] + bias + 0.25*tanh + norms -----
__global__ void __launch_bounds__(256) k_gemm2(const float* __restrict__ W3,
                                               const float* __restrict__ b3,
                                               float* __restrict__ out) {
    __shared__ float hs[16 * 256];
    int tid = threadIdx.x;
    int t0 = blockIdx.x * 16;
    if (blockIdx.x == 0 && tid < 3)
        out[(size_t)T * H + tid] = g_norm3[tid] * (1.0f / (float)T);
    for (int i = tid; i < 16 * 256; i += 256)
        hs[i] = g_hidden[(size_t)t0 * 256 + i];
    __syncthreads();
    int n = tid & 127;
    int half = tid >> 7;
    const float* hp = hs + half * 8 * 256;
    u64 acc2[8];
#pragma unroll
    for (int r = 0; r < 8; r++) acc2[r] = 0ull;
    for (int k = 0; k < 256; k += 4) {
        float w0 = W3[(k + 0) * 128 + n];
        float w1 = W3[(k + 1) * 128 + n];
        float w2 = W3[(k + 2) * 128 + n];
        float w3v = W3[(k + 3) * 128 + n];
        u64 w01 = pack2(w0, w1);
        u64 w23 = pack2(w2, w3v);
#pragma unroll
        for (int r = 0; r < 8; r++) {
            ulonglong2 hv = *(const ulonglong2*)&hp[r * 256 + k];
            fma2(acc2[r], hv.x, w01);
            fma2(acc2[r], hv.y, w23);
        }
    }
    float bias = b3[n];
#pragma unroll
    for (int r = 0; r < 8; r++) {
        float lo, hi;
        unpack2(acc2[r], lo, hi);
        out[(size_t)(t0 + half * 8 + r) * 128 + n] = 0.25f * tanhf(lo + hi + bias);
    }
}

// ---------------- launcher --------------------------------------------------
extern "C" void kernel_launch(void* const* d_in, const int* in_sizes, int n_in,
                              void* d_out, int out_size) {
    const float* node_repr = (const float*)d_in[0];
    const float* edge_repr = (const float*)d_in[1];
    const int*   edge_src  = (const int*)d_in[2];
    const int*   edge_dst  = (const int*)d_in[3];
    const int*   rel_ids   = (const int*)d_in[4];
    const float* etime     = (const float*)d_in[5];
    const int*   tli       = (const int*)d_in[6];
    const int*   nsg       = (const int*)d_in[7];
    const int*   esg       = (const int*)d_in[8];
    const int*   hop       = (const int*)d_in[9];
    const float* W1 = (const float*)d_in[10];
    const float* b1 = (const float*)d_in[11];
    const float* W2 = (const float*)d_in[12];
    const float* b2 = (const float*)d_in[13];
    const float* W3 = (const float*)d_in[14];
    const float* b3 = (const float*)d_in[15];
    float* out = (float*)d_out;

    k_init<<<16, 256>>>();
    k_cvtB<<<FD * HD / 256, 256>>>(W2);
    k_scatter<<<EBLK + NBLK, 256>>>(edge_dst, esg, tli, rel_ids, etime, edge_src, nsg, hop);
    k_er<<<T, 128>>>(edge_repr, W1, b1);
    k_gather<<<2 * T, 128>>>(node_repr);
    k_gemm1<<<dim3(32, 4), 256>>>(b2);
    k_gemm2<<<T / 16, 256>>>(W3, b3, out);
}

// round 9
// speedup vs baseline: 1.8870x; 1.0191x over previous
#include <cuda_runtime.h>
#include <cuda_bf16.h>
#include <cstdint>

#define H 128
#define E 1048576
#define NV 262144
#define T 4096
#define NET 8
#define FD 1056   // 8*H + 32
#define HD 256    // 2*H
#define KS 132    // FD / 8 k-steps
#define ECAP 256
#define NCAP 256

// ---------------- scratch ---------------------------------------------------
__device__ int g_ecnt[T];
__device__ int g_ncnt[T];
__device__ int g_icnt[T];
__device__ int g_hcnt[T];
__device__ float4   g_emeta[(size_t)T * ECAP];
__device__ unsigned g_nlist[(size_t)T * NCAP];
__device__ float g_Af[(size_t)(T / 16) * KS * 128];
__device__ float g_Bf[(size_t)KS * 32 * 64];
__device__ float g_hidden[(size_t)T * HD];
__device__ float g_norm3[3];

typedef unsigned long long u64;

__device__ __forceinline__ float gelu_exact(float x) {
    return 0.5f * x * (1.0f + erff(x * 0.7071067811865476f));
}
__device__ __forceinline__ u64 pack2(float lo, float hi) {
    u64 r; asm("mov.b64 %0, {%1, %2};" : "=l"(r) : "f"(lo), "f"(hi)); return r;
}
__device__ __forceinline__ void fma2(u64& acc, u64 a, u64 b) {
    asm("fma.rn.f32x2 %0, %1, %2, %0;" : "+l"(acc) : "l"(a), "l"(b));
}
__device__ __forceinline__ void unpack2(u64 v, float& lo, float& hi) {
    asm("mov.b64 {%0, %1}, %2;" : "=f"(lo), "=f"(hi) : "l"(v));
}
__device__ __forceinline__ float to_tf32(float x) {
    uint32_t u; asm("cvt.rna.tf32.f32 %0, %1;" : "=r"(u) : "f"(x));
    return __uint_as_float(u);
}
__device__ __forceinline__ void mma8(float* c, const float4& a, const float2& b) {
    asm("mma.sync.aligned.m16n8k8.row.col.f32.tf32.tf32.f32 "
        "{%0,%1,%2,%3}, {%4,%5,%6,%7}, {%8,%9}, {%0,%1,%2,%3};"
        : "+f"(c[0]), "+f"(c[1]), "+f"(c[2]), "+f"(c[3])
        : "r"(__float_as_uint(a.x)), "r"(__float_as_uint(a.y)),
          "r"(__float_as_uint(a.z)), "r"(__float_as_uint(a.w)),
          "r"(__float_as_uint(b.x)), "r"(__float_as_uint(b.y)));
}
__device__ __forceinline__ void storeA(int m, int k, float v) {
    int kstep = k >> 3, kc = k & 7, mr = m & 15;
    int th = ((mr & 7) << 2) | (kc & 3);
    int reg = (mr >> 3) | ((kc >> 2) << 1);
    g_Af[((size_t)(m >> 4) * KS + kstep) * 128 + th * 4 + reg] = to_tf32(v);
}

// ---------------- init ------------------------------------------------------
__global__ void k_init() {
    int i = blockIdx.x * blockDim.x + threadIdx.x;
    if (i < T) { g_ecnt[i] = 0; g_ncnt[i] = 0; g_icnt[i] = 0; g_hcnt[i] = 0; }
    if (i < 3) g_norm3[i] = 0.0f;
}

// ---------------- W2 -> tf32 B-fragments ------------------------------------
__global__ void k_cvtB(const float* __restrict__ W2) {
    int i = blockIdx.x * blockDim.x + threadIdx.x;
    int k = i >> 8, n = i & 255;
    float v = to_tf32(W2[i]);
    int kstep = k >> 3, kc = k & 7;
    int th = ((n & 7) << 2) | (kc & 3);
    int reg = kc >> 2;
    g_Bf[((size_t)kstep * 32 + (n >> 3)) * 64 + th * 2 + reg] = v;
}

// ---------------- scatter into fixed-capacity buckets -----------------------
#define EBLK (E / 4 / 256)
#define NBLK (NV / 4 / 256)
__global__ void k_scatter(const int* __restrict__ ed, const int* __restrict__ esg,
                          const int* __restrict__ tli, const int* __restrict__ rel,
                          const float* __restrict__ tm, const int* __restrict__ esrc,
                          const int* __restrict__ nsg, const int* __restrict__ hop) {
    int b = blockIdx.x;
    if (b < EBLK) {
        int i = b * 256 + threadIdx.x;
        int4 d4 = ((const int4*)ed)[i];
        int4 s4 = ((const int4*)esg)[i];
        int4 r4 = ((const int4*)rel)[i];
        float4 t4 = ((const float4*)tm)[i];
        int4 sr4 = ((const int4*)esrc)[i];
        int dd[4] = {d4.x, d4.y, d4.z, d4.w};
        int ss[4] = {s4.x, s4.y, s4.z, s4.w};
        int rr[4] = {r4.x, r4.y, r4.z, r4.w};
        float tt[4] = {t4.x, t4.y, t4.z, t4.w};
        int sc[4] = {sr4.x, sr4.y, sr4.z, sr4.w};
#pragma unroll
        for (int q = 0; q < 4; q++) {
            if (dd[q] == __ldg(&tli[ss[q]])) {
                int pos = atomicAdd(&g_ecnt[ss[q]], 1);
                bool inb = (rr[q] < NET);
                if (inb) atomicAdd(&g_icnt[ss[q]], 1);
                float t = tt[q];
                unsigned pk = (unsigned)(i * 4 + q) | (inb ? 0x80000000u : 0u);
                float4 mt;
                mt.x = __uint_as_float(pk);
                mt.y = __int_as_float(sc[q]);
                mt.z = expf(-t);
                mt.w = expf(-t * (1.0f / 24.0f));
                g_emeta[(size_t)ss[q] * ECAP + pos] = mt;
            }
        }
    } else {
        int i = (b - EBLK) * 256 + threadIdx.x;
        int4 n4 = ((const int4*)nsg)[i];
        int4 h4 = ((const int4*)hop)[i];
        int nn[4] = {n4.x, n4.y, n4.z, n4.w};
        int hh[4] = {h4.x, h4.y, h4.z, h4.w};
#pragma unroll
        for (int q = 0; q < 4; q++) {
            int pos = atomicAdd(&g_ncnt[nn[q]], 1);
            bool h1 = (hh[q] == 1);
            if (h1) atomicAdd(&g_hcnt[nn[q]], 1);
            g_nlist[(size_t)nn[q] * NCAP + pos] =
                (unsigned)(i * 4 + q) | (h1 ? 0x80000000u : 0u);
        }
    }
}

// ---------------- block reduce helpers (128 threads) ------------------------
__device__ __forceinline__ float blk_sum(float v, float* sb) {
#pragma unroll
    for (int o = 16; o > 0; o >>= 1) v += __shfl_xor_sync(0xffffffffu, v, o);
    __syncthreads();
    if ((threadIdx.x & 31) == 0) sb[threadIdx.x >> 5] = v;
    __syncthreads();
    return sb[0] + sb[1] + sb[2] + sb[3];
}
__device__ __forceinline__ float blk_ln(float x, float* sb) {
    float m = blk_sum(x, sb) * (1.0f / 128.0f);
    float d = x - m;
    float v = blk_sum(d * d, sb) * (1.0f / 128.0f);
    return d * rsqrtf(v + 1e-5f);
}

// ---------------- edge_repr-side aggregation (features 0,1,4,7,8) -----------
__global__ void __launch_bounds__(128, 10) k_er(const float* __restrict__ edge_repr,
                                                const float* __restrict__ W1,
                                                const float* __restrict__ b1) {
    __shared__ float4 smeta[ECAP];
    __shared__ float cmb[4][4][128];
    __shared__ float scmb[4][5];
    __shared__ float sb[4];
    int t = blockIdx.x;
    int tid = threadIdx.x;
    int wid = tid >> 5, lane = tid & 31;
    int c4 = lane << 2;

    int ecount = g_ecnt[t];
    const float4* ebase = g_emeta + (size_t)t * ECAP;
    for (int i = tid; i < ecount; i += 128) smeta[i] = ebase[i];
    __syncthreads();

    float4 v_is = {0,0,0,0}, v_os = {0,0,0,0}, v_il = {0,0,0,0}, v_ol = {0,0,0,0};
    float d_is = 0, d_os = 0, d_il = 0, d_ol = 0, tsum = 0;

#pragma unroll 4
    for (int i = wid; i < ecount; i += 4) {
        float4 mt = smeta[i];
        unsigned pk = __float_as_uint(mt.x);
        int eidx = pk & 0x7fffffff;
        float sw = mt.z, lw = mt.w;
        float4 er = *(const float4*)(edge_repr + (size_t)eidx * H + c4);
        if (pk & 0x80000000u) {
            v_is.x += sw * er.x; v_is.y += sw * er.y; v_is.z += sw * er.z; v_is.w += sw * er.w;
            v_il.x += lw * er.x; v_il.y += lw * er.y; v_il.z += lw * er.z; v_il.w += lw * er.w;
            d_is += sw; d_il += lw;
        } else {
            v_os.x += sw * er.x; v_os.y += sw * er.y; v_os.z += sw * er.z; v_os.w += sw * er.w;
            v_ol.x += lw * er.x; v_ol.y += lw * er.y; v_ol.z += lw * er.z; v_ol.w += lw * er.w;
            d_os += sw; d_ol += lw;
        }
        tsum += -__logf(sw);
    }

    *(float4*)&cmb[wid][0][c4] = v_is;
    *(float4*)&cmb[wid][1][c4] = v_os;
    *(float4*)&cmb[wid][2][c4] = v_il;
    *(float4*)&cmb[wid][3][c4] = v_ol;
    if (lane == 0) {
        scmb[wid][0] = d_is; scmb[wid][1] = d_os; scmb[wid][2] = d_il; scmb[wid][3] = d_ol;
        scmb[wid][4] = tsum;
    }
    __syncthreads();

    int h = tid;
    float a_is = cmb[0][0][h] + cmb[1][0][h] + cmb[2][0][h] + cmb[3][0][h];
    float a_os = cmb[0][1][h] + cmb[1][1][h] + cmb[2][1][h] + cmb[3][1][h];
    float a_il = cmb[0][2][h] + cmb[1][2][h] + cmb[2][2][h] + cmb[3][2][h];
    float a_ol = cmb[0][3][h] + cmb[1][3][h] + cmb[2][3][h] + cmb[3][3][h];
    d_is = scmb[0][0] + scmb[1][0] + scmb[2][0] + scmb[3][0];
    d_os = scmb[0][1] + scmb[1][1] + scmb[2][1] + scmb[3][1];
    d_il = scmb[0][2] + scmb[1][2] + scmb[2][2] + scmb[3][2];
    d_ol = scmb[0][3] + scmb[1][3] + scmb[2][3] + scmb[3][3];
    tsum = scmb[0][4] + scmb[1][4] + scmb[2][4] + scmb[3][4];

    float in_s  = a_is / fmaxf(d_is, 1e-6f);
    float out_s = a_os / fmaxf(d_os, 1e-6f);
    float in_l  = a_il / fmaxf(d_il, 1e-6f);
    float out_l = a_ol / fmaxf(d_ol, 1e-6f);

    float burst = blk_ln(in_s + out_s - in_l - out_l, sb);
    float dirg  = blk_ln(out_l - in_l, sb);
    float asym  = blk_ln(fabsf(dirg), sb);
    float rb    = blk_ln(in_l + out_l, sb);

    float ssd = blk_sum(dirg * dirg, sb);
    if (h == 0) atomicAdd(&g_norm3[2], sqrtf(ssd));

    storeA(t, 0 * H + h, burst);
    storeA(t, 1 * H + h, dirg);
    storeA(t, 4 * H + h, asym);
    storeA(t, 7 * H + h, rb);

    if (h < 32) {
        float cin = (float)g_icnt[t];
        float cnt = (float)ecount;
        float cout = cnt - cin;
        float c1 = (float)g_hcnt[t];
        float c2 = (float)g_ncnt[t] - c1;
        float smw = d_is + d_os;
        float lmw = d_il + d_ol;
        float s0 = log1pf(cin), s1 = log1pf(cout), s2 = log1pf(c1), s3 = log1pf(c2);
        float s4 = tsum / fmaxf(cnt, 1e-6f);
        float s5 = smw, s6 = lmw, s7 = smw - lmw;
        float acc = b1[h];
        acc += s0 * W1[0 * 32 + h] + s1 * W1[1 * 32 + h] + s2 * W1[2 * 32 + h] + s3 * W1[3 * 32 + h]
             + s4 * W1[4 * 32 + h] + s5 * W1[5 * 32 + h] + s6 * W1[6 * 32 + h] + s7 * W1[7 * 32 + h];
        storeA(t, 8 * H + h, gelu_exact(acc));
    }
}

// ---------------- src gather (feature 3, norm[1]) ----------------------------
__global__ void __launch_bounds__(128, 12) k_gsrc(const float* __restrict__ node_repr) {
    __shared__ float4 smeta[ECAP];
    __shared__ float cmb[4][2][128];
    __shared__ float scmb[4][2];
    __shared__ float sb[4];
    int t = blockIdx.x;
    int tid = threadIdx.x;
    int wid = tid >> 5, lane = tid & 31;
    int c4 = lane << 2;
    int h = tid;

    int ecount = g_ecnt[t];
    const float4* ebase = g_emeta + (size_t)t * ECAP;
    for (int i = tid; i < ecount; i += 128) smeta[i] = ebase[i];
    __syncthreads();

    float4 v_hs = {0,0,0,0}, v_hl = {0,0,0,0};
    float smw = 0, lmw = 0;
#pragma unroll 4
    for (int i = wid; i < ecount; i += 4) {
        float4 mt = smeta[i];
        int src = __float_as_int(mt.y);
        float sw = mt.z, lw = mt.w;
        float4 sr = *(const float4*)(node_repr + (size_t)src * H + c4);
        v_hs.x += sw * sr.x; v_hs.y += sw * sr.y; v_hs.z += sw * sr.z; v_hs.w += sw * sr.w;
        v_hl.x += lw * sr.x; v_hl.y += lw * sr.y; v_hl.z += lw * sr.z; v_hl.w += lw * sr.w;
        smw += sw; lmw += lw;
    }
    *(float4*)&cmb[wid][0][c4] = v_hs;
    *(float4*)&cmb[wid][1][c4] = v_hl;
    if (lane == 0) { scmb[wid][0] = smw; scmb[wid][1] = lmw; }
    __syncthreads();

    float a_hs = cmb[0][0][h] + cmb[1][0][h] + cmb[2][0][h] + cmb[3][0][h];
    float a_hl = cmb[0][1][h] + cmb[1][1][h] + cmb[2][1][h] + cmb[3][1][h];
    smw = scmb[0][0] + scmb[1][0] + scmb[2][0] + scmb[3][0];
    lmw = scmb[0][1] + scmb[1][1] + scmb[2][1] + scmb[3][1];

    float h1es = a_hs / fmaxf(smw, 1e-6f);
    float h1el = a_hl / fmaxf(lmw, 1e-6f);
    float slg = blk_ln(h1es - h1el, sb);
    float sss = blk_sum(slg * slg, sb);
    if (h == 0) atomicAdd(&g_norm3[1], sqrtf(sss));
    storeA(t, 3 * H + h, slg);
}

// ---------------- node gather (features 2,5,6, norm[0]) ----------------------
__global__ void __launch_bounds__(128, 12) k_gnode(const float* __restrict__ node_repr) {
    __shared__ unsigned snl[NCAP];
    __shared__ float cmb[4][2][128];
    __shared__ float sb[4];
    int t = blockIdx.x;
    int tid = threadIdx.x;
    int wid = tid >> 5, lane = tid & 31;
    int c4 = lane << 2;
    int h = tid;

    int ncount = g_ncnt[t];
    const unsigned* nbase = g_nlist + (size_t)t * NCAP;
    for (int i = tid; i < ncount; i += 128) snl[i] = nbase[i];
    __syncthreads();

    float4 v_h1 = {0,0,0,0}, v_h2 = {0,0,0,0};
#pragma unroll 4
    for (int i = wid; i < ncount; i += 4) {
        unsigned pk = snl[i];
        float4 nr = *(const float4*)(node_repr + (size_t)(pk & 0x7fffffff) * H + c4);
        if (pk & 0x80000000u) {
            v_h1.x += nr.x; v_h1.y += nr.y; v_h1.z += nr.z; v_h1.w += nr.w;
        } else {
            v_h2.x += nr.x; v_h2.y += nr.y; v_h2.z += nr.z; v_h2.w += nr.w;
        }
    }
    *(float4*)&cmb[wid][0][c4] = v_h1;
    *(float4*)&cmb[wid][1][c4] = v_h2;
    __syncthreads();

    float a_h1 = cmb[0][0][h] + cmb[1][0][h] + cmb[2][0][h] + cmb[3][0][h];
    float a_h2 = cmb[0][1][h] + cmb[1][1][h] + cmb[2][1][h] + cmb[3][1][h];
    float c1 = (float)g_hcnt[t];
    float c2 = (float)ncount - c1;

    float h1m = a_h1 / fmaxf(c1, 1e-6f);
    float h2m = a_h2 / fmaxf(c2, 1e-6f);

    float hopg = blk_ln(h1m - h2m, sb);
    float h1n  = blk_ln(h1m, sb);
    float h2n  = blk_ln(h2m, sb);

    float ssh = blk_sum(hopg * hopg, sb);
    if (h == 0) atomicAdd(&g_norm3[0], sqrtf(ssh));

    storeA(t, 2 * H + h, hopg);
    storeA(t, 5 * H + h, h1n);
    storeA(t, 6 * H + h, h2n);
}

// ---------------- GEMM1: tf32 mma.sync, [T,1056]@[1056,256] + bias + GELU ---
__global__ void __launch_bounds__(256) k_gemm1(const float* __restrict__ b2) {
    int tid = threadIdx.x, lane = tid & 31, warp = tid >> 5;
    int wm = warp & 3, wn = warp >> 2;
    int bm = blockIdx.x * 128, bn = blockIdx.y * 64;
    int mt0 = (bm >> 4) + wm * 2;
    int nt0 = (bn >> 3) + wn * 4;

    float c[2][4][4];
#pragma unroll
    for (int i = 0; i < 2; i++)
#pragma unroll
        for (int j = 0; j < 4; j++)
#pragma unroll
            for (int r = 0; r < 4; r++) c[i][j][r] = 0.0f;

    const float4* A0 = (const float4*)(g_Af + (size_t)mt0 * KS * 128) + lane;
    const float4* A1 = (const float4*)(g_Af + (size_t)(mt0 + 1) * KS * 128) + lane;
    const float2* B0 = (const float2*)(g_Bf + (size_t)nt0 * 64) + lane;

#pragma unroll 2
    for (int ks = 0; ks < KS; ks++) {
        float4 a0 = A0[ks * 32];
        float4 a1 = A1[ks * 32];
        float2 bf[4];
#pragma unroll
        for (int j = 0; j < 4; j++) bf[j] = B0[((size_t)ks * 32 + j) * 32];
#pragma unroll
        for (int j = 0; j < 4; j++) {
            mma8(c[0][j], a0, bf[j]);
            mma8(c[1][j], a1, bf[j]);
        }
    }

#pragma unroll
    for (int i = 0; i < 2; i++) {
        int r0 = bm + wm * 32 + i * 16 + (lane >> 2);
#pragma unroll
        for (int j = 0; j < 4; j++) {
            int cc = bn + wn * 32 + j * 8 + (lane & 3) * 2;
            float bx = b2[cc], by = b2[cc + 1];
            float2 lo, hi;
            lo.x = gelu_exact(c[i][j][0] + bx);
            lo.y = gelu_exact(c[i][j][1] + by);
            hi.x = gelu_exact(c[i][j][2] + bx);
            hi.y = gelu_exact(c[i][j][3] + by);
            *(float2*)(g_hidden + (size_t)r0 * HD + cc) = lo;
            *(float2*)(g_hidden + (size_t)(r0 + 8) * HD + cc) = hi;
        }
    }
}

// ---------------- GEMM2: [T,256] @ [256,128] + bias + 0.25*tanh + norms -----
__global__ void __launch_bounds__(256) k_gemm2(const float* __restrict__ W3,
                                               const float* __restrict__ b3,
                                               float* __restrict__ out) {
    __shared__ float hs[16 * 256];
    int tid = threadIdx.x;
    int t0 = blockIdx.x * 16;
    if (blockIdx.x == 0 && tid < 3)
        out[(size_t)T * H + tid] = g_norm3[tid] * (1.0f / (float)T);
    for (int i = tid; i < 16 * 256; i += 256)
        hs[i] = g_hidden[(size_t)t0 * 256 + i];
    __syncthreads();
    int n = tid & 127;
    int half = tid >> 7;
    const float* hp = hs + half * 8 * 256;
    u64 acc2[8];
#pragma unroll
    for (int r = 0; r < 8; r++) acc2[r] = 0ull;
    for (int k = 0; k < 256; k += 4) {
        float w0 = W3[(k + 0) * 128 + n];
        float w1 = W3[(k + 1) * 128 + n];
        float w2 = W3[(k + 2) * 128 + n];
        float w3v = W3[(k + 3) * 128 + n];
        u64 w01 = pack2(w0, w1);
        u64 w23 = pack2(w2, w3v);
#pragma unroll
        for (int r = 0; r < 8; r++) {
            ulonglong2 hv = *(const ulonglong2*)&hp[r * 256 + k];
            fma2(acc2[r], hv.x, w01);
            fma2(acc2[r], hv.y, w23);
        }
    }
    float bias = b3[n];
#pragma unroll
    for (int r = 0; r < 8; r++) {
        float lo, hi;
        unpack2(acc2[r], lo, hi);
        out[(size_t)(t0 + half * 8 + r) * 128 + n] = 0.25f * tanhf(lo + hi + bias);
    }
}

// ---------------- launcher --------------------------------------------------
extern "C" void kernel_launch(void* const* d_in, const int* in_sizes, int n_in,
                              void* d_out, int out_size) {
    const float* node_repr = (const float*)d_in[0];
    const float* edge_repr = (const float*)d_in[1];
    const int*   edge_src  = (const int*)d_in[2];
    const int*   edge_dst  = (const int*)d_in[3];
    const int*   rel_ids   = (const int*)d_in[4];
    const float* etime     = (const float*)d_in[5];
    const int*   tli       = (const int*)d_in[6];
    const int*   nsg       = (const int*)d_in[7];
    const int*   esg       = (const int*)d_in[8];
    const int*   hop       = (const int*)d_in[9];
    const float* W1 = (const float*)d_in[10];
    const float* b1 = (const float*)d_in[11];
    const float* W2 = (const float*)d_in[12];
    const float* b2 = (const float*)d_in[13];
    const float* W3 = (const float*)d_in[14];
    const float* b3 = (const float*)d_in[15];
    float* out = (float*)d_out;

    k_init<<<16, 256>>>();
    k_cvtB<<<FD * HD / 256, 256>>>(W2);
    k_scatter<<<EBLK + NBLK, 256>>>(edge_dst, esg, tli, rel_ids, etime, edge_src, nsg, hop);
    k_er<<<T, 128>>>(edge_repr, W1, b1);
    k_gsrc<<<T, 128>>>(node_repr);
    k_gnode<<<T, 128>>>(node_repr);
    k_gemm1<<<dim3(32, 4), 256>>>(b2);
    k_gemm2<<<T / 16, 256>>>(W3, b3, out);
}

// round 10
// speedup vs baseline: 1.9833x; 1.0510x over previous
#include <cuda_runtime.h>
#include <cuda_bf16.h>
#include <cstdint>

#define H 128
#define E 1048576
#define NV 262144
#define T 4096
#define NET 8
#define FD 1056   // 8*H + 32
#define HD 256    // 2*H
#define KS 132    // FD / 8 k-steps
#define ECAP 256
#define NCAP 256

// ---------------- scratch ---------------------------------------------------
__device__ int g_ecnt[T];
__device__ int g_ncnt[T];
__device__ int g_icnt[T];
__device__ int g_hcnt[T];
__device__ float4   g_emeta[(size_t)T * ECAP];
__device__ unsigned g_nlist[(size_t)T * NCAP];
__device__ float g_Af[(size_t)(T / 16) * KS * 128];
__device__ float g_Bf[(size_t)KS * 32 * 64];
__device__ float g_hidden[(size_t)T * HD];
__device__ float g_norm3[3];

typedef unsigned long long u64;

__device__ __forceinline__ float gelu_exact(float x) {
    return 0.5f * x * (1.0f + erff(x * 0.7071067811865476f));
}
__device__ __forceinline__ u64 pack2(float lo, float hi) {
    u64 r; asm("mov.b64 %0, {%1, %2};" : "=l"(r) : "f"(lo), "f"(hi)); return r;
}
__device__ __forceinline__ void fma2(u64& acc, u64 a, u64 b) {
    asm("fma.rn.f32x2 %0, %1, %2, %0;" : "+l"(acc) : "l"(a), "l"(b));
}
__device__ __forceinline__ void unpack2(u64 v, float& lo, float& hi) {
    asm("mov.b64 {%0, %1}, %2;" : "=f"(lo), "=f"(hi) : "l"(v));
}
__device__ __forceinline__ float to_tf32(float x) {
    uint32_t u; asm("cvt.rna.tf32.f32 %0, %1;" : "=r"(u) : "f"(x));
    return __uint_as_float(u);
}
__device__ __forceinline__ void mma8(float* c, const float4& a, const float2& b) {
    asm("mma.sync.aligned.m16n8k8.row.col.f32.tf32.tf32.f32 "
        "{%0,%1,%2,%3}, {%4,%5,%6,%7}, {%8,%9}, {%0,%1,%2,%3};"
        : "+f"(c[0]), "+f"(c[1]), "+f"(c[2]), "+f"(c[3])
        : "r"(__float_as_uint(a.x)), "r"(__float_as_uint(a.y)),
          "r"(__float_as_uint(a.z)), "r"(__float_as_uint(a.w)),
          "r"(__float_as_uint(b.x)), "r"(__float_as_uint(b.y)));
}
__device__ __forceinline__ void storeA(int m, int k, float v) {
    int kstep = k >> 3, kc = k & 7, mr = m & 15;
    int th = ((mr & 7) << 2) | (kc & 3);
    int reg = (mr >> 3) | ((kc >> 2) << 1);
    g_Af[((size_t)(m >> 4) * KS + kstep) * 128 + th * 4 + reg] = to_tf32(v);
}

// ---------------- init ------------------------------------------------------
__global__ void k_init() {
    int i = blockIdx.x * blockDim.x + threadIdx.x;
    if (i < T) { g_ecnt[i] = 0; g_ncnt[i] = 0; g_icnt[i] = 0; g_hcnt[i] = 0; }
    if (i < 3) g_norm3[i] = 0.0f;
}

// ---------------- W2 -> tf32 B-fragments ------------------------------------
__global__ void k_cvtB(const float* __restrict__ W2) {
    int i = blockIdx.x * blockDim.x + threadIdx.x;
    int k = i >> 8, n = i & 255;
    float v = to_tf32(W2[i]);
    int kstep = k >> 3, kc = k & 7;
    int th = ((n & 7) << 2) | (kc & 3);
    int reg = kc >> 2;
    g_Bf[((size_t)kstep * 32 + (n >> 3)) * 64 + th * 2 + reg] = v;
}

// ---------------- scatter into fixed-capacity buckets -----------------------
#define EBLK (E / 4 / 256)
#define NBLK (NV / 4 / 256)
__global__ void k_scatter(const int* __restrict__ ed, const int* __restrict__ esg,
                          const int* __restrict__ tli, const int* __restrict__ rel,
                          const float* __restrict__ tm, const int* __restrict__ esrc,
                          const int* __restrict__ nsg, const int* __restrict__ hop) {
    int b = blockIdx.x;
    if (b < EBLK) {
        int i = b * 256 + threadIdx.x;
        int4 d4 = ((const int4*)ed)[i];
        int4 s4 = ((const int4*)esg)[i];
        int4 r4 = ((const int4*)rel)[i];
        float4 t4 = ((const float4*)tm)[i];
        int4 sr4 = ((const int4*)esrc)[i];
        int dd[4] = {d4.x, d4.y, d4.z, d4.w};
        int ss[4] = {s4.x, s4.y, s4.z, s4.w};
        int rr[4] = {r4.x, r4.y, r4.z, r4.w};
        float tt[4] = {t4.x, t4.y, t4.z, t4.w};
        int sc[4] = {sr4.x, sr4.y, sr4.z, sr4.w};
#pragma unroll
        for (int q = 0; q < 4; q++) {
            if (dd[q] == __ldg(&tli[ss[q]])) {
                int pos = atomicAdd(&g_ecnt[ss[q]], 1);
                bool inb = (rr[q] < NET);
                if (inb) atomicAdd(&g_icnt[ss[q]], 1);
                float t = tt[q];
                unsigned pk = (unsigned)(i * 4 + q) | (inb ? 0x80000000u : 0u);
                float4 mt;
                mt.x = __uint_as_float(pk);
                mt.y = __int_as_float(sc[q]);
                mt.z = expf(-t);
                mt.w = expf(-t * (1.0f / 24.0f));
                g_emeta[(size_t)ss[q] * ECAP + pos] = mt;
            }
        }
    } else {
        int i = (b - EBLK) * 256 + threadIdx.x;
        int4 n4 = ((const int4*)nsg)[i];
        int4 h4 = ((const int4*)hop)[i];
        int nn[4] = {n4.x, n4.y, n4.z, n4.w};
        int hh[4] = {h4.x, h4.y, h4.z, h4.w};
#pragma unroll
        for (int q = 0; q < 4; q++) {
            int pos = atomicAdd(&g_ncnt[nn[q]], 1);
            bool h1 = (hh[q] == 1);
            if (h1) atomicAdd(&g_hcnt[nn[q]], 1);
            g_nlist[(size_t)nn[q] * NCAP + pos] =
                (unsigned)(i * 4 + q) | (h1 ? 0x80000000u : 0u);
        }
    }
}

// ---------------- block reduce helpers (128 threads) ------------------------
__device__ __forceinline__ float blk_sum(float v, float* sb) {
#pragma unroll
    for (int o = 16; o > 0; o >>= 1) v += __shfl_xor_sync(0xffffffffu, v, o);
    __syncthreads();
    if ((threadIdx.x & 31) == 0) sb[threadIdx.x >> 5] = v;
    __syncthreads();
    return sb[0] + sb[1] + sb[2] + sb[3];
}
__device__ __forceinline__ float blk_ln(float x, float* sb) {
    float m = blk_sum(x, sb) * (1.0f / 128.0f);
    float d = x - m;
    float v = blk_sum(d * d, sb) * (1.0f / 128.0f);
    return d * rsqrtf(v + 1e-5f);
}

// ---------------- edge_repr-side aggregation (features 0,1,4,7,8) -----------
__global__ void __launch_bounds__(128, 10) k_er(const float* __restrict__ edge_repr,
                                                const float* __restrict__ W1,
                                                const float* __restrict__ b1) {
    __shared__ float4 smeta[ECAP];
    __shared__ float cmb[4][4][128];
    __shared__ float scmb[4][5];
    __shared__ float sb[4];
    int t = blockIdx.x;
    int tid = threadIdx.x;
    int wid = tid >> 5, lane = tid & 31;
    int c4 = lane << 2;

    int ecount = g_ecnt[t];
    const float4* ebase = g_emeta + (size_t)t * ECAP;
    for (int i = tid; i < ecount; i += 128) smeta[i] = ebase[i];
    __syncthreads();

    float4 v_is = {0,0,0,0}, v_os = {0,0,0,0}, v_il = {0,0,0,0}, v_ol = {0,0,0,0};
    float d_is = 0, d_os = 0, d_il = 0, d_ol = 0, tsum = 0;

#pragma unroll 4
    for (int i = wid; i < ecount; i += 4) {
        float4 mt = smeta[i];
        unsigned pk = __float_as_uint(mt.x);
        int eidx = pk & 0x7fffffff;
        float sw = mt.z, lw = mt.w;
        float4 er = *(const float4*)(edge_repr + (size_t)eidx * H + c4);
        if (pk & 0x80000000u) {
            v_is.x += sw * er.x; v_is.y += sw * er.y; v_is.z += sw * er.z; v_is.w += sw * er.w;
            v_il.x += lw * er.x; v_il.y += lw * er.y; v_il.z += lw * er.z; v_il.w += lw * er.w;
            d_is += sw; d_il += lw;
        } else {
            v_os.x += sw * er.x; v_os.y += sw * er.y; v_os.z += sw * er.z; v_os.w += sw * er.w;
            v_ol.x += lw * er.x; v_ol.y += lw * er.y; v_ol.z += lw * er.z; v_ol.w += lw * er.w;
            d_os += sw; d_ol += lw;
        }
        tsum += -__logf(sw);
    }

    *(float4*)&cmb[wid][0][c4] = v_is;
    *(float4*)&cmb[wid][1][c4] = v_os;
    *(float4*)&cmb[wid][2][c4] = v_il;
    *(float4*)&cmb[wid][3][c4] = v_ol;
    if (lane == 0) {
        scmb[wid][0] = d_is; scmb[wid][1] = d_os; scmb[wid][2] = d_il; scmb[wid][3] = d_ol;
        scmb[wid][4] = tsum;
    }
    __syncthreads();

    int h = tid;
    float a_is = cmb[0][0][h] + cmb[1][0][h] + cmb[2][0][h] + cmb[3][0][h];
    float a_os = cmb[0][1][h] + cmb[1][1][h] + cmb[2][1][h] + cmb[3][1][h];
    float a_il = cmb[0][2][h] + cmb[1][2][h] + cmb[2][2][h] + cmb[3][2][h];
    float a_ol = cmb[0][3][h] + cmb[1][3][h] + cmb[2][3][h] + cmb[3][3][h];
    d_is = scmb[0][0] + scmb[1][0] + scmb[2][0] + scmb[3][0];
    d_os = scmb[0][1] + scmb[1][1] + scmb[2][1] + scmb[3][1];
    d_il = scmb[0][2] + scmb[1][2] + scmb[2][2] + scmb[3][2];
    d_ol = scmb[0][3] + scmb[1][3] + scmb[2][3] + scmb[3][3];
    tsum = scmb[0][4] + scmb[1][4] + scmb[2][4] + scmb[3][4];

    float in_s  = a_is / fmaxf(d_is, 1e-6f);
    float out_s = a_os / fmaxf(d_os, 1e-6f);
    float in_l  = a_il / fmaxf(d_il, 1e-6f);
    float out_l = a_ol / fmaxf(d_ol, 1e-6f);

    float burst = blk_ln(in_s + out_s - in_l - out_l, sb);
    float dirg  = blk_ln(out_l - in_l, sb);
    float asym  = blk_ln(fabsf(dirg), sb);
    float rb    = blk_ln(in_l + out_l, sb);

    float ssd = blk_sum(dirg * dirg, sb);
    if (h == 0) atomicAdd(&g_norm3[2], sqrtf(ssd));

    storeA(t, 0 * H + h, burst);
    storeA(t, 1 * H + h, dirg);
    storeA(t, 4 * H + h, asym);
    storeA(t, 7 * H + h, rb);

    if (h < 32) {
        float cin = (float)g_icnt[t];
        float cnt = (float)ecount;
        float cout = cnt - cin;
        float c1 = (float)g_hcnt[t];
        float c2 = (float)g_ncnt[t] - c1;
        float smw = d_is + d_os;
        float lmw = d_il + d_ol;
        float s0 = log1pf(cin), s1 = log1pf(cout), s2 = log1pf(c1), s3 = log1pf(c2);
        float s4 = tsum / fmaxf(cnt, 1e-6f);
        float s5 = smw, s6 = lmw, s7 = smw - lmw;
        float acc = b1[h];
        acc += s0 * W1[0 * 32 + h] + s1 * W1[1 * 32 + h] + s2 * W1[2 * 32 + h] + s3 * W1[3 * 32 + h]
             + s4 * W1[4 * 32 + h] + s5 * W1[5 * 32 + h] + s6 * W1[6 * 32 + h] + s7 * W1[7 * 32 + h];
        storeA(t, 8 * H + h, gelu_exact(acc));
    }
}

// ---------------- gather kernel: grid 2T (src + node) ------------------------
__global__ void __launch_bounds__(128, 12) k_gather(const float* __restrict__ node_repr) {
    __shared__ float4 smeta[ECAP];
    __shared__ float cmb[4][2][128];
    __shared__ float scmb[4][2];
    __shared__ float sb[4];
    int b = blockIdx.x;
    int tid = threadIdx.x;
    int wid = tid >> 5, lane = tid & 31;
    int c4 = lane << 2;
    int h = tid;

    if (b < T) {
        int t = b;
        int ecount = g_ecnt[t];
        const float4* ebase = g_emeta + (size_t)t * ECAP;
        for (int i = tid; i < ecount; i += 128) smeta[i] = ebase[i];
        __syncthreads();

        float4 v_hs = {0,0,0,0}, v_hl = {0,0,0,0};
        float smw = 0, lmw = 0;
#pragma unroll 4
        for (int i = wid; i < ecount; i += 4) {
            float4 mt = smeta[i];
            int src = __float_as_int(mt.y);
            float sw = mt.z, lw = mt.w;
            float4 sr = *(const float4*)(node_repr + (size_t)src * H + c4);
            v_hs.x += sw * sr.x; v_hs.y += sw * sr.y; v_hs.z += sw * sr.z; v_hs.w += sw * sr.w;
            v_hl.x += lw * sr.x; v_hl.y += lw * sr.y; v_hl.z += lw * sr.z; v_hl.w += lw * sr.w;
            smw += sw; lmw += lw;
        }
        *(float4*)&cmb[wid][0][c4] = v_hs;
        *(float4*)&cmb[wid][1][c4] = v_hl;
        if (lane == 0) { scmb[wid][0] = smw; scmb[wid][1] = lmw; }
        __syncthreads();

        float a_hs = cmb[0][0][h] + cmb[1][0][h] + cmb[2][0][h] + cmb[3][0][h];
        float a_hl = cmb[0][1][h] + cmb[1][1][h] + cmb[2][1][h] + cmb[3][1][h];
        smw = scmb[0][0] + scmb[1][0] + scmb[2][0] + scmb[3][0];
        lmw = scmb[0][1] + scmb[1][1] + scmb[2][1] + scmb[3][1];

        float h1es = a_hs / fmaxf(smw, 1e-6f);
        float h1el = a_hl / fmaxf(lmw, 1e-6f);
        float slg = blk_ln(h1es - h1el, sb);
        float sss = blk_sum(slg * slg, sb);
        if (h == 0) atomicAdd(&g_norm3[1], sqrtf(sss));
        storeA(t, 3 * H + h, slg);
    } else {
        int t = b - T;
        int ncount = g_ncnt[t];
        unsigned* snl = (unsigned*)smeta;
        const unsigned* nbase = g_nlist + (size_t)t * NCAP;
        for (int i = tid; i < ncount; i += 128) snl[i] = nbase[i];
        __syncthreads();

        float4 v_h1 = {0,0,0,0}, v_h2 = {0,0,0,0};
#pragma unroll 4
        for (int i = wid; i < ncount; i += 4) {
            unsigned pk = snl[i];
            float4 nr = *(const float4*)(node_repr + (size_t)(pk & 0x7fffffff) * H + c4);
            if (pk & 0x80000000u) {
                v_h1.x += nr.x; v_h1.y += nr.y; v_h1.z += nr.z; v_h1.w += nr.w;
            } else {
                v_h2.x += nr.x; v_h2.y += nr.y; v_h2.z += nr.z; v_h2.w += nr.w;
            }
        }
        *(float4*)&cmb[wid][0][c4] = v_h1;
        *(float4*)&cmb[wid][1][c4] = v_h2;
        __syncthreads();

        float a_h1 = cmb[0][0][h] + cmb[1][0][h] + cmb[2][0][h] + cmb[3][0][h];
        float a_h2 = cmb[0][1][h] + cmb[1][1][h] + cmb[2][1][h] + cmb[3][1][h];
        float c1 = (float)g_hcnt[t];
        float c2 = (float)ncount - c1;

        float h1m = a_h1 / fmaxf(c1, 1e-6f);
        float h2m = a_h2 / fmaxf(c2, 1e-6f);

        float hopg = blk_ln(h1m - h2m, sb);
        float h1n  = blk_ln(h1m, sb);
        float h2n  = blk_ln(h2m, sb);

        float ssh = blk_sum(hopg * hopg, sb);
        if (h == 0) atomicAdd(&g_norm3[0], sqrtf(ssh));

        storeA(t, 2 * H + h, hopg);
        storeA(t, 5 * H + h, h1n);
        storeA(t, 6 * H + h, h2n);
    }
}

// ---------------- GEMM1: tf32 mma.sync, 512 threads, warp tile 32x16 --------
// 16 warps: wm = warp&3 (2 m16 tiles each), wn = warp>>2 (2 n8 tiles each).
// BM=128 BN=64, grid (32,4) = 128 blocks, 4 warps/SMSP for L2-latency hiding.
__global__ void __launch_bounds__(512) k_gemm1(const float* __restrict__ b2) {
    int tid = threadIdx.x, lane = tid & 31, warp = tid >> 5;
    int wm = warp & 3, wn = warp >> 2;          // wm 0-3, wn 0-3
    int bm = blockIdx.x * 128, bn = blockIdx.y * 64;
    int mt0 = (bm >> 4) + wm * 2;               // 2 m16 tiles
    int nt0 = (bn >> 3) + wn * 2;               // 2 n8 tiles

    float c[2][2][4];
#pragma unroll
    for (int i = 0; i < 2; i++)
#pragma unroll
        for (int j = 0; j < 2; j++)
#pragma unroll
            for (int r = 0; r < 4; r++) c[i][j][r] = 0.0f;

    const float4* A0 = (const float4*)(g_Af + (size_t)mt0 * KS * 128) + lane;
    const float4* A1 = (const float4*)(g_Af + (size_t)(mt0 + 1) * KS * 128) + lane;
    const float2* B0 = (const float2*)g_Bf + (size_t)nt0 * 32 + lane;

#pragma unroll 4
    for (int ks = 0; ks < KS; ks++) {
        float4 a0 = A0[ks * 32];
        float4 a1 = A1[ks * 32];
        float2 bf0 = B0[(size_t)ks * 1024];
        float2 bf1 = B0[(size_t)ks * 1024 + 32];
        mma8(c[0][0], a0, bf0);
        mma8(c[1][0], a1, bf0);
        mma8(c[0][1], a0, bf1);
        mma8(c[1][1], a1, bf1);
    }

#pragma unroll
    for (int i = 0; i < 2; i++) {
        int r0 = bm + wm * 32 + i * 16 + (lane >> 2);
#pragma unroll
        for (int j = 0; j < 2; j++) {
            int cc = bn + wn * 16 + j * 8 + (lane & 3) * 2;
            float bx = b2[cc], by = b2[cc + 1];
            float2 lo, hi;
            lo.x = gelu_exact(c[i][j][0] + bx);
            lo.y = gelu_exact(c[i][j][1] + by);
            hi.x = gelu_exact(c[i][j][2] + bx);
            hi.y = gelu_exact(c[i][j][3] + by);
            *(float2*)(g_hidden + (size_t)r0 * HD + cc) = lo;
            *(float2*)(g_hidden + (size_t)(r0 + 8) * HD + cc) = hi;
        }
    }
}

// ---------------- GEMM2: [T,256] @ [256,128] + bias + 0.25*tanh + norms -----
__global__ void __launch_bounds__(256) k_gemm2(const float* __restrict__ W3,
                                               const float* __restrict__ b3,
                                               float* __restrict__ out) {
    __shared__ float hs[16 * 256];
    int tid = threadIdx.x;
    int t0 = blockIdx.x * 16;
    if (blockIdx.x == 0 && tid < 3)
        out[(size_t)T * H + tid] = g_norm3[tid] * (1.0f / (float)T);
    for (int i = tid; i < 16 * 256; i += 256)
        hs[i] = g_hidden[(size_t)t0 * 256 + i];
    __syncthreads();
    int n = tid & 127;
    int half = tid >> 7;
    const float* hp = hs + half * 8 * 256;
    u64 acc2[8];
#pragma unroll
    for (int r = 0; r < 8; r++) acc2[r] = 0ull;
    for (int k = 0; k < 256; k += 4) {
        float w0 = W3[(k + 0) * 128 + n];
        float w1 = W3[(k + 1) * 128 + n];
        float w2 = W3[(k + 2) * 128 + n];
        float w3v = W3[(k + 3) * 128 + n];
        u64 w01 = pack2(w0, w1);
        u64 w23 = pack2(w2, w3v);
#pragma unroll
        for (int r = 0; r < 8; r++) {
            ulonglong2 hv = *(const ulonglong2*)&hp[r * 256 + k];
            fma2(acc2[r], hv.x, w01);
            fma2(acc2[r], hv.y, w23);
        }
    }
    float bias = b3[n];
#pragma unroll
    for (int r = 0; r < 8; r++) {
        float lo, hi;
        unpack2(acc2[r], lo, hi);
        out[(size_t)(t0 + half * 8 + r) * 128 + n] = 0.25f * tanhf(lo + hi + bias);
    }
}

// ---------------- launcher --------------------------------------------------
extern "C" void kernel_launch(void* const* d_in, const int* in_sizes, int n_in,
                              void* d_out, int out_size) {
    const float* node_repr = (const float*)d_in[0];
    const float* edge_repr = (const float*)d_in[1];
    const int*   edge_src  = (const int*)d_in[2];
    const int*   edge_dst  = (const int*)d_in[3];
    const int*   rel_ids   = (const int*)d_in[4];
    const float* etime     = (const float*)d_in[5];
    const int*   tli       = (const int*)d_in[6];
    const int*   nsg       = (const int*)d_in[7];
    const int*   esg       = (const int*)d_in[8];
    const int*   hop       = (const int*)d_in[9];
    const float* W1 = (const float*)d_in[10];
    const float* b1 = (const float*)d_in[11];
    const float* W2 = (const float*)d_in[12];
    const float* b2 = (const float*)d_in[13];
    const float* W3 = (const float*)d_in[14];
    const float* b3 = (const float*)d_in[15];
    float* out = (float*)d_out;

    k_init<<<16, 256>>>();
    k_cvtB<<<FD * HD / 256, 256>>>(W2);
    k_scatter<<<EBLK + NBLK, 256>>>(edge_dst, esg, tli, rel_ids, etime, edge_src, nsg, hop);
    k_er<<<T, 128>>>(edge_repr, W1, b1);
    k_gather<<<2 * T, 128>>>(node_repr);
    k_gemm1<<<dim3(32, 4), 512>>>(b2);
    k_gemm2<<<T / 16, 256>>>(W3, b3, out);
}

// round 11
// speedup vs baseline: 2.0378x; 1.0275x over previous
#include <cuda_runtime.h>
#include <cuda_bf16.h>
#include <cstdint>

#define H 128
#define E 1048576
#define NV 262144
#define T 4096
#define NET 8
#define FD 1056   // 8*H + 32
#define HD 256    // 2*H
#define KS 132    // FD / 8 k-steps
#define ECAP 256
#define NCAP 256

// ---------------- scratch ---------------------------------------------------
__device__ int g_ecnt[T];
__device__ int g_ncnt[T];
__device__ int g_icnt[T];
__device__ int g_hcnt[T];
__device__ float4   g_emeta[(size_t)T * ECAP];
__device__ unsigned g_nlist[(size_t)T * NCAP];
__device__ float g_Af[(size_t)(T / 16) * KS * 128];
__device__ float g_Bf[(size_t)KS * 32 * 64];
__device__ float g_hidden[(size_t)T * HD];
__device__ float g_norm3[3];

typedef unsigned long long u64;

__device__ __forceinline__ float gelu_exact(float x) {
    return 0.5f * x * (1.0f + erff(x * 0.7071067811865476f));
}
__device__ __forceinline__ u64 pack2(float lo, float hi) {
    u64 r; asm("mov.b64 %0, {%1, %2};" : "=l"(r) : "f"(lo), "f"(hi)); return r;
}
__device__ __forceinline__ void fma2(u64& acc, u64 a, u64 b) {
    asm("fma.rn.f32x2 %0, %1, %2, %0;" : "+l"(acc) : "l"(a), "l"(b));
}
__device__ __forceinline__ void unpack2(u64 v, float& lo, float& hi) {
    asm("mov.b64 {%0, %1}, %2;" : "=f"(lo), "=f"(hi) : "l"(v));
}
__device__ __forceinline__ float to_tf32(float x) {
    uint32_t u; asm("cvt.rna.tf32.f32 %0, %1;" : "=r"(u) : "f"(x));
    return __uint_as_float(u);
}
__device__ __forceinline__ void mma8(float* c, const float4& a, const float2& b) {
    asm("mma.sync.aligned.m16n8k8.row.col.f32.tf32.tf32.f32 "
        "{%0,%1,%2,%3}, {%4,%5,%6,%7}, {%8,%9}, {%0,%1,%2,%3};"
        : "+f"(c[0]), "+f"(c[1]), "+f"(c[2]), "+f"(c[3])
        : "r"(__float_as_uint(a.x)), "r"(__float_as_uint(a.y)),
          "r"(__float_as_uint(a.z)), "r"(__float_as_uint(a.w)),
          "r"(__float_as_uint(b.x)), "r"(__float_as_uint(b.y)));
}
__device__ __forceinline__ void storeA(int m, int k, float v) {
    int kstep = k >> 3, kc = k & 7, mr = m & 15;
    int th = ((mr & 7) << 2) | (kc & 3);
    int reg = (mr >> 3) | ((kc >> 2) << 1);
    g_Af[((size_t)(m >> 4) * KS + kstep) * 128 + th * 4 + reg] = to_tf32(v);
}

// ---------------- init ------------------------------------------------------
__global__ void k_init() {
    int i = blockIdx.x * blockDim.x + threadIdx.x;
    if (i < T) { g_ecnt[i] = 0; g_ncnt[i] = 0; g_icnt[i] = 0; g_hcnt[i] = 0; }
    if (i < 3) g_norm3[i] = 0.0f;
}

// ---------------- W2 -> tf32 B-fragments ------------------------------------
__global__ void k_cvtB(const float* __restrict__ W2) {
    int i = blockIdx.x * blockDim.x + threadIdx.x;
    int k = i >> 8, n = i & 255;
    float v = to_tf32(W2[i]);
    int kstep = k >> 3, kc = k & 7;
    int th = ((n & 7) << 2) | (kc & 3);
    int reg = kc >> 2;
    g_Bf[((size_t)kstep * 32 + (n >> 3)) * 64 + th * 2 + reg] = v;
}

// ---------------- scatter into fixed-capacity buckets -----------------------
#define EBLK (E / 4 / 256)
#define NBLK (NV / 4 / 256)
__global__ void k_scatter(const int* __restrict__ ed, const int* __restrict__ esg,
                          const int* __restrict__ tli, const int* __restrict__ rel,
                          const float* __restrict__ tm, const int* __restrict__ esrc,
                          const int* __restrict__ nsg, const int* __restrict__ hop) {
    int b = blockIdx.x;
    if (b < EBLK) {
        int i = b * 256 + threadIdx.x;
        int4 d4 = ((const int4*)ed)[i];
        int4 s4 = ((const int4*)esg)[i];
        int4 r4 = ((const int4*)rel)[i];
        float4 t4 = ((const float4*)tm)[i];
        int4 sr4 = ((const int4*)esrc)[i];
        int dd[4] = {d4.x, d4.y, d4.z, d4.w};
        int ss[4] = {s4.x, s4.y, s4.z, s4.w};
        int rr[4] = {r4.x, r4.y, r4.z, r4.w};
        float tt[4] = {t4.x, t4.y, t4.z, t4.w};
        int sc[4] = {sr4.x, sr4.y, sr4.z, sr4.w};
#pragma unroll
        for (int q = 0; q < 4; q++) {
            if (dd[q] == __ldg(&tli[ss[q]])) {
                int pos = atomicAdd(&g_ecnt[ss[q]], 1);
                bool inb = (rr[q] < NET);
                if (inb) atomicAdd(&g_icnt[ss[q]], 1);
                float t = tt[q];
                unsigned pk = (unsigned)(i * 4 + q) | (inb ? 0x80000000u : 0u);
                float4 mt;
                mt.x = __uint_as_float(pk);
                mt.y = __int_as_float(sc[q]);
                mt.z = expf(-t);
                mt.w = expf(-t * (1.0f / 24.0f));
                g_emeta[(size_t)ss[q] * ECAP + pos] = mt;
            }
        }
    } else {
        int i = (b - EBLK) * 256 + threadIdx.x;
        int4 n4 = ((const int4*)nsg)[i];
        int4 h4 = ((const int4*)hop)[i];
        int nn[4] = {n4.x, n4.y, n4.z, n4.w};
        int hh[4] = {h4.x, h4.y, h4.z, h4.w};
#pragma unroll
        for (int q = 0; q < 4; q++) {
            int pos = atomicAdd(&g_ncnt[nn[q]], 1);
            bool h1 = (hh[q] == 1);
            if (h1) atomicAdd(&g_hcnt[nn[q]], 1);
            g_nlist[(size_t)nn[q] * NCAP + pos] =
                (unsigned)(i * 4 + q) | (h1 ? 0x80000000u : 0u);
        }
    }
}

// ---------------- block reduce helpers (128 threads) ------------------------
__device__ __forceinline__ float blk_sum(float v, float* sb) {
#pragma unroll
    for (int o = 16; o > 0; o >>= 1) v += __shfl_xor_sync(0xffffffffu, v, o);
    __syncthreads();
    if ((threadIdx.x & 31) == 0) sb[threadIdx.x >> 5] = v;
    __syncthreads();
    return sb[0] + sb[1] + sb[2] + sb[3];
}
__device__ __forceinline__ float blk_ln(float x, float* sb) {
    float m = blk_sum(x, sb) * (1.0f / 128.0f);
    float d = x - m;
    float v = blk_sum(d * d, sb) * (1.0f / 128.0f);
    return d * rsqrtf(v + 1e-5f);
}

// ---------------- merged aggregation: grid 3T, interleaved b%3 ---------------
// type 0: edge_repr aggregation (features 0,1,4,7,8)
// type 1: src gather (feature 3, norm[1])
// type 2: node gather (features 2,5,6, norm[0])
__global__ void __launch_bounds__(128, 10) k_agg(const float* __restrict__ edge_repr,
                                                 const float* __restrict__ node_repr,
                                                 const float* __restrict__ W1,
                                                 const float* __restrict__ b1) {
    __shared__ __align__(16) char sbuf[4096 + 8192 + 128];
    float4*   smeta4 = (float4*)sbuf;
    unsigned* smetau = (unsigned*)sbuf;
    float* cmb  = (float*)(sbuf + 4096);          // up to [4][4][128]
    float* scmb = (float*)(sbuf + 4096 + 8192);   // up to [4][5]
    float* sb   = scmb + 24;

    int b = blockIdx.x;
    int type = b % 3;
    int t = b / 3;
    int tid = threadIdx.x;
    int wid = tid >> 5, lane = tid & 31;
    int c4 = lane << 2;
    int h = tid;

    if (type == 0) {
        int ecount = g_ecnt[t];
        const float4* ebase = g_emeta + (size_t)t * ECAP;
        for (int i = tid; i < ecount; i += 128) smeta4[i] = ebase[i];
        __syncthreads();

        float4 v_is = {0,0,0,0}, v_os = {0,0,0,0}, v_il = {0,0,0,0}, v_ol = {0,0,0,0};
        float d_is = 0, d_os = 0, d_il = 0, d_ol = 0, tsum = 0;
#pragma unroll 4
        for (int i = wid; i < ecount; i += 4) {
            float4 mt = smeta4[i];
            unsigned pk = __float_as_uint(mt.x);
            int eidx = pk & 0x7fffffff;
            float sw = mt.z, lw = mt.w;
            float4 er = *(const float4*)(edge_repr + (size_t)eidx * H + c4);
            if (pk & 0x80000000u) {
                v_is.x += sw * er.x; v_is.y += sw * er.y; v_is.z += sw * er.z; v_is.w += sw * er.w;
                v_il.x += lw * er.x; v_il.y += lw * er.y; v_il.z += lw * er.z; v_il.w += lw * er.w;
                d_is += sw; d_il += lw;
            } else {
                v_os.x += sw * er.x; v_os.y += sw * er.y; v_os.z += sw * er.z; v_os.w += sw * er.w;
                v_ol.x += lw * er.x; v_ol.y += lw * er.y; v_ol.z += lw * er.z; v_ol.w += lw * er.w;
                d_os += sw; d_ol += lw;
            }
            tsum += -__logf(sw);
        }

        *(float4*)&cmb[(wid * 4 + 0) * 128 + c4] = v_is;
        *(float4*)&cmb[(wid * 4 + 1) * 128 + c4] = v_os;
        *(float4*)&cmb[(wid * 4 + 2) * 128 + c4] = v_il;
        *(float4*)&cmb[(wid * 4 + 3) * 128 + c4] = v_ol;
        if (lane == 0) {
            scmb[wid * 5 + 0] = d_is; scmb[wid * 5 + 1] = d_os;
            scmb[wid * 5 + 2] = d_il; scmb[wid * 5 + 3] = d_ol;
            scmb[wid * 5 + 4] = tsum;
        }
        __syncthreads();

        float a_is = cmb[0 * 128 + h] + cmb[4 * 128 + h] + cmb[8 * 128 + h] + cmb[12 * 128 + h];
        float a_os = cmb[1 * 128 + h] + cmb[5 * 128 + h] + cmb[9 * 128 + h] + cmb[13 * 128 + h];
        float a_il = cmb[2 * 128 + h] + cmb[6 * 128 + h] + cmb[10 * 128 + h] + cmb[14 * 128 + h];
        float a_ol = cmb[3 * 128 + h] + cmb[7 * 128 + h] + cmb[11 * 128 + h] + cmb[15 * 128 + h];
        d_is = scmb[0] + scmb[5] + scmb[10] + scmb[15];
        d_os = scmb[1] + scmb[6] + scmb[11] + scmb[16];
        d_il = scmb[2] + scmb[7] + scmb[12] + scmb[17];
        d_ol = scmb[3] + scmb[8] + scmb[13] + scmb[18];
        tsum = scmb[4] + scmb[9] + scmb[14] + scmb[19];

        float in_s  = a_is / fmaxf(d_is, 1e-6f);
        float out_s = a_os / fmaxf(d_os, 1e-6f);
        float in_l  = a_il / fmaxf(d_il, 1e-6f);
        float out_l = a_ol / fmaxf(d_ol, 1e-6f);

        float burst = blk_ln(in_s + out_s - in_l - out_l, sb);
        float dirg  = blk_ln(out_l - in_l, sb);
        float asym  = blk_ln(fabsf(dirg), sb);
        float rb    = blk_ln(in_l + out_l, sb);

        float ssd = blk_sum(dirg * dirg, sb);
        if (h == 0) atomicAdd(&g_norm3[2], sqrtf(ssd));

        storeA(t, 0 * H + h, burst);
        storeA(t, 1 * H + h, dirg);
        storeA(t, 4 * H + h, asym);
        storeA(t, 7 * H + h, rb);

        if (h < 32) {
            float cin = (float)g_icnt[t];
            float cnt = (float)ecount;
            float cout = cnt - cin;
            float c1 = (float)g_hcnt[t];
            float c2 = (float)g_ncnt[t] - c1;
            float smw = d_is + d_os;
            float lmw = d_il + d_ol;
            float s0 = log1pf(cin), s1 = log1pf(cout), s2 = log1pf(c1), s3 = log1pf(c2);
            float s4 = tsum / fmaxf(cnt, 1e-6f);
            float s5 = smw, s6 = lmw, s7 = smw - lmw;
            float acc = b1[h];
            acc += s0 * W1[0 * 32 + h] + s1 * W1[1 * 32 + h] + s2 * W1[2 * 32 + h] + s3 * W1[3 * 32 + h]
                 + s4 * W1[4 * 32 + h] + s5 * W1[5 * 32 + h] + s6 * W1[6 * 32 + h] + s7 * W1[7 * 32 + h];
            storeA(t, 8 * H + h, gelu_exact(acc));
        }
    } else if (type == 1) {
        int ecount = g_ecnt[t];
        const float4* ebase = g_emeta + (size_t)t * ECAP;
        for (int i = tid; i < ecount; i += 128) smeta4[i] = ebase[i];
        __syncthreads();

        float4 v_hs = {0,0,0,0}, v_hl = {0,0,0,0};
        float smw = 0, lmw = 0;
#pragma unroll 4
        for (int i = wid; i < ecount; i += 4) {
            float4 mt = smeta4[i];
            int src = __float_as_int(mt.y);
            float sw = mt.z, lw = mt.w;
            float4 sr = *(const float4*)(node_repr + (size_t)src * H + c4);
            v_hs.x += sw * sr.x; v_hs.y += sw * sr.y; v_hs.z += sw * sr.z; v_hs.w += sw * sr.w;
            v_hl.x += lw * sr.x; v_hl.y += lw * sr.y; v_hl.z += lw * sr.z; v_hl.w += lw * sr.w;
            smw += sw; lmw += lw;
        }
        *(float4*)&cmb[(wid * 2 + 0) * 128 + c4] = v_hs;
        *(float4*)&cmb[(wid * 2 + 1) * 128 + c4] = v_hl;
        if (lane == 0) { scmb[wid * 2 + 0] = smw; scmb[wid * 2 + 1] = lmw; }
        __syncthreads();

        float a_hs = cmb[0 * 128 + h] + cmb[2 * 128 + h] + cmb[4 * 128 + h] + cmb[6 * 128 + h];
        float a_hl = cmb[1 * 128 + h] + cmb[3 * 128 + h] + cmb[5 * 128 + h] + cmb[7 * 128 + h];
        smw = scmb[0] + scmb[2] + scmb[4] + scmb[6];
        lmw = scmb[1] + scmb[3] + scmb[5] + scmb[7];

        float h1es = a_hs / fmaxf(smw, 1e-6f);
        float h1el = a_hl / fmaxf(lmw, 1e-6f);
        float slg = blk_ln(h1es - h1el, sb);
        float sss = blk_sum(slg * slg, sb);
        if (h == 0) atomicAdd(&g_norm3[1], sqrtf(sss));
        storeA(t, 3 * H + h, slg);
    } else {
        int ncount = g_ncnt[t];
        const unsigned* nbase = g_nlist + (size_t)t * NCAP;
        for (int i = tid; i < ncount; i += 128) smetau[i] = nbase[i];
        __syncthreads();

        float4 v_h1 = {0,0,0,0}, v_h2 = {0,0,0,0};
#pragma unroll 4
        for (int i = wid; i < ncount; i += 4) {
            unsigned pk = smetau[i];
            float4 nr = *(const float4*)(node_repr + (size_t)(pk & 0x7fffffff) * H + c4);
            if (pk & 0x80000000u) {
                v_h1.x += nr.x; v_h1.y += nr.y; v_h1.z += nr.z; v_h1.w += nr.w;
            } else {
                v_h2.x += nr.x; v_h2.y += nr.y; v_h2.z += nr.z; v_h2.w += nr.w;
            }
        }
        *(float4*)&cmb[(wid * 2 + 0) * 128 + c4] = v_h1;
        *(float4*)&cmb[(wid * 2 + 1) * 128 + c4] = v_h2;
        __syncthreads();

        float a_h1 = cmb[0 * 128 + h] + cmb[2 * 128 + h] + cmb[4 * 128 + h] + cmb[6 * 128 + h];
        float a_h2 = cmb[1 * 128 + h] + cmb[3 * 128 + h] + cmb[5 * 128 + h] + cmb[7 * 128 + h];
        float c1 = (float)g_hcnt[t];
        float c2 = (float)ncount - c1;

        float h1m = a_h1 / fmaxf(c1, 1e-6f);
        float h2m = a_h2 / fmaxf(c2, 1e-6f);

        float hopg = blk_ln(h1m - h2m, sb);
        float h1n  = blk_ln(h1m, sb);
        float h2n  = blk_ln(h2m, sb);

        float ssh = blk_sum(hopg * hopg, sb);
        if (h == 0) atomicAdd(&g_norm3[0], sqrtf(ssh));

        storeA(t, 2 * H + h, hopg);
        storeA(t, 5 * H + h, h1n);
        storeA(t, 6 * H + h, h2n);
    }
}

// ---------------- GEMM1: tf32 mma.sync, BM=64 BN=64, 512 thr, grid (64,4) ---
// 16 warps: wm = warp&3 -> 1 m16 tile, wn = warp>>2 -> 2 n8 tiles. ~2 blocks/SM.
__global__ void __launch_bounds__(512) k_gemm1(const float* __restrict__ b2) {
    int tid = threadIdx.x, lane = tid & 31, warp = tid >> 5;
    int wm = warp & 3, wn = warp >> 2;
    int bm = blockIdx.x * 64, bn = blockIdx.y * 64;
    int mt = (bm >> 4) + wm;           // 1 m16 tile
    int nt0 = (bn >> 3) + wn * 2;      // 2 n8 tiles

    float c[2][4];
#pragma unroll
    for (int j = 0; j < 2; j++)
#pragma unroll
        for (int r = 0; r < 4; r++) c[j][r] = 0.0f;

    const float4* A0 = (const float4*)(g_Af + (size_t)mt * KS * 128) + lane;
    const float2* B0 = (const float2*)g_Bf + (size_t)nt0 * 32 + lane;

#pragma unroll 4
    for (int ks = 0; ks < KS; ks++) {
        float4 a0 = A0[ks * 32];
        float2 bf0 = B0[(size_t)ks * 1024];
        float2 bf1 = B0[(size_t)ks * 1024 + 32];
        mma8(c[0], a0, bf0);
        mma8(c[1], a0, bf1);
    }

    int r0 = bm + wm * 16 + (lane >> 2);
#pragma unroll
    for (int j = 0; j < 2; j++) {
        int cc = bn + wn * 16 + j * 8 + (lane & 3) * 2;
        float bx = b2[cc], by = b2[cc + 1];
        float2 lo, hi;
        lo.x = gelu_exact(c[j][0] + bx);
        lo.y = gelu_exact(c[j][1] + by);
        hi.x = gelu_exact(c[j][2] + bx);
        hi.y = gelu_exact(c[j][3] + by);
        *(float2*)(g_hidden + (size_t)r0 * HD + cc) = lo;
        *(float2*)(g_hidden + (size_t)(r0 + 8) * HD + cc) = hi;
    }
}

// ---------------- GEMM2: [T,256] @ [256,128] + bias + 0.25*tanh + norms -----
__global__ void __launch_bounds__(256) k_gemm2(const float* __restrict__ W3,
                                               const float* __restrict__ b3,
                                               float* __restrict__ out) {
    __shared__ float hs[16 * 256];
    int tid = threadIdx.x;
    int t0 = blockIdx.x * 16;
    if (blockIdx.x == 0 && tid < 3)
        out[(size_t)T * H + tid] = g_norm3[tid] * (1.0f / (float)T);
    for (int i = tid; i < 16 * 256; i += 256)
        hs[i] = g_hidden[(size_t)t0 * 256 + i];
    __syncthreads();
    int n = tid & 127;
    int half = tid >> 7;
    const float* hp = hs + half * 8 * 256;
    u64 acc2[8];
#pragma unroll
    for (int r = 0; r < 8; r++) acc2[r] = 0ull;
    for (int k = 0; k < 256; k += 4) {
        float w0 = W3[(k + 0) * 128 + n];
        float w1 = W3[(k + 1) * 128 + n];
        float w2 = W3[(k + 2) * 128 + n];
        float w3v = W3[(k + 3) * 128 + n];
        u64 w01 = pack2(w0, w1);
        u64 w23 = pack2(w2, w3v);
#pragma unroll
        for (int r = 0; r < 8; r++) {
            ulonglong2 hv = *(const ulonglong2*)&hp[r * 256 + k];
            fma2(acc2[r], hv.x, w01);
            fma2(acc2[r], hv.y, w23);
        }
    }
    float bias = b3[n];
#pragma unroll
    for (int r = 0; r < 8; r++) {
        float lo, hi;
        unpack2(acc2[r], lo, hi);
        out[(size_t)(t0 + half * 8 + r) * 128 + n] = 0.25f * tanhf(lo + hi + bias);
    }
}

// ---------------- launcher --------------------------------------------------
extern "C" void kernel_launch(void* const* d_in, const int* in_sizes, int n_in,
                              void* d_out, int out_size) {
    const float* node_repr = (const float*)d_in[0];
    const float* edge_repr = (const float*)d_in[1];
    const int*   edge_src  = (const int*)d_in[2];
    const int*   edge_dst  = (const int*)d_in[3];
    const int*   rel_ids   = (const int*)d_in[4];
    const float* etime     = (const float*)d_in[5];
    const int*   tli       = (const int*)d_in[6];
    const int*   nsg       = (const int*)d_in[7];
    const int*   esg       = (const int*)d_in[8];
    const int*   hop       = (const int*)d_in[9];
    const float* W1 = (const float*)d_in[10];
    const float* b1 = (const float*)d_in[11];
    const float* W2 = (const float*)d_in[12];
    const float* b2 = (const float*)d_in[13];
    const float* W3 = (const float*)d_in[14];
    const float* b3 = (const float*)d_in[15];
    float* out = (float*)d_out;

    k_init<<<16, 256>>>();
    k_cvtB<<<FD * HD / 256, 256>>>(W2);
    k_scatter<<<EBLK + NBLK, 256>>>(edge_dst, esg, tli, rel_ids, etime, edge_src, nsg, hop);
    k_agg<<<3 * T, 128>>>(edge_repr, node_repr, W1, b1);
    k_gemm1<<<dim3(64, 4), 512>>>(b2);
    k_gemm2<<<T / 16, 256>>>(W3, b3, out);
}